// round 1
// baseline (speedup 1.0000x reference)
#include <cuda_runtime.h>
#include <cuda_bf16.h>
#include <math.h>

// ---------------- problem constants ----------------
#define BB 4
#define CIN 2048
#define IC 512
#define C8 64
#define NCLS 81
#define HH 64
#define WW 64
#define HW 4096
#define OHW (128*128)

// ---------------- scratch (__device__ globals, no runtime alloc) ----------------
__device__ float g_wt1p[9*CIN*IC];
__device__ float g_wt1c[9*CIN*IC];
__device__ float g_wt2p[9*IC*IC];
__device__ float g_wt2c[9*IC*IC];
__device__ float g_featp0[BB*IC*HW];
__device__ float g_featc0[BB*IC*HW];
__device__ float g_fb[BB*C8*HW];
__device__ float g_fc[BB*C8*HW];
__device__ float g_fd[BB*IC*HW];
__device__ float g_attn[(size_t)BB*HW*HW];
__device__ float g_pam[BB*IC*HW];
__device__ float g_featp[BB*IC*HW];
__device__ float g_camatt[BB*IC*IC];
__device__ float g_cam[BB*IC*HW];
__device__ float g_featc[BB*IC*HW];
__device__ float g_fusion[BB*IC*HW];
__device__ float g_pout[BB*NCLS*HW];
__device__ float g_cout[BB*NCLS*HW];
__device__ float g_fout[BB*NCLS*HW];

// ---------------- weight transpose: wt[(tap*Cin+ci)*Cout+co] = w[(co*Cin+ci)*9+tap] ----------------
__global__ void wtrans_kernel(const float* __restrict__ w, float* __restrict__ wt,
                              int Cin, int Cout) {
    size_t total = (size_t)Cout * Cin * 9;
    for (size_t i = (size_t)blockIdx.x * blockDim.x + threadIdx.x; i < total;
         i += (size_t)gridDim.x * blockDim.x) {
        int co = (int)(i % Cout);
        size_t r = i / Cout;
        int ci = (int)(r % Cin);
        int tap = (int)(r / Cin);
        wt[i] = w[((size_t)co * Cin + ci) * 9 + tap];
    }
}

// ---------------- 3x3 conv, implicit GEMM, fused scale/bias/relu ----------------
// grid: (BB*HH/2, Cout/128), 256 threads. Tile: 128 couts x 128 spatial (2 rows).
__global__ void conv3x3_kernel(const float* __restrict__ x, const float* __restrict__ wt,
                               float* __restrict__ out,
                               const float* __restrict__ s, const float* __restrict__ bias,
                               int Cin, int relu) {
    const int Cout = gridDim.y * 128;
    int sb = blockIdx.x;
    int b = sb >> 5;
    int y0 = (sb & 31) * 2;
    int co0 = blockIdx.y * 128;
    int t = threadIdx.x;
    int tx = t & 15, ty = t >> 4;

    __shared__ float wS[8][128];
    __shared__ float xS[8][128];

    float acc[8][8];
#pragma unroll
    for (int i = 0; i < 8; i++)
#pragma unroll
        for (int j = 0; j < 8; j++) acc[i][j] = 0.f;

    const float* xb = x + (size_t)b * Cin * HW;

    for (int tap = 0; tap < 9; ++tap) {
        int dy = tap / 3 - 1, dx = tap % 3 - 1;
        const float* wtap = wt + (size_t)tap * Cin * Cout;
        for (int ck = 0; ck < Cin; ck += 8) {
#pragma unroll
            for (int i = 0; i < 4; ++i) {
                int idx = t + i * 256;
                int k = idx >> 7, cc = idx & 127;
                wS[k][cc] = wtap[(size_t)(ck + k) * Cout + co0 + cc];
            }
#pragma unroll
            for (int i = 0; i < 4; ++i) {
                int idx = t + i * 256;
                int k = idx >> 7, n = idx & 127;
                int iy = y0 + (n >> 6) + dy;
                int ix = (n & 63) + dx;
                float v = 0.f;
                if ((unsigned)iy < 64u && (unsigned)ix < 64u)
                    v = xb[((size_t)(ck + k) * HH + iy) * WW + ix];
                xS[k][n] = v;
            }
            __syncthreads();
#pragma unroll
            for (int kk = 0; kk < 8; ++kk) {
                float a[8], bv[8];
#pragma unroll
                for (int i = 0; i < 8; i++) a[i] = wS[kk][ty * 8 + i];
#pragma unroll
                for (int j = 0; j < 8; j++) bv[j] = xS[kk][tx * 8 + j];
#pragma unroll
                for (int i = 0; i < 8; i++)
#pragma unroll
                    for (int j = 0; j < 8; j++) acc[i][j] = fmaf(a[i], bv[j], acc[i][j]);
            }
            __syncthreads();
        }
    }

#pragma unroll
    for (int i = 0; i < 8; i++) {
        int co = co0 + ty * 8 + i;
        float sc = s ? s[co] : 1.f;
        float bi = bias ? bias[co] : 0.f;
#pragma unroll
        for (int j = 0; j < 8; j++) {
            int n = tx * 8 + j;
            int yy = y0 + (n >> 6), xx = n & 63;
            float v = acc[i][j] * sc + bi;
            if (relu) v = fmaxf(v, 0.f);
            out[(((size_t)b * Cout + co) * HH + yy) * WW + xx] = v;
        }
    }
}

// ---------------- generic 128x128 GEMM: C[m,n] = sum_k A[m,k]*B[k,n] (NN) ----------------
// optional: bias[m]; or residual epilogue C = scale[0]*acc + Res.
__global__ void gemm_nn_kernel(const float* __restrict__ A, long aBS,
                               const float* __restrict__ Bm, long bBS,
                               float* __restrict__ C, long cBS,
                               const float* __restrict__ bias,
                               const float* __restrict__ scalePtr,
                               const float* __restrict__ Res,
                               int M, int N, int K) {
    int z = blockIdx.z;
    const float* Ab = A + (size_t)z * aBS;
    const float* Bb = Bm + (size_t)z * bBS;
    float* Cb = C + (size_t)z * cBS;
    const float* Rb = Res ? Res + (size_t)z * cBS : (const float*)0;
    int n0 = blockIdx.x * 128, m0 = blockIdx.y * 128;
    int t = threadIdx.x, tx = t & 15, ty = t >> 4;
    __shared__ float aS[8][128];
    __shared__ float bS[8][128];
    float acc[8][8];
#pragma unroll
    for (int i = 0; i < 8; i++)
#pragma unroll
        for (int j = 0; j < 8; j++) acc[i][j] = 0.f;

    int mload = t >> 1;
    int kq = (t & 1) * 4;

    for (int ck = 0; ck < K; ck += 8) {
        float4 av = make_float4(0.f, 0.f, 0.f, 0.f);
        if (m0 + mload < M)
            av = *(const float4*)(Ab + (size_t)(m0 + mload) * K + ck + kq);
        aS[kq + 0][mload] = av.x;
        aS[kq + 1][mload] = av.y;
        aS[kq + 2][mload] = av.z;
        aS[kq + 3][mload] = av.w;
#pragma unroll
        for (int i = 0; i < 4; ++i) {
            int idx = t + i * 256;
            int k = idx >> 7, n = idx & 127;
            bS[k][n] = Bb[(size_t)(ck + k) * N + n0 + n];
        }
        __syncthreads();
#pragma unroll
        for (int kk = 0; kk < 8; ++kk) {
            float a[8], bv[8];
#pragma unroll
            for (int i = 0; i < 8; i++) a[i] = aS[kk][ty * 8 + i];
#pragma unroll
            for (int j = 0; j < 8; j++) bv[j] = bS[kk][tx * 8 + j];
#pragma unroll
            for (int i = 0; i < 8; i++)
#pragma unroll
                for (int j = 0; j < 8; j++) acc[i][j] = fmaf(a[i], bv[j], acc[i][j]);
        }
        __syncthreads();
    }

    float scale = scalePtr ? scalePtr[0] : 1.f;
#pragma unroll
    for (int i = 0; i < 8; i++) {
        int m = m0 + ty * 8 + i;
        if (m < M) {
            float bi = bias ? bias[m] : 0.f;
#pragma unroll
            for (int j = 0; j < 8; j++) {
                int n = n0 + tx * 8 + j;
                size_t off = (size_t)m * N + n;
                float v = acc[i][j];
                if (Rb) v = scale * v + Rb[off];
                else v += bi;
                Cb[off] = v;
            }
        }
    }
}

// ---------------- generic 128x128 GEMM NT: C[m,n] = sum_k A[m,k]*B[n,k] ----------------
__global__ void gemm_nt_kernel(const float* __restrict__ A, long aBS,
                               const float* __restrict__ Bm, long bBS,
                               float* __restrict__ C, long cBS,
                               const float* __restrict__ bias,
                               const float* __restrict__ scalePtr,
                               const float* __restrict__ Res,
                               int M, int N, int K) {
    int z = blockIdx.z;
    const float* Ab = A + (size_t)z * aBS;
    const float* Bb = Bm + (size_t)z * bBS;
    float* Cb = C + (size_t)z * cBS;
    const float* Rb = Res ? Res + (size_t)z * cBS : (const float*)0;
    int n0 = blockIdx.x * 128, m0 = blockIdx.y * 128;
    int t = threadIdx.x, tx = t & 15, ty = t >> 4;
    __shared__ float aS[8][128];
    __shared__ float bS[8][128];
    float acc[8][8];
#pragma unroll
    for (int i = 0; i < 8; i++)
#pragma unroll
        for (int j = 0; j < 8; j++) acc[i][j] = 0.f;

    int rload = t >> 1;
    int kq = (t & 1) * 4;

    for (int ck = 0; ck < K; ck += 8) {
        float4 av = make_float4(0.f, 0.f, 0.f, 0.f);
        if (m0 + rload < M)
            av = *(const float4*)(Ab + (size_t)(m0 + rload) * K + ck + kq);
        aS[kq + 0][rload] = av.x;
        aS[kq + 1][rload] = av.y;
        aS[kq + 2][rload] = av.z;
        aS[kq + 3][rload] = av.w;
        float4 bv4 = *(const float4*)(Bb + (size_t)(n0 + rload) * K + ck + kq);
        bS[kq + 0][rload] = bv4.x;
        bS[kq + 1][rload] = bv4.y;
        bS[kq + 2][rload] = bv4.z;
        bS[kq + 3][rload] = bv4.w;
        __syncthreads();
#pragma unroll
        for (int kk = 0; kk < 8; ++kk) {
            float a[8], bv[8];
#pragma unroll
            for (int i = 0; i < 8; i++) a[i] = aS[kk][ty * 8 + i];
#pragma unroll
            for (int j = 0; j < 8; j++) bv[j] = bS[kk][tx * 8 + j];
#pragma unroll
            for (int i = 0; i < 8; i++)
#pragma unroll
                for (int j = 0; j < 8; j++) acc[i][j] = fmaf(a[i], bv[j], acc[i][j]);
        }
        __syncthreads();
    }

    float scale = scalePtr ? scalePtr[0] : 1.f;
#pragma unroll
    for (int i = 0; i < 8; i++) {
        int m = m0 + ty * 8 + i;
        if (m < M) {
            float bi = bias ? bias[m] : 0.f;
#pragma unroll
            for (int j = 0; j < 8; j++) {
                int n = n0 + tx * 8 + j;
                size_t off = (size_t)m * N + n;
                float v = acc[i][j];
                if (Rb) v = scale * v + Rb[off];
                else v += bi;
                Cb[off] = v;
            }
        }
    }
}

// ---------------- PAM attention logits: attn[b][n][m] = sum_c fb[b,c,n]*fc[b,c,m] ----------------
// grid (64, 64, 4), 256 threads, K=64 fully resident in smem.
__global__ void pam_logits_kernel(const float* __restrict__ fb, const float* __restrict__ fc,
                                  float* __restrict__ attn) {
    int b = blockIdx.z;
    int n0 = blockIdx.x * 64, m0 = blockIdx.y * 64;
    __shared__ float aS[64][65];
    __shared__ float bS[64][65];
    int t = threadIdx.x;
#pragma unroll
    for (int i = 0; i < 16; i++) {
        int idx = t + i * 256;
        int c = idx >> 6, n = idx & 63;
        aS[c][n] = fb[((size_t)b * 64 + c) * HW + n0 + n];
        bS[c][n] = fc[((size_t)b * 64 + c) * HW + m0 + n];
    }
    __syncthreads();
    int tx = t & 15, ty = t >> 4;
    float acc[4][4];
#pragma unroll
    for (int i = 0; i < 4; i++)
#pragma unroll
        for (int j = 0; j < 4; j++) acc[i][j] = 0.f;
#pragma unroll 8
    for (int c = 0; c < 64; c++) {
        float a[4], bv[4];
#pragma unroll
        for (int i = 0; i < 4; i++) a[i] = aS[c][ty * 4 + i];
#pragma unroll
        for (int j = 0; j < 4; j++) bv[j] = bS[c][tx * 4 + j];
#pragma unroll
        for (int i = 0; i < 4; i++)
#pragma unroll
            for (int j = 0; j < 4; j++) acc[i][j] = fmaf(a[i], bv[j], acc[i][j]);
    }
    float* dst = attn + (size_t)b * HW * HW;
#pragma unroll
    for (int i = 0; i < 4; i++)
#pragma unroll
        for (int j = 0; j < 4; j++)
            dst[(size_t)(n0 + ty * 4 + i) * HW + m0 + tx * 4 + j] = acc[i][j];
}

// ---------------- row softmax, cols = 4096, one block per row ----------------
__global__ void softmax4096_kernel(float* __restrict__ data) {
    size_t row = blockIdx.x;
    float4* p4 = (float4*)(data + row * (size_t)HW);
    int t = threadIdx.x;
    float4 v[4];
    float m = -1e30f;
#pragma unroll
    for (int i = 0; i < 4; i++) {
        v[i] = p4[t + i * 256];
        m = fmaxf(m, fmaxf(fmaxf(v[i].x, v[i].y), fmaxf(v[i].z, v[i].w)));
    }
    __shared__ float red[256];
    red[t] = m;
    __syncthreads();
    for (int s = 128; s > 0; s >>= 1) {
        if (t < s) red[t] = fmaxf(red[t], red[t + s]);
        __syncthreads();
    }
    m = red[0];
    __syncthreads();
    float sum = 0.f;
#pragma unroll
    for (int i = 0; i < 4; i++) {
        v[i].x = __expf(v[i].x - m);
        v[i].y = __expf(v[i].y - m);
        v[i].z = __expf(v[i].z - m);
        v[i].w = __expf(v[i].w - m);
        sum += v[i].x + v[i].y + v[i].z + v[i].w;
    }
    red[t] = sum;
    __syncthreads();
    for (int s = 128; s > 0; s >>= 1) {
        if (t < s) red[t] += red[t + s];
        __syncthreads();
    }
    float inv = 1.f / red[0];
#pragma unroll
    for (int i = 0; i < 4; i++) {
        v[i].x *= inv; v[i].y *= inv; v[i].z *= inv; v[i].w *= inv;
        p4[t + i * 256] = v[i];
    }
}

// ---------------- CAM softmax: row length 512, softmax(rowmax - x) ----------------
__global__ void cam_softmax_kernel(float* __restrict__ data) {
    float4* p4 = (float4*)(data + (size_t)blockIdx.x * IC);
    int t = threadIdx.x;  // 128 threads
    float4 v = p4[t];
    __shared__ float red[128];
    float m = fmaxf(fmaxf(v.x, v.y), fmaxf(v.z, v.w));
    red[t] = m;
    __syncthreads();
    for (int s = 64; s > 0; s >>= 1) {
        if (t < s) red[t] = fmaxf(red[t], red[t + s]);
        __syncthreads();
    }
    float m1 = red[0];
    __syncthreads();
    // w = m1 - x; softmax(w): m2 = max(w) = m1 - min(x)
    float mn = fminf(fminf(v.x, v.y), fminf(v.z, v.w));
    red[t] = mn;
    __syncthreads();
    for (int s = 64; s > 0; s >>= 1) {
        if (t < s) red[t] = fminf(red[t], red[t + s]);
        __syncthreads();
    }
    float m2 = m1 - red[0];
    __syncthreads();
    float4 e;
    e.x = __expf(m1 - v.x - m2);
    e.y = __expf(m1 - v.y - m2);
    e.z = __expf(m1 - v.z - m2);
    e.w = __expf(m1 - v.w - m2);
    red[t] = e.x + e.y + e.z + e.w;
    __syncthreads();
    for (int s = 64; s > 0; s >>= 1) {
        if (t < s) red[t] += red[t + s];
        __syncthreads();
    }
    float inv = 1.f / red[0];
    e.x *= inv; e.y *= inv; e.z *= inv; e.w *= inv;
    p4[t] = e;
}

// ---------------- elementwise add ----------------
__global__ void add_kernel(const float* __restrict__ a, const float* __restrict__ b,
                           float* __restrict__ c, int n) {
    int i = blockIdx.x * 256 + threadIdx.x;
    if (i < n) c[i] = a[i] + b[i];
}

// ---------------- bilinear 2x upsample (half-pixel, edge clamp) ----------------
__global__ void up2x_kernel(const float* __restrict__ src, float* __restrict__ dst) {
    int idx = blockIdx.x * 256 + threadIdx.x;
    const int total = BB * NCLS * OHW;
    if (idx >= total) return;
    int ox = idx & 127;
    int r = idx >> 7;
    int oy = r & 127;
    r >>= 7;  // b*81 + c
    float sy = oy * 0.5f - 0.25f;
    float sx = ox * 0.5f - 0.25f;
    float fy = floorf(sy), fx = floorf(sx);
    float wy = sy - fy, wx = sx - fx;
    int y0 = (int)fy, x0 = (int)fx;
    int y0c = max(y0, 0), y1c = min(y0 + 1, 63);
    int x0c = max(x0, 0), x1c = min(x0 + 1, 63);
    const float* s = src + (size_t)r * HW;
    float v00 = s[y0c * 64 + x0c], v01 = s[y0c * 64 + x1c];
    float v10 = s[y1c * 64 + x0c], v11 = s[y1c * 64 + x1c];
    dst[idx] = (1.f - wy) * ((1.f - wx) * v00 + wx * v01) +
               wy * ((1.f - wx) * v10 + wx * v11);
}

// ---------------- orchestration ----------------
extern "C" void kernel_launch(void* const* d_in, const int* in_sizes, int n_in,
                              void* d_out, int out_size) {
    (void)in_sizes; (void)n_in; (void)out_size;
    const float* x    = (const float*)d_in[0];
    const float* wp1  = (const float*)d_in[1];
    const float* sp1  = (const float*)d_in[2];
    const float* bp1  = (const float*)d_in[3];
    const float* wc1  = (const float*)d_in[4];
    const float* sc1  = (const float*)d_in[5];
    const float* bc1  = (const float*)d_in[6];
    const float* pwb  = (const float*)d_in[7];
    const float* pbb  = (const float*)d_in[8];
    const float* pwc  = (const float*)d_in[9];
    const float* pbc  = (const float*)d_in[10];
    const float* pwd  = (const float*)d_in[11];
    const float* pbd  = (const float*)d_in[12];
    const float* alpha = (const float*)d_in[13];
    const float* beta  = (const float*)d_in[14];
    const float* wp2  = (const float*)d_in[15];
    const float* sp2  = (const float*)d_in[16];
    const float* bp2  = (const float*)d_in[17];
    const float* wc2  = (const float*)d_in[18];
    const float* sc2  = (const float*)d_in[19];
    const float* bc2  = (const float*)d_in[20];
    const float* wlog = (const float*)d_in[21];
    const float* blog = (const float*)d_in[22];
    const float* wp3  = (const float*)d_in[23];
    const float* bp3  = (const float*)d_in[24];
    const float* wc3  = (const float*)d_in[25];
    const float* bc3  = (const float*)d_in[26];
    float* out = (float*)d_out;

    float *wt1p, *wt1c, *wt2p, *wt2c, *featp0, *featc0, *fb, *fc, *fd, *attn;
    float *pam, *featp, *camatt, *cam, *featc, *fusion, *pout, *cout_, *fout;
    cudaGetSymbolAddress((void**)&wt1p, g_wt1p);
    cudaGetSymbolAddress((void**)&wt1c, g_wt1c);
    cudaGetSymbolAddress((void**)&wt2p, g_wt2p);
    cudaGetSymbolAddress((void**)&wt2c, g_wt2c);
    cudaGetSymbolAddress((void**)&featp0, g_featp0);
    cudaGetSymbolAddress((void**)&featc0, g_featc0);
    cudaGetSymbolAddress((void**)&fb, g_fb);
    cudaGetSymbolAddress((void**)&fc, g_fc);
    cudaGetSymbolAddress((void**)&fd, g_fd);
    cudaGetSymbolAddress((void**)&attn, g_attn);
    cudaGetSymbolAddress((void**)&pam, g_pam);
    cudaGetSymbolAddress((void**)&featp, g_featp);
    cudaGetSymbolAddress((void**)&camatt, g_camatt);
    cudaGetSymbolAddress((void**)&cam, g_cam);
    cudaGetSymbolAddress((void**)&featc, g_featc);
    cudaGetSymbolAddress((void**)&fusion, g_fusion);
    cudaGetSymbolAddress((void**)&pout, g_pout);
    cudaGetSymbolAddress((void**)&cout_, g_cout);
    cudaGetSymbolAddress((void**)&fout, g_fout);

    // 1) weight transposes
    wtrans_kernel<<<4096, 256>>>(wp1, wt1p, CIN, IC);
    wtrans_kernel<<<4096, 256>>>(wc1, wt1c, CIN, IC);
    wtrans_kernel<<<2048, 256>>>(wp2, wt2p, IC, IC);
    wtrans_kernel<<<2048, 256>>>(wc2, wt2c, IC, IC);

    // 2) first convs: 2048 -> 512, BN fold + relu
    conv3x3_kernel<<<dim3(128, 4), 256>>>(x, wt1p, featp0, sp1, bp1, CIN, 1);
    conv3x3_kernel<<<dim3(128, 4), 256>>>(x, wt1c, featc0, sc1, bc1, CIN, 1);

    // 3) PAM projections (1x1 convs)
    gemm_nn_kernel<<<dim3(32, 1, 4), 256>>>(pwb, 0, featp0, (long)IC * HW,
                                            fb, (long)C8 * HW, pbb, 0, 0, C8, HW, IC);
    gemm_nn_kernel<<<dim3(32, 1, 4), 256>>>(pwc, 0, featp0, (long)IC * HW,
                                            fc, (long)C8 * HW, pbc, 0, 0, C8, HW, IC);
    gemm_nn_kernel<<<dim3(32, 4, 4), 256>>>(pwd, 0, featp0, (long)IC * HW,
                                            fd, (long)IC * HW, pbd, 0, 0, IC, HW, IC);

    // 4) attention logits + softmax
    pam_logits_kernel<<<dim3(64, 64, 4), 256>>>(fb, fc, attn);
    softmax4096_kernel<<<BB * HW, 256>>>(attn);

    // 5) PAM apply: pam = alpha * (fd @ attn^T) + featp0
    gemm_nt_kernel<<<dim3(32, 4, 4), 256>>>(fd, (long)IC * HW, attn, (long)HW * HW,
                                            pam, (long)IC * HW, 0, alpha, featp0,
                                            IC, HW, HW);

    // 6) conv p2
    conv3x3_kernel<<<dim3(128, 4), 256>>>(pam, wt2p, featp, sp2, bp2, IC, 1);

    // 7) CAM: gram, softmax, apply
    gemm_nt_kernel<<<dim3(4, 4, 4), 256>>>(featc0, (long)IC * HW, featc0, (long)IC * HW,
                                           camatt, (long)IC * IC, 0, 0, 0,
                                           IC, IC, HW);
    cam_softmax_kernel<<<BB * IC, 128>>>(camatt);
    gemm_nn_kernel<<<dim3(32, 4, 4), 256>>>(camatt, (long)IC * IC, featc0, (long)IC * HW,
                                            cam, (long)IC * HW, 0, beta, featc0,
                                            IC, HW, IC);

    // 8) conv c2
    conv3x3_kernel<<<dim3(128, 4), 256>>>(cam, wt2c, featc, sc2, bc2, IC, 1);

    // 9) fusion + output heads (1x1 convs)
    add_kernel<<<(BB * IC * HW) / 256, 256>>>(featp, featc, fusion, BB * IC * HW);
    gemm_nn_kernel<<<dim3(32, 1, 4), 256>>>(wp3, 0, featp, (long)IC * HW,
                                            pout, (long)NCLS * HW, bp3, 0, 0, NCLS, HW, IC);
    gemm_nn_kernel<<<dim3(32, 1, 4), 256>>>(wc3, 0, featc, (long)IC * HW,
                                            cout_, (long)NCLS * HW, bc3, 0, 0, NCLS, HW, IC);
    gemm_nn_kernel<<<dim3(32, 1, 4), 256>>>(wlog, 0, fusion, (long)IC * HW,
                                            fout, (long)NCLS * HW, blog, 0, 0, NCLS, HW, IC);

    // 10) upsample 2x into output: (p, c, fusion) order
    const int outElems = BB * NCLS * OHW;  // 5,308,416 per tensor
    up2x_kernel<<<(outElems + 255) / 256, 256>>>(pout, out);
    up2x_kernel<<<(outElems + 255) / 256, 256>>>(cout_, out + outElems);
    up2x_kernel<<<(outElems + 255) / 256, 256>>>(fout, out + 2 * (size_t)outElems);
}

// round 4
// speedup vs baseline: 1.2327x; 1.2327x over previous
#include <cuda_runtime.h>
#include <cuda_bf16.h>
#include <math.h>
#include <stdint.h>

// ---------------- problem constants ----------------
#define BB 4
#define CIN 2048
#define IC 512
#define C8 64
#define NCLS 81
#define HH 64
#define WW 64
#define HW 4096
#define OHW (128*128)

// ---------------- scratch (__device__ globals, no runtime alloc) ----------------
__device__ float g_wt1p[9*CIN*IC];
__device__ float g_wt1cs[9*3*CIN*IC];   // 3x split: (hi, lo, hi) per channel along K
__device__ float g_wt2p[9*IC*IC];
__device__ float g_wt2cs[9*3*IC*IC];    // 3x split
__device__ float g_featp0[BB*IC*HW];
__device__ float g_featc0[BB*IC*HW];
__device__ float g_fb[BB*C8*HW];
__device__ float g_fc[BB*C8*HW];
__device__ float g_fd[BB*IC*HW];
__device__ float g_attn[(size_t)BB*HW*HW];
__device__ float g_pam[BB*IC*HW];
__device__ float g_featp[BB*IC*HW];
__device__ float g_camatt[BB*IC*IC];
__device__ float g_cam[BB*IC*HW];
__device__ float g_featc[BB*IC*HW];
__device__ float g_fusion[BB*IC*HW];
__device__ float g_pout[BB*NCLS*HW];
__device__ float g_cout[BB*NCLS*HW];
__device__ float g_fout[BB*NCLS*HW];

// ---------------- helpers ----------------
__device__ __forceinline__ uint32_t f2tf32(float f) {
    uint32_t r;
    asm("cvt.rna.tf32.f32 %0, %1;" : "=r"(r) : "f"(f));
    return r;
}

__device__ __forceinline__ void mma_tf32(float* c, const uint32_t* a, const uint32_t* b) {
    asm volatile(
        "mma.sync.aligned.m16n8k8.row.col.f32.tf32.tf32.f32 "
        "{%0,%1,%2,%3}, {%4,%5,%6,%7}, {%8,%9}, {%0,%1,%2,%3};"
        : "+f"(c[0]), "+f"(c[1]), "+f"(c[2]), "+f"(c[3])
        : "r"(a[0]), "r"(a[1]), "r"(a[2]), "r"(a[3]), "r"(b[0]), "r"(b[1]));
}

// ---------------- weight transpose: wt[(tap*Cin+ci)*Cout+co] = w[(co*Cin+ci)*9+tap] ----------------
__global__ void wtrans_kernel(const float* __restrict__ w, float* __restrict__ wt,
                              int Cin, int Cout) {
    size_t total = (size_t)Cout * Cin * 9;
    for (size_t i = (size_t)blockIdx.x * blockDim.x + threadIdx.x; i < total;
         i += (size_t)gridDim.x * blockDim.x) {
        int co = (int)(i % Cout);
        size_t r = i / Cout;
        int ci = (int)(r % Cin);
        int tap = (int)(r / Cin);
        wt[i] = w[((size_t)co * Cin + ci) * 9 + tap];
    }
}

// ---------------- 3x split weight transpose ----------------
// K-slot layout per channel: part0 = w (-> hi), part1 = w - tf32(w) (lo), part2 = w (-> hi).
// Pairs with activation phases (hi, hi, lo): product = w*x - lo_w*lo_x (~2^-22).
__global__ void wsplit3_kernel(const float* __restrict__ w, float* __restrict__ wt,
                               int Cin, int Cout) {
    size_t total = (size_t)Cout * Cin * 3 * 9;
    for (size_t i = (size_t)blockIdx.x * blockDim.x + threadIdx.x; i < total;
         i += (size_t)gridDim.x * blockDim.x) {
        int co = (int)(i % Cout);
        size_t r = i / Cout;
        int part = (int)(r % 3);
        int ci = (int)((r / 3) % Cin);
        int tap = (int)(r / (3 * (size_t)Cin));
        float v = w[((size_t)co * Cin + ci) * 9 + tap];
        if (part == 1) {
            float vh = __uint_as_float(f2tf32(v));
            v = v - vh;
        }
        wt[i] = v;
    }
}

// ---------------- 3x3 conv via tf32 tensor-core implicit GEMM ----------------
// Tile: 128 couts (M) x 128 spatial (N, 2 image rows), BK=16, double-buffered.
// 8 warps: 4 in M x 2 in N; per warp 2x8 m16n8k8 tiles.
// SPLIT=3: K holds 3 slots per channel (w:hi,lo,hi ; x:hi,hi,lo) -> fp32-grade accuracy.
#define CPAD 136

template<int SPLIT>
__global__ __launch_bounds__(256, 2)
void conv3x3_mma_kernel(const float* __restrict__ x, const float* __restrict__ wt,
                        float* __restrict__ out,
                        const float* __restrict__ s, const float* __restrict__ bias,
                        int CinK, int relu) {
    const int Cout = gridDim.y * 128;
    const int Cin = CinK / SPLIT;
    int sb = blockIdx.x;
    int b = sb >> 5;
    int y0 = (sb & 31) * 2;
    int co0 = blockIdx.y * 128;
    int t = threadIdx.x;
    int lane = t & 31, wid = t >> 5;
    int wm = (wid & 3) * 32;       // warp M offset
    int wn = (wid >> 2) * 64;      // warp N offset
    int lg = lane >> 2, lq = lane & 3;

    __shared__ uint32_t aS[2][16][CPAD];   // [k][m], tf32 bits
    __shared__ uint32_t bS[2][16][CPAD];   // [k][n], tf32 bits

    float acc[2][8][4];
#pragma unroll
    for (int i = 0; i < 2; i++)
#pragma unroll
        for (int j = 0; j < 8; j++)
#pragma unroll
            for (int q = 0; q < 4; q++) acc[i][j][q] = 0.f;

    const float* xb = x + (size_t)b * Cin * HW;
    const int iters = 9 * CinK / 16;

    float aR[8], bR[8];

    // ---- prologue: load tile 0 (tap 0: dy=-1, dx=-1; slot base 0) ----
    {
#pragma unroll
        for (int i = 0; i < 2; i++) {
            int f = t + i * 256;
            int k = f >> 5, m4 = (f & 31) * 4;
            float4 v = *(const float4*)(wt + (size_t)k * Cout + co0 + m4);
            aR[i * 4 + 0] = v.x; aR[i * 4 + 1] = v.y;
            aR[i * 4 + 2] = v.z; aR[i * 4 + 3] = v.w;
        }
#pragma unroll
        for (int i = 0; i < 8; i++) {
            int f = t + i * 256;
            int k = f >> 7, n = f & 127;
            int ci = (SPLIT == 1) ? k : (k / SPLIT);
            int ph = (SPLIT == 1) ? 0 : (k % SPLIT);
            int iy = y0 + (n >> 6) - 1, ix = (n & 63) - 1;
            float v = 0.f;
            if ((unsigned)iy < 64u && (unsigned)ix < 64u)
                v = xb[((size_t)ci * HH + iy) * WW + ix];
            if (SPLIT != 1 && ph == 2) v = v - __uint_as_float(f2tf32(v));
            bR[i] = v;
        }
#pragma unroll
        for (int i = 0; i < 2; i++) {
            int f = t + i * 256;
            int k = f >> 5, m4 = (f & 31) * 4;
#pragma unroll
            for (int j = 0; j < 4; j++) aS[0][k][m4 + j] = f2tf32(aR[i * 4 + j]);
        }
#pragma unroll
        for (int i = 0; i < 8; i++) {
            int f = t + i * 256;
            int k = f >> 7, n = f & 127;
            bS[0][k][n] = f2tf32(bR[i]);
        }
    }
    __syncthreads();

    for (int kt = 0; kt < iters; kt++) {
        int cur = kt & 1;
        bool more = (kt + 1 < iters);

        if (more) {
            int gk0 = (kt + 1) * 16;
#pragma unroll
            for (int i = 0; i < 2; i++) {
                int f = t + i * 256;
                int k = f >> 5, m4 = (f & 31) * 4;
                float4 v = *(const float4*)(wt + (size_t)(gk0 + k) * Cout + co0 + m4);
                aR[i * 4 + 0] = v.x; aR[i * 4 + 1] = v.y;
                aR[i * 4 + 2] = v.z; aR[i * 4 + 3] = v.w;
            }
            int tap = gk0 / CinK;
            int rem = gk0 - tap * CinK;
            int dy = tap / 3 - 1, dx = tap % 3 - 1;
#pragma unroll
            for (int i = 0; i < 8; i++) {
                int f = t + i * 256;
                int k = f >> 7, n = f & 127;
                int slot = rem + k;
                int ci = (SPLIT == 1) ? slot : (slot / SPLIT);
                int ph = (SPLIT == 1) ? 0 : (slot % SPLIT);
                int iy = y0 + (n >> 6) + dy, ix = (n & 63) + dx;
                float v = 0.f;
                if ((unsigned)iy < 64u && (unsigned)ix < 64u)
                    v = xb[((size_t)ci * HH + iy) * WW + ix];
                if (SPLIT != 1 && ph == 2) v = v - __uint_as_float(f2tf32(v));
                bR[i] = v;
            }
        }

        // ---- compute on cur ----
#pragma unroll
        for (int k0 = 0; k0 < 16; k0 += 8) {
            uint32_t af[2][4], bf[8][2];
#pragma unroll
            for (int mt = 0; mt < 2; mt++) {
                int m = wm + mt * 16;
                af[mt][0] = aS[cur][k0 + lq][m + lg];
                af[mt][1] = aS[cur][k0 + lq][m + 8 + lg];
                af[mt][2] = aS[cur][k0 + 4 + lq][m + lg];
                af[mt][3] = aS[cur][k0 + 4 + lq][m + 8 + lg];
            }
#pragma unroll
            for (int nt = 0; nt < 8; nt++) {
                int n = wn + nt * 8;
                bf[nt][0] = bS[cur][k0 + lq][n + lg];
                bf[nt][1] = bS[cur][k0 + 4 + lq][n + lg];
            }
#pragma unroll
            for (int mt = 0; mt < 2; mt++)
#pragma unroll
                for (int nt = 0; nt < 8; nt++)
                    mma_tf32(acc[mt][nt], af[mt], bf[nt]);
        }

        if (more) {
            int nb = cur ^ 1;
#pragma unroll
            for (int i = 0; i < 2; i++) {
                int f = t + i * 256;
                int k = f >> 5, m4 = (f & 31) * 4;
#pragma unroll
                for (int j = 0; j < 4; j++) aS[nb][k][m4 + j] = f2tf32(aR[i * 4 + j]);
            }
#pragma unroll
            for (int i = 0; i < 8; i++) {
                int f = t + i * 256;
                int k = f >> 7, n = f & 127;
                bS[nb][k][n] = f2tf32(bR[i]);
            }
        }
        __syncthreads();
    }

    // ---- epilogue: scale/bias/relu, float2 stores ----
#pragma unroll
    for (int mt = 0; mt < 2; mt++) {
        int r0 = co0 + wm + mt * 16 + lg;   // rows r0 and r0+8
        float s0 = s ? s[r0] : 1.f, s1 = s ? s[r0 + 8] : 1.f;
        float b0 = bias ? bias[r0] : 0.f, b1 = bias ? bias[r0 + 8] : 0.f;
#pragma unroll
        for (int nt = 0; nt < 8; nt++) {
            int col = wn + nt * 8 + lq * 2;
            int yy = y0 + (col >> 6), xx = col & 63;
            float v0 = acc[mt][nt][0] * s0 + b0;
            float v1 = acc[mt][nt][1] * s0 + b0;
            float v2 = acc[mt][nt][2] * s1 + b1;
            float v3 = acc[mt][nt][3] * s1 + b1;
            if (relu) {
                v0 = fmaxf(v0, 0.f); v1 = fmaxf(v1, 0.f);
                v2 = fmaxf(v2, 0.f); v3 = fmaxf(v3, 0.f);
            }
            size_t o0 = (((size_t)b * Cout + r0) * HH + yy) * WW + xx;
            size_t o1 = (((size_t)b * Cout + r0 + 8) * HH + yy) * WW + xx;
            *(float2*)(out + o0) = make_float2(v0, v1);
            *(float2*)(out + o1) = make_float2(v2, v3);
        }
    }
}

// ---------------- generic 128x128 GEMM: C[m,n] = sum_k A[m,k]*B[k,n] (NN) ----------------
__global__ void gemm_nn_kernel(const float* __restrict__ A, long aBS,
                               const float* __restrict__ Bm, long bBS,
                               float* __restrict__ C, long cBS,
                               const float* __restrict__ bias,
                               const float* __restrict__ scalePtr,
                               const float* __restrict__ Res,
                               int M, int N, int K) {
    int z = blockIdx.z;
    const float* Ab = A + (size_t)z * aBS;
    const float* Bb = Bm + (size_t)z * bBS;
    float* Cb = C + (size_t)z * cBS;
    const float* Rb = Res ? Res + (size_t)z * cBS : (const float*)0;
    int n0 = blockIdx.x * 128, m0 = blockIdx.y * 128;
    int t = threadIdx.x, tx = t & 15, ty = t >> 4;
    __shared__ float aS[8][128];
    __shared__ float bS[8][128];
    float acc[8][8];
#pragma unroll
    for (int i = 0; i < 8; i++)
#pragma unroll
        for (int j = 0; j < 8; j++) acc[i][j] = 0.f;

    int mload = t >> 1;
    int kq = (t & 1) * 4;

    for (int ck = 0; ck < K; ck += 8) {
        float4 av = make_float4(0.f, 0.f, 0.f, 0.f);
        if (m0 + mload < M)
            av = *(const float4*)(Ab + (size_t)(m0 + mload) * K + ck + kq);
        aS[kq + 0][mload] = av.x;
        aS[kq + 1][mload] = av.y;
        aS[kq + 2][mload] = av.z;
        aS[kq + 3][mload] = av.w;
#pragma unroll
        for (int i = 0; i < 4; ++i) {
            int idx = t + i * 256;
            int k = idx >> 7, n = idx & 127;
            bS[k][n] = Bb[(size_t)(ck + k) * N + n0 + n];
        }
        __syncthreads();
#pragma unroll
        for (int kk = 0; kk < 8; ++kk) {
            float a[8], bv[8];
#pragma unroll
            for (int i = 0; i < 8; i++) a[i] = aS[kk][ty * 8 + i];
#pragma unroll
            for (int j = 0; j < 8; j++) bv[j] = bS[kk][tx * 8 + j];
#pragma unroll
            for (int i = 0; i < 8; i++)
#pragma unroll
                for (int j = 0; j < 8; j++) acc[i][j] = fmaf(a[i], bv[j], acc[i][j]);
        }
        __syncthreads();
    }

    float scale = scalePtr ? scalePtr[0] : 1.f;
#pragma unroll
    for (int i = 0; i < 8; i++) {
        int m = m0 + ty * 8 + i;
        if (m < M) {
            float bi = bias ? bias[m] : 0.f;
#pragma unroll
            for (int j = 0; j < 8; j++) {
                int n = n0 + tx * 8 + j;
                size_t off = (size_t)m * N + n;
                float v = acc[i][j];
                if (Rb) v = scale * v + Rb[off];
                else v += bi;
                Cb[off] = v;
            }
        }
    }
}

// ---------------- generic 128x128 GEMM NT: C[m,n] = sum_k A[m,k]*B[n,k] ----------------
__global__ void gemm_nt_kernel(const float* __restrict__ A, long aBS,
                               const float* __restrict__ Bm, long bBS,
                               float* __restrict__ C, long cBS,
                               const float* __restrict__ bias,
                               const float* __restrict__ scalePtr,
                               const float* __restrict__ Res,
                               int M, int N, int K) {
    int z = blockIdx.z;
    const float* Ab = A + (size_t)z * aBS;
    const float* Bb = Bm + (size_t)z * bBS;
    float* Cb = C + (size_t)z * cBS;
    const float* Rb = Res ? Res + (size_t)z * cBS : (const float*)0;
    int n0 = blockIdx.x * 128, m0 = blockIdx.y * 128;
    int t = threadIdx.x, tx = t & 15, ty = t >> 4;
    __shared__ float aS[8][128];
    __shared__ float bS[8][128];
    float acc[8][8];
#pragma unroll
    for (int i = 0; i < 8; i++)
#pragma unroll
        for (int j = 0; j < 8; j++) acc[i][j] = 0.f;

    int rload = t >> 1;
    int kq = (t & 1) * 4;

    for (int ck = 0; ck < K; ck += 8) {
        float4 av = make_float4(0.f, 0.f, 0.f, 0.f);
        if (m0 + rload < M)
            av = *(const float4*)(Ab + (size_t)(m0 + rload) * K + ck + kq);
        aS[kq + 0][rload] = av.x;
        aS[kq + 1][rload] = av.y;
        aS[kq + 2][rload] = av.z;
        aS[kq + 3][rload] = av.w;
        float4 bv4 = *(const float4*)(Bb + (size_t)(n0 + rload) * K + ck + kq);
        bS[kq + 0][rload] = bv4.x;
        bS[kq + 1][rload] = bv4.y;
        bS[kq + 2][rload] = bv4.z;
        bS[kq + 3][rload] = bv4.w;
        __syncthreads();
#pragma unroll
        for (int kk = 0; kk < 8; ++kk) {
            float a[8], bv[8];
#pragma unroll
            for (int i = 0; i < 8; i++) a[i] = aS[kk][ty * 8 + i];
#pragma unroll
            for (int j = 0; j < 8; j++) bv[j] = bS[kk][tx * 8 + j];
#pragma unroll
            for (int i = 0; i < 8; i++)
#pragma unroll
                for (int j = 0; j < 8; j++) acc[i][j] = fmaf(a[i], bv[j], acc[i][j]);
        }
        __syncthreads();
    }

    float scale = scalePtr ? scalePtr[0] : 1.f;
#pragma unroll
    for (int i = 0; i < 8; i++) {
        int m = m0 + ty * 8 + i;
        if (m < M) {
            float bi = bias ? bias[m] : 0.f;
#pragma unroll
            for (int j = 0; j < 8; j++) {
                int n = n0 + tx * 8 + j;
                size_t off = (size_t)m * N + n;
                float v = acc[i][j];
                if (Rb) v = scale * v + Rb[off];
                else v += bi;
                Cb[off] = v;
            }
        }
    }
}

// ---------------- PAM attention logits ----------------
__global__ void pam_logits_kernel(const float* __restrict__ fb, const float* __restrict__ fc,
                                  float* __restrict__ attn) {
    int b = blockIdx.z;
    int n0 = blockIdx.x * 64, m0 = blockIdx.y * 64;
    __shared__ float aS[64][65];
    __shared__ float bS[64][65];
    int t = threadIdx.x;
#pragma unroll
    for (int i = 0; i < 16; i++) {
        int idx = t + i * 256;
        int c = idx >> 6, n = idx & 63;
        aS[c][n] = fb[((size_t)b * 64 + c) * HW + n0 + n];
        bS[c][n] = fc[((size_t)b * 64 + c) * HW + m0 + n];
    }
    __syncthreads();
    int tx = t & 15, ty = t >> 4;
    float acc[4][4];
#pragma unroll
    for (int i = 0; i < 4; i++)
#pragma unroll
        for (int j = 0; j < 4; j++) acc[i][j] = 0.f;
#pragma unroll 8
    for (int c = 0; c < 64; c++) {
        float a[4], bv[4];
#pragma unroll
        for (int i = 0; i < 4; i++) a[i] = aS[c][ty * 4 + i];
#pragma unroll
        for (int j = 0; j < 4; j++) bv[j] = bS[c][tx * 4 + j];
#pragma unroll
        for (int i = 0; i < 4; i++)
#pragma unroll
            for (int j = 0; j < 4; j++) acc[i][j] = fmaf(a[i], bv[j], acc[i][j]);
    }
    float* dst = attn + (size_t)b * HW * HW;
#pragma unroll
    for (int i = 0; i < 4; i++)
#pragma unroll
        for (int j = 0; j < 4; j++)
            dst[(size_t)(n0 + ty * 4 + i) * HW + m0 + tx * 4 + j] = acc[i][j];
}

// ---------------- row softmax, cols = 4096 ----------------
__global__ void softmax4096_kernel(float* __restrict__ data) {
    size_t row = blockIdx.x;
    float4* p4 = (float4*)(data + row * (size_t)HW);
    int t = threadIdx.x;
    float4 v[4];
    float m = -1e30f;
#pragma unroll
    for (int i = 0; i < 4; i++) {
        v[i] = p4[t + i * 256];
        m = fmaxf(m, fmaxf(fmaxf(v[i].x, v[i].y), fmaxf(v[i].z, v[i].w)));
    }
    __shared__ float red[256];
    red[t] = m;
    __syncthreads();
    for (int s = 128; s > 0; s >>= 1) {
        if (t < s) red[t] = fmaxf(red[t], red[t + s]);
        __syncthreads();
    }
    m = red[0];
    __syncthreads();
    float sum = 0.f;
#pragma unroll
    for (int i = 0; i < 4; i++) {
        v[i].x = __expf(v[i].x - m);
        v[i].y = __expf(v[i].y - m);
        v[i].z = __expf(v[i].z - m);
        v[i].w = __expf(v[i].w - m);
        sum += v[i].x + v[i].y + v[i].z + v[i].w;
    }
    red[t] = sum;
    __syncthreads();
    for (int s = 128; s > 0; s >>= 1) {
        if (t < s) red[t] += red[t + s];
        __syncthreads();
    }
    float inv = 1.f / red[0];
#pragma unroll
    for (int i = 0; i < 4; i++) {
        v[i].x *= inv; v[i].y *= inv; v[i].z *= inv; v[i].w *= inv;
        p4[t + i * 256] = v[i];
    }
}

// ---------------- CAM softmax: row length 512, softmax(rowmax - x) ----------------
__global__ void cam_softmax_kernel(float* __restrict__ data) {
    float4* p4 = (float4*)(data + (size_t)blockIdx.x * IC);
    int t = threadIdx.x;  // 128 threads
    float4 v = p4[t];
    __shared__ float red[128];
    float m = fmaxf(fmaxf(v.x, v.y), fmaxf(v.z, v.w));
    red[t] = m;
    __syncthreads();
    for (int s = 64; s > 0; s >>= 1) {
        if (t < s) red[t] = fmaxf(red[t], red[t + s]);
        __syncthreads();
    }
    float m1 = red[0];
    __syncthreads();
    float mn = fminf(fminf(v.x, v.y), fminf(v.z, v.w));
    red[t] = mn;
    __syncthreads();
    for (int s = 64; s > 0; s >>= 1) {
        if (t < s) red[t] = fminf(red[t], red[t + s]);
        __syncthreads();
    }
    float m2 = m1 - red[0];
    __syncthreads();
    float4 e;
    e.x = __expf(m1 - v.x - m2);
    e.y = __expf(m1 - v.y - m2);
    e.z = __expf(m1 - v.z - m2);
    e.w = __expf(m1 - v.w - m2);
    red[t] = e.x + e.y + e.z + e.w;
    __syncthreads();
    for (int s = 64; s > 0; s >>= 1) {
        if (t < s) red[t] += red[t + s];
        __syncthreads();
    }
    float inv = 1.f / red[0];
    e.x *= inv; e.y *= inv; e.z *= inv; e.w *= inv;
    p4[t] = e;
}

// ---------------- elementwise add ----------------
__global__ void add_kernel(const float* __restrict__ a, const float* __restrict__ b,
                           float* __restrict__ c, int n) {
    int i = blockIdx.x * 256 + threadIdx.x;
    if (i < n) c[i] = a[i] + b[i];
}

// ---------------- bilinear 2x upsample (half-pixel, edge clamp) ----------------
__global__ void up2x_kernel(const float* __restrict__ src, float* __restrict__ dst) {
    int idx = blockIdx.x * 256 + threadIdx.x;
    const int total = BB * NCLS * OHW;
    if (idx >= total) return;
    int ox = idx & 127;
    int r = idx >> 7;
    int oy = r & 127;
    r >>= 7;  // b*81 + c
    float sy = oy * 0.5f - 0.25f;
    float sx = ox * 0.5f - 0.25f;
    float fy = floorf(sy), fx = floorf(sx);
    float wy = sy - fy, wx = sx - fx;
    int y0 = (int)fy, x0 = (int)fx;
    int y0c = max(y0, 0), y1c = min(y0 + 1, 63);
    int x0c = max(x0, 0), x1c = min(x0 + 1, 63);
    const float* s = src + (size_t)r * HW;
    float v00 = s[y0c * 64 + x0c], v01 = s[y0c * 64 + x1c];
    float v10 = s[y1c * 64 + x0c], v11 = s[y1c * 64 + x1c];
    dst[idx] = (1.f - wy) * ((1.f - wx) * v00 + wx * v01) +
               wy * ((1.f - wx) * v10 + wx * v11);
}

// ---------------- orchestration ----------------
extern "C" void kernel_launch(void* const* d_in, const int* in_sizes, int n_in,
                              void* d_out, int out_size) {
    (void)in_sizes; (void)n_in; (void)out_size;
    const float* x    = (const float*)d_in[0];
    const float* wp1  = (const float*)d_in[1];
    const float* sp1  = (const float*)d_in[2];
    const float* bp1  = (const float*)d_in[3];
    const float* wc1  = (const float*)d_in[4];
    const float* sc1  = (const float*)d_in[5];
    const float* bc1  = (const float*)d_in[6];
    const float* pwb  = (const float*)d_in[7];
    const float* pbb  = (const float*)d_in[8];
    const float* pwc  = (const float*)d_in[9];
    const float* pbc  = (const float*)d_in[10];
    const float* pwd  = (const float*)d_in[11];
    const float* pbd  = (const float*)d_in[12];
    const float* alpha = (const float*)d_in[13];
    const float* beta  = (const float*)d_in[14];
    const float* wp2  = (const float*)d_in[15];
    const float* sp2  = (const float*)d_in[16];
    const float* bp2  = (const float*)d_in[17];
    const float* wc2  = (const float*)d_in[18];
    const float* sc2  = (const float*)d_in[19];
    const float* bc2  = (const float*)d_in[20];
    const float* wlog = (const float*)d_in[21];
    const float* blog = (const float*)d_in[22];
    const float* wp3  = (const float*)d_in[23];
    const float* bp3  = (const float*)d_in[24];
    const float* wc3  = (const float*)d_in[25];
    const float* bc3  = (const float*)d_in[26];
    float* out = (float*)d_out;

    float *wt1p, *wt1cs, *wt2p, *wt2cs, *featp0, *featc0, *fb, *fc, *fd, *attn;
    float *pam, *featp, *camatt, *cam, *featc, *fusion, *pout, *cout_, *fout;
    cudaGetSymbolAddress((void**)&wt1p, g_wt1p);
    cudaGetSymbolAddress((void**)&wt1cs, g_wt1cs);
    cudaGetSymbolAddress((void**)&wt2p, g_wt2p);
    cudaGetSymbolAddress((void**)&wt2cs, g_wt2cs);
    cudaGetSymbolAddress((void**)&featp0, g_featp0);
    cudaGetSymbolAddress((void**)&featc0, g_featc0);
    cudaGetSymbolAddress((void**)&fb, g_fb);
    cudaGetSymbolAddress((void**)&fc, g_fc);
    cudaGetSymbolAddress((void**)&fd, g_fd);
    cudaGetSymbolAddress((void**)&attn, g_attn);
    cudaGetSymbolAddress((void**)&pam, g_pam);
    cudaGetSymbolAddress((void**)&featp, g_featp);
    cudaGetSymbolAddress((void**)&camatt, g_camatt);
    cudaGetSymbolAddress((void**)&cam, g_cam);
    cudaGetSymbolAddress((void**)&featc, g_featc);
    cudaGetSymbolAddress((void**)&fusion, g_fusion);
    cudaGetSymbolAddress((void**)&pout, g_pout);
    cudaGetSymbolAddress((void**)&cout_, g_cout);
    cudaGetSymbolAddress((void**)&fout, g_fout);

    // 1) weight transposes (p1/p2 plain tf32; c1/c2 3x-split for fp32-grade)
    wtrans_kernel<<<4096, 256>>>(wp1, wt1p, CIN, IC);
    wsplit3_kernel<<<8192, 256>>>(wc1, wt1cs, CIN, IC);
    wtrans_kernel<<<2048, 256>>>(wp2, wt2p, IC, IC);
    wsplit3_kernel<<<4096, 256>>>(wc2, wt2cs, IC, IC);

    // 2) first convs: 2048 -> 512, BN fold + relu (tensor core)
    conv3x3_mma_kernel<1><<<dim3(128, 4), 256>>>(x, wt1p, featp0, sp1, bp1, CIN, 1);
    conv3x3_mma_kernel<3><<<dim3(128, 4), 256>>>(x, wt1cs, featc0, sc1, bc1, 3 * CIN, 1);

    // 3) PAM projections (1x1 convs)
    gemm_nn_kernel<<<dim3(32, 1, 4), 256>>>(pwb, 0, featp0, (long)IC * HW,
                                            fb, (long)C8 * HW, pbb, 0, 0, C8, HW, IC);
    gemm_nn_kernel<<<dim3(32, 1, 4), 256>>>(pwc, 0, featp0, (long)IC * HW,
                                            fc, (long)C8 * HW, pbc, 0, 0, C8, HW, IC);
    gemm_nn_kernel<<<dim3(32, 4, 4), 256>>>(pwd, 0, featp0, (long)IC * HW,
                                            fd, (long)IC * HW, pbd, 0, 0, IC, HW, IC);

    // 4) attention logits + softmax
    pam_logits_kernel<<<dim3(64, 64, 4), 256>>>(fb, fc, attn);
    softmax4096_kernel<<<BB * HW, 256>>>(attn);

    // 5) PAM apply: pam = alpha * (fd @ attn^T) + featp0
    gemm_nt_kernel<<<dim3(32, 4, 4), 256>>>(fd, (long)IC * HW, attn, (long)HW * HW,
                                            pam, (long)IC * HW, 0, alpha, featp0,
                                            IC, HW, HW);

    // 6) conv p2 (plain tf32 tensor core)
    conv3x3_mma_kernel<1><<<dim3(128, 4), 256>>>(pam, wt2p, featp, sp2, bp2, IC, 1);

    // 7) CAM: gram (fp32 SIMT), softmax, apply (fp32 SIMT)
    gemm_nt_kernel<<<dim3(4, 4, 4), 256>>>(featc0, (long)IC * HW, featc0, (long)IC * HW,
                                           camatt, (long)IC * IC, 0, 0, 0,
                                           IC, IC, HW);
    cam_softmax_kernel<<<BB * IC, 128>>>(camatt);
    gemm_nn_kernel<<<dim3(32, 4, 4), 256>>>(camatt, (long)IC * IC, featc0, (long)IC * HW,
                                            cam, (long)IC * HW, 0, beta, featc0,
                                            IC, HW, IC);

    // 8) conv c2 (3x-split tf32 tensor core, fp32-grade)
    conv3x3_mma_kernel<3><<<dim3(128, 4), 256>>>(cam, wt2cs, featc, sc2, bc2, 3 * IC, 1);

    // 9) fusion + output heads (1x1 convs)
    add_kernel<<<(BB * IC * HW) / 256, 256>>>(featp, featc, fusion, BB * IC * HW);
    gemm_nn_kernel<<<dim3(32, 1, 4), 256>>>(wp3, 0, featp, (long)IC * HW,
                                            pout, (long)NCLS * HW, bp3, 0, 0, NCLS, HW, IC);
    gemm_nn_kernel<<<dim3(32, 1, 4), 256>>>(wc3, 0, featc, (long)IC * HW,
                                            cout_, (long)NCLS * HW, bc3, 0, 0, NCLS, HW, IC);
    gemm_nn_kernel<<<dim3(32, 1, 4), 256>>>(wlog, 0, fusion, (long)IC * HW,
                                            fout, (long)NCLS * HW, blog, 0, 0, NCLS, HW, IC);

    // 10) upsample 2x into output: (p, c, fusion) order
    const int outElems = BB * NCLS * OHW;
    up2x_kernel<<<(outElems + 255) / 256, 256>>>(pout, out);
    up2x_kernel<<<(outElems + 255) / 256, 256>>>(cout_, out + outElems);
    up2x_kernel<<<(outElems + 255) / 256, 256>>>(fout, out + 2 * (size_t)outElems);
}

// round 5
// speedup vs baseline: 1.4704x; 1.1928x over previous
#include <cuda_runtime.h>
#include <cuda_bf16.h>
#include <math.h>
#include <stdint.h>

// ---------------- problem constants ----------------
#define BB 4
#define CIN 2048
#define IC 512
#define C8 64
#define NCLS 81
#define HH 64
#define WW 64
#define HW 4096
#define OHW (128*128)

// ---------------- scratch (__device__ globals, no runtime alloc) ----------------
__device__ float    g_wt1p[9*CIN*IC];
__device__ uint32_t g_wbc1[9*(3*CIN/2)*IC];   // bf16-pair-packed triple-split weights, c1
__device__ float    g_wt2p[9*IC*IC];
__device__ uint32_t g_wbc2[9*(3*IC/2)*IC];    // bf16-pair-packed triple-split weights, c2
__device__ float g_featp0[BB*IC*HW];
__device__ float g_featc0[BB*IC*HW];
__device__ float g_fb[BB*C8*HW];
__device__ float g_fc[BB*C8*HW];
__device__ float g_fd[BB*IC*HW];
__device__ float g_attn[(size_t)BB*HW*HW];
__device__ float g_pam[BB*IC*HW];
__device__ float g_featp[BB*IC*HW];
__device__ float g_camatt[BB*IC*IC];
__device__ float g_cam[BB*IC*HW];
__device__ float g_featc[BB*IC*HW];
__device__ float g_fusion[BB*IC*HW];
__device__ float g_pout[BB*NCLS*HW];
__device__ float g_cout[BB*NCLS*HW];
__device__ float g_fout[BB*NCLS*HW];

// ---------------- helpers ----------------
__device__ __forceinline__ uint32_t f2tf32(float f) {
    uint32_t r;
    asm("cvt.rna.tf32.f32 %0, %1;" : "=r"(r) : "f"(f));
    return r;
}

__device__ __forceinline__ void mma_tf32(float* c, const uint32_t* a, const uint32_t* b) {
    asm volatile(
        "mma.sync.aligned.m16n8k8.row.col.f32.tf32.tf32.f32 "
        "{%0,%1,%2,%3}, {%4,%5,%6,%7}, {%8,%9}, {%0,%1,%2,%3};"
        : "+f"(c[0]), "+f"(c[1]), "+f"(c[2]), "+f"(c[3])
        : "r"(a[0]), "r"(a[1]), "r"(a[2]), "r"(a[3]), "r"(b[0]), "r"(b[1]));
}

__device__ __forceinline__ void mma_bf16(float* c, const uint32_t* a, const uint32_t* b) {
    asm volatile(
        "mma.sync.aligned.m16n8k16.row.col.f32.bf16.bf16.f32 "
        "{%0,%1,%2,%3}, {%4,%5,%6,%7}, {%8,%9}, {%0,%1,%2,%3};"
        : "+f"(c[0]), "+f"(c[1]), "+f"(c[2]), "+f"(c[3])
        : "r"(a[0]), "r"(a[1]), "r"(a[2]), "r"(a[3]), "r"(b[0]), "r"(b[1]));
}

__device__ __forceinline__ unsigned short bf16bits(float v) {
    __nv_bfloat16 b = __float2bfloat16_rn(v);
    return *reinterpret_cast<unsigned short*>(&b);
}
__device__ __forceinline__ float bf16hi(float v) {
    return __bfloat162float(__float2bfloat16_rn(v));
}

// ---------------- weight transpose (tf32 path): wt[(tap*Cin+ci)*Cout+co] ----------------
__global__ void wtrans_kernel(const float* __restrict__ w, float* __restrict__ wt,
                              int Cin, int Cout) {
    size_t total = (size_t)Cout * Cin * 9;
    for (size_t i = (size_t)blockIdx.x * blockDim.x + threadIdx.x; i < total;
         i += (size_t)gridDim.x * blockDim.x) {
        int co = (int)(i % Cout);
        size_t r = i / Cout;
        int ci = (int)(r % Cin);
        int tap = (int)(r / Cin);
        wt[i] = w[((size_t)co * Cin + ci) * 9 + tap];
    }
}

// ---------------- bf16 triple-split packed weight prep ----------------
// Slot layout per channel: 0 = w_hi, 1 = w_lo, 2 = w_hi (pairs with x: hi, hi, lo).
// Packed as u32 = (bf16 slot 2k2+1)<<16 | bf16 slot 2k2, layout [(tap*K2C + k2)*Cout + co].
__global__ void wsplitbf_kernel(const float* __restrict__ w, uint32_t* __restrict__ wp,
                                int Cin, int Cout) {
    int K2C = 3 * Cin / 2;
    size_t total = (size_t)9 * K2C * Cout;
    for (size_t i = (size_t)blockIdx.x * blockDim.x + threadIdx.x; i < total;
         i += (size_t)gridDim.x * blockDim.x) {
        int co = (int)(i % Cout);
        size_t r = i / Cout;
        int k2 = (int)(r % K2C);
        int tap = (int)(r / K2C);
        unsigned short h[2];
#pragma unroll
        for (int j = 0; j < 2; j++) {
            int s = 2 * k2 + j;
            int ci = s / 3, part = s - 3 * ci;
            float v = w[((size_t)co * Cin + ci) * 9 + tap];
            float vv;
            if (part == 1) vv = v - bf16hi(v);
            else vv = v;
            h[j] = bf16bits(vv);
        }
        wp[i] = (uint32_t)h[0] | ((uint32_t)h[1] << 16);
    }
}

#define CPAD 136

// ---------------- 3x3 conv via tf32 tensor core (p-branch, plain tf32) ----------------
__global__ __launch_bounds__(256, 2)
void conv3x3_tf32_kernel(const float* __restrict__ x, const float* __restrict__ wt,
                         float* __restrict__ out,
                         const float* __restrict__ s, const float* __restrict__ bias,
                         int Cin, int relu) {
    const int Cout = gridDim.y * 128;
    int sb = blockIdx.x;
    int b = sb >> 5;
    int y0 = (sb & 31) * 2;
    int co0 = blockIdx.y * 128;
    int t = threadIdx.x;
    int lane = t & 31, wid = t >> 5;
    int wm = (wid & 3) * 32;
    int wn = (wid >> 2) * 64;
    int lg = lane >> 2, lq = lane & 3;

    __shared__ uint32_t aS[2][16][CPAD];
    __shared__ uint32_t bS[2][16][CPAD];

    float acc[2][8][4];
#pragma unroll
    for (int i = 0; i < 2; i++)
#pragma unroll
        for (int j = 0; j < 8; j++)
#pragma unroll
            for (int q = 0; q < 4; q++) acc[i][j][q] = 0.f;

    const float* xb = x + (size_t)b * Cin * HW;
    const int iters = 9 * Cin / 16;

    float aR[8], bR[8];

    {
#pragma unroll
        for (int i = 0; i < 2; i++) {
            int f = t + i * 256;
            int k = f >> 5, m4 = (f & 31) * 4;
            float4 v = *(const float4*)(wt + (size_t)k * Cout + co0 + m4);
            aR[i*4+0]=v.x; aR[i*4+1]=v.y; aR[i*4+2]=v.z; aR[i*4+3]=v.w;
        }
#pragma unroll
        for (int i = 0; i < 8; i++) {
            int f = t + i * 256;
            int k = f >> 7, n = f & 127;
            int iy = y0 + (n >> 6) - 1, ix = (n & 63) - 1;
            float v = 0.f;
            if ((unsigned)iy < 64u && (unsigned)ix < 64u)
                v = xb[((size_t)k * HH + iy) * WW + ix];
            bR[i] = v;
        }
#pragma unroll
        for (int i = 0; i < 2; i++) {
            int f = t + i * 256;
            int k = f >> 5, m4 = (f & 31) * 4;
#pragma unroll
            for (int j = 0; j < 4; j++) aS[0][k][m4+j] = f2tf32(aR[i*4+j]);
        }
#pragma unroll
        for (int i = 0; i < 8; i++) {
            int f = t + i * 256;
            bS[0][f >> 7][f & 127] = f2tf32(bR[i]);
        }
    }
    __syncthreads();

    for (int kt = 0; kt < iters; kt++) {
        int cur = kt & 1;
        bool more = (kt + 1 < iters);

        if (more) {
            int gk0 = (kt + 1) * 16;
#pragma unroll
            for (int i = 0; i < 2; i++) {
                int f = t + i * 256;
                int k = f >> 5, m4 = (f & 31) * 4;
                float4 v = *(const float4*)(wt + (size_t)(gk0 + k) * Cout + co0 + m4);
                aR[i*4+0]=v.x; aR[i*4+1]=v.y; aR[i*4+2]=v.z; aR[i*4+3]=v.w;
            }
            int tap = gk0 / Cin;
            int ci0 = gk0 - tap * Cin;
            int dy = tap / 3 - 1, dx = tap % 3 - 1;
#pragma unroll
            for (int i = 0; i < 8; i++) {
                int f = t + i * 256;
                int k = f >> 7, n = f & 127;
                int iy = y0 + (n >> 6) + dy, ix = (n & 63) + dx;
                float v = 0.f;
                if ((unsigned)iy < 64u && (unsigned)ix < 64u)
                    v = xb[((size_t)(ci0 + k) * HH + iy) * WW + ix];
                bR[i] = v;
            }
        }

#pragma unroll
        for (int k0 = 0; k0 < 16; k0 += 8) {
            uint32_t af[2][4], bf[8][2];
#pragma unroll
            for (int mt = 0; mt < 2; mt++) {
                int m = wm + mt * 16;
                af[mt][0] = aS[cur][k0+lq][m+lg];
                af[mt][1] = aS[cur][k0+lq][m+8+lg];
                af[mt][2] = aS[cur][k0+4+lq][m+lg];
                af[mt][3] = aS[cur][k0+4+lq][m+8+lg];
            }
#pragma unroll
            for (int nt = 0; nt < 8; nt++) {
                int n = wn + nt * 8;
                bf[nt][0] = bS[cur][k0+lq][n+lg];
                bf[nt][1] = bS[cur][k0+4+lq][n+lg];
            }
#pragma unroll
            for (int mt = 0; mt < 2; mt++)
#pragma unroll
                for (int nt = 0; nt < 8; nt++)
                    mma_tf32(acc[mt][nt], af[mt], bf[nt]);
        }

        if (more) {
            int nb = cur ^ 1;
#pragma unroll
            for (int i = 0; i < 2; i++) {
                int f = t + i * 256;
                int k = f >> 5, m4 = (f & 31) * 4;
#pragma unroll
                for (int j = 0; j < 4; j++) aS[nb][k][m4+j] = f2tf32(aR[i*4+j]);
            }
#pragma unroll
            for (int i = 0; i < 8; i++) {
                int f = t + i * 256;
                bS[nb][f >> 7][f & 127] = f2tf32(bR[i]);
            }
        }
        __syncthreads();
    }

#pragma unroll
    for (int mt = 0; mt < 2; mt++) {
        int r0 = co0 + wm + mt * 16 + lg;
        float s0 = s ? s[r0] : 1.f, s1 = s ? s[r0+8] : 1.f;
        float b0 = bias ? bias[r0] : 0.f, b1 = bias ? bias[r0+8] : 0.f;
#pragma unroll
        for (int nt = 0; nt < 8; nt++) {
            int col = wn + nt * 8 + lq * 2;
            int yy = y0 + (col >> 6), xx = col & 63;
            float v0 = acc[mt][nt][0]*s0+b0, v1 = acc[mt][nt][1]*s0+b0;
            float v2 = acc[mt][nt][2]*s1+b1, v3 = acc[mt][nt][3]*s1+b1;
            if (relu) { v0=fmaxf(v0,0.f); v1=fmaxf(v1,0.f); v2=fmaxf(v2,0.f); v3=fmaxf(v3,0.f); }
            size_t o0 = (((size_t)b * Cout + r0) * HH + yy) * WW + xx;
            size_t o1 = (((size_t)b * Cout + r0+8) * HH + yy) * WW + xx;
            *(float2*)(out + o0) = make_float2(v0, v1);
            *(float2*)(out + o1) = make_float2(v2, v3);
        }
    }
}

// ---------------- 3x3 conv via bf16 triple-split tensor core (c-branch, fp32-grade) ----------------
// K' = 3*Cin slots; per channel: (w_hi,x_hi),(w_lo,x_hi),(w_hi,x_lo). BK = 16 slots = 8 u32 pairs.
// m16n8k16 bf16 MMA; smem holds bf16x2-packed words [k2][col].
__global__ __launch_bounds__(256, 2)
void conv3x3_bf16s_kernel(const float* __restrict__ x, const uint32_t* __restrict__ wp,
                          float* __restrict__ out,
                          const float* __restrict__ s, const float* __restrict__ bias,
                          int Cin, int relu) {
    const int Cout = gridDim.y * 128;
    const int KS = 3 * Cin;              // slots per tap
    int sb = blockIdx.x;
    int b = sb >> 5;
    int y0 = (sb & 31) * 2;
    int co0 = blockIdx.y * 128;
    int t = threadIdx.x;
    int lane = t & 31, wid = t >> 5;
    int wm = (wid & 3) * 32;
    int wn = (wid >> 2) * 64;
    int lg = lane >> 2, lq = lane & 3;

    __shared__ uint32_t aS[2][8][CPAD];   // bf16x2 pairs along k
    __shared__ uint32_t bS[2][8][CPAD];

    float acc[2][8][4];
#pragma unroll
    for (int i = 0; i < 2; i++)
#pragma unroll
        for (int j = 0; j < 8; j++)
#pragma unroll
            for (int q = 0; q < 4; q++) acc[i][j][q] = 0.f;

    const float* xb = x + (size_t)b * Cin * HW;
    const int iters = 9 * KS / 16;       // BK = 16 slots per iter

    uint4 aR;           // 4 packed u32 (one float4-load worth)
    float bR[8];        // 8 slot values (post phase-transform)

    const int ak2 = t >> 5;              // this thread's A k2-row (0..7)
    const int am4 = (t & 31) * 4;        // A col base

    // ---- prologue (iter 0: tap 0, dy=-1, dx=-1) ----
    {
        aR = *(const uint4*)(wp + (size_t)ak2 * Cout + co0 + am4);
#pragma unroll
        for (int i = 0; i < 4; i++) {
            int f = t + i * 256;
            int k2 = f >> 7, n = f & 127;
            int iy = y0 + (n >> 6) - 1, ix = (n & 63) - 1;
            bool inb = ((unsigned)iy < 64u && (unsigned)ix < 64u);
#pragma unroll
            for (int j = 0; j < 2; j++) {
                int ws = 2 * k2 + j;
                int ci = ws / 3, ph = ws - 3 * ci;
                float v = inb ? xb[((size_t)ci * HH + iy) * WW + ix] : 0.f;
                if (ph == 2) v = v - bf16hi(v);
                bR[2*i+j] = v;
            }
        }
        *(uint4*)&aS[0][ak2][am4] = aR;
#pragma unroll
        for (int i = 0; i < 4; i++) {
            int f = t + i * 256;
            uint32_t u = (uint32_t)bf16bits(bR[2*i]) | ((uint32_t)bf16bits(bR[2*i+1]) << 16);
            bS[0][f >> 7][f & 127] = u;
        }
    }
    __syncthreads();

    for (int kt = 0; kt < iters; kt++) {
        int cur = kt & 1;
        bool more = (kt + 1 < iters);

        if (more) {
            int gk2 = (kt + 1) * 8;       // global pair-row base
            aR = *(const uint4*)(wp + (size_t)(gk2 + ak2) * Cout + co0 + am4);
            int gs0 = (kt + 1) * 16;      // global slot base
            int tap = gs0 / KS;
            int rem = gs0 - tap * KS;
            int dy = tap / 3 - 1, dx = tap % 3 - 1;
#pragma unroll
            for (int i = 0; i < 4; i++) {
                int f = t + i * 256;
                int k2 = f >> 7, n = f & 127;
                int iy = y0 + (n >> 6) + dy, ix = (n & 63) + dx;
                bool inb = ((unsigned)iy < 64u && (unsigned)ix < 64u);
#pragma unroll
                for (int j = 0; j < 2; j++) {
                    int ws = rem + 2 * k2 + j;
                    int ci = ws / 3, ph = ws - 3 * ci;
                    float v = inb ? xb[((size_t)ci * HH + iy) * WW + ix] : 0.f;
                    if (ph == 2) v = v - bf16hi(v);
                    bR[2*i+j] = v;
                }
            }
        }

        // ---- compute on cur: one k16 MMA per (mt, nt) ----
        {
            uint32_t af[2][4], bf[8][2];
#pragma unroll
            for (int mt = 0; mt < 2; mt++) {
                int m = wm + mt * 16;
                af[mt][0] = aS[cur][lq][m+lg];
                af[mt][1] = aS[cur][lq][m+8+lg];
                af[mt][2] = aS[cur][lq+4][m+lg];
                af[mt][3] = aS[cur][lq+4][m+8+lg];
            }
#pragma unroll
            for (int nt = 0; nt < 8; nt++) {
                int n = wn + nt * 8;
                bf[nt][0] = bS[cur][lq][n+lg];
                bf[nt][1] = bS[cur][lq+4][n+lg];
            }
#pragma unroll
            for (int mt = 0; mt < 2; mt++)
#pragma unroll
                for (int nt = 0; nt < 8; nt++)
                    mma_bf16(acc[mt][nt], af[mt], bf[nt]);
        }

        if (more) {
            int nb = cur ^ 1;
            *(uint4*)&aS[nb][ak2][am4] = aR;
#pragma unroll
            for (int i = 0; i < 4; i++) {
                int f = t + i * 256;
                uint32_t u = (uint32_t)bf16bits(bR[2*i]) | ((uint32_t)bf16bits(bR[2*i+1]) << 16);
                bS[nb][f >> 7][f & 127] = u;
            }
        }
        __syncthreads();
    }

#pragma unroll
    for (int mt = 0; mt < 2; mt++) {
        int r0 = co0 + wm + mt * 16 + lg;
        float s0 = s ? s[r0] : 1.f, s1 = s ? s[r0+8] : 1.f;
        float b0 = bias ? bias[r0] : 0.f, b1 = bias ? bias[r0+8] : 0.f;
#pragma unroll
        for (int nt = 0; nt < 8; nt++) {
            int col = wn + nt * 8 + lq * 2;
            int yy = y0 + (col >> 6), xx = col & 63;
            float v0 = acc[mt][nt][0]*s0+b0, v1 = acc[mt][nt][1]*s0+b0;
            float v2 = acc[mt][nt][2]*s1+b1, v3 = acc[mt][nt][3]*s1+b1;
            if (relu) { v0=fmaxf(v0,0.f); v1=fmaxf(v1,0.f); v2=fmaxf(v2,0.f); v3=fmaxf(v3,0.f); }
            size_t o0 = (((size_t)b * Cout + r0) * HH + yy) * WW + xx;
            size_t o1 = (((size_t)b * Cout + r0+8) * HH + yy) * WW + xx;
            *(float2*)(out + o0) = make_float2(v0, v1);
            *(float2*)(out + o1) = make_float2(v2, v3);
        }
    }
}

// ---------------- generic 128x128 GEMM NN ----------------
__global__ void gemm_nn_kernel(const float* __restrict__ A, long aBS,
                               const float* __restrict__ Bm, long bBS,
                               float* __restrict__ C, long cBS,
                               const float* __restrict__ bias,
                               const float* __restrict__ scalePtr,
                               const float* __restrict__ Res,
                               int M, int N, int K) {
    int z = blockIdx.z;
    const float* Ab = A + (size_t)z * aBS;
    const float* Bb = Bm + (size_t)z * bBS;
    float* Cb = C + (size_t)z * cBS;
    const float* Rb = Res ? Res + (size_t)z * cBS : (const float*)0;
    int n0 = blockIdx.x * 128, m0 = blockIdx.y * 128;
    int t = threadIdx.x, tx = t & 15, ty = t >> 4;
    __shared__ float aS[8][128];
    __shared__ float bS[8][128];
    float acc[8][8];
#pragma unroll
    for (int i = 0; i < 8; i++)
#pragma unroll
        for (int j = 0; j < 8; j++) acc[i][j] = 0.f;

    int mload = t >> 1;
    int kq = (t & 1) * 4;

    for (int ck = 0; ck < K; ck += 8) {
        float4 av = make_float4(0.f, 0.f, 0.f, 0.f);
        if (m0 + mload < M)
            av = *(const float4*)(Ab + (size_t)(m0 + mload) * K + ck + kq);
        aS[kq+0][mload]=av.x; aS[kq+1][mload]=av.y; aS[kq+2][mload]=av.z; aS[kq+3][mload]=av.w;
#pragma unroll
        for (int i = 0; i < 4; ++i) {
            int idx = t + i * 256;
            int k = idx >> 7, n = idx & 127;
            bS[k][n] = Bb[(size_t)(ck + k) * N + n0 + n];
        }
        __syncthreads();
#pragma unroll
        for (int kk = 0; kk < 8; ++kk) {
            float a[8], bv[8];
#pragma unroll
            for (int i = 0; i < 8; i++) a[i] = aS[kk][ty*8+i];
#pragma unroll
            for (int j = 0; j < 8; j++) bv[j] = bS[kk][tx*8+j];
#pragma unroll
            for (int i = 0; i < 8; i++)
#pragma unroll
                for (int j = 0; j < 8; j++) acc[i][j] = fmaf(a[i], bv[j], acc[i][j]);
        }
        __syncthreads();
    }

    float scale = scalePtr ? scalePtr[0] : 1.f;
#pragma unroll
    for (int i = 0; i < 8; i++) {
        int m = m0 + ty * 8 + i;
        if (m < M) {
            float bi = bias ? bias[m] : 0.f;
#pragma unroll
            for (int j = 0; j < 8; j++) {
                int n = n0 + tx * 8 + j;
                size_t off = (size_t)m * N + n;
                float v = acc[i][j];
                if (Rb) v = scale * v + Rb[off];
                else v += bi;
                Cb[off] = v;
            }
        }
    }
}

// ---------------- generic 128x128 GEMM NT ----------------
__global__ void gemm_nt_kernel(const float* __restrict__ A, long aBS,
                               const float* __restrict__ Bm, long bBS,
                               float* __restrict__ C, long cBS,
                               const float* __restrict__ bias,
                               const float* __restrict__ scalePtr,
                               const float* __restrict__ Res,
                               int M, int N, int K) {
    int z = blockIdx.z;
    const float* Ab = A + (size_t)z * aBS;
    const float* Bb = Bm + (size_t)z * bBS;
    float* Cb = C + (size_t)z * cBS;
    const float* Rb = Res ? Res + (size_t)z * cBS : (const float*)0;
    int n0 = blockIdx.x * 128, m0 = blockIdx.y * 128;
    int t = threadIdx.x, tx = t & 15, ty = t >> 4;
    __shared__ float aS[8][128];
    __shared__ float bS[8][128];
    float acc[8][8];
#pragma unroll
    for (int i = 0; i < 8; i++)
#pragma unroll
        for (int j = 0; j < 8; j++) acc[i][j] = 0.f;

    int rload = t >> 1;
    int kq = (t & 1) * 4;

    for (int ck = 0; ck < K; ck += 8) {
        float4 av = make_float4(0.f, 0.f, 0.f, 0.f);
        if (m0 + rload < M)
            av = *(const float4*)(Ab + (size_t)(m0 + rload) * K + ck + kq);
        aS[kq+0][rload]=av.x; aS[kq+1][rload]=av.y; aS[kq+2][rload]=av.z; aS[kq+3][rload]=av.w;
        float4 bv4 = *(const float4*)(Bb + (size_t)(n0 + rload) * K + ck + kq);
        bS[kq+0][rload]=bv4.x; bS[kq+1][rload]=bv4.y; bS[kq+2][rload]=bv4.z; bS[kq+3][rload]=bv4.w;
        __syncthreads();
#pragma unroll
        for (int kk = 0; kk < 8; ++kk) {
            float a[8], bv[8];
#pragma unroll
            for (int i = 0; i < 8; i++) a[i] = aS[kk][ty*8+i];
#pragma unroll
            for (int j = 0; j < 8; j++) bv[j] = bS[kk][tx*8+j];
#pragma unroll
            for (int i = 0; i < 8; i++)
#pragma unroll
                for (int j = 0; j < 8; j++) acc[i][j] = fmaf(a[i], bv[j], acc[i][j]);
        }
        __syncthreads();
    }

    float scale = scalePtr ? scalePtr[0] : 1.f;
#pragma unroll
    for (int i = 0; i < 8; i++) {
        int m = m0 + ty * 8 + i;
        if (m < M) {
            float bi = bias ? bias[m] : 0.f;
#pragma unroll
            for (int j = 0; j < 8; j++) {
                int n = n0 + tx * 8 + j;
                size_t off = (size_t)m * N + n;
                float v = acc[i][j];
                if (Rb) v = scale * v + Rb[off];
                else v += bi;
                Cb[off] = v;
            }
        }
    }
}

// ---------------- PAM attention logits ----------------
__global__ void pam_logits_kernel(const float* __restrict__ fb, const float* __restrict__ fc,
                                  float* __restrict__ attn) {
    int b = blockIdx.z;
    int n0 = blockIdx.x * 64, m0 = blockIdx.y * 64;
    __shared__ float aS[64][65];
    __shared__ float bS[64][65];
    int t = threadIdx.x;
#pragma unroll
    for (int i = 0; i < 16; i++) {
        int idx = t + i * 256;
        int c = idx >> 6, n = idx & 63;
        aS[c][n] = fb[((size_t)b * 64 + c) * HW + n0 + n];
        bS[c][n] = fc[((size_t)b * 64 + c) * HW + m0 + n];
    }
    __syncthreads();
    int tx = t & 15, ty = t >> 4;
    float acc[4][4];
#pragma unroll
    for (int i = 0; i < 4; i++)
#pragma unroll
        for (int j = 0; j < 4; j++) acc[i][j] = 0.f;
#pragma unroll 8
    for (int c = 0; c < 64; c++) {
        float a[4], bv[4];
#pragma unroll
        for (int i = 0; i < 4; i++) a[i] = aS[c][ty*4+i];
#pragma unroll
        for (int j = 0; j < 4; j++) bv[j] = bS[c][tx*4+j];
#pragma unroll
        for (int i = 0; i < 4; i++)
#pragma unroll
            for (int j = 0; j < 4; j++) acc[i][j] = fmaf(a[i], bv[j], acc[i][j]);
    }
    float* dst = attn + (size_t)b * HW * HW;
#pragma unroll
    for (int i = 0; i < 4; i++)
#pragma unroll
        for (int j = 0; j < 4; j++)
            dst[(size_t)(n0 + ty*4+i) * HW + m0 + tx*4+j] = acc[i][j];
}

// ---------------- row softmax, cols = 4096 ----------------
__global__ void softmax4096_kernel(float* __restrict__ data) {
    size_t row = blockIdx.x;
    float4* p4 = (float4*)(data + row * (size_t)HW);
    int t = threadIdx.x;
    float4 v[4];
    float m = -1e30f;
#pragma unroll
    for (int i = 0; i < 4; i++) {
        v[i] = p4[t + i * 256];
        m = fmaxf(m, fmaxf(fmaxf(v[i].x, v[i].y), fmaxf(v[i].z, v[i].w)));
    }
    __shared__ float red[256];
    red[t] = m;
    __syncthreads();
    for (int s = 128; s > 0; s >>= 1) {
        if (t < s) red[t] = fmaxf(red[t], red[t + s]);
        __syncthreads();
    }
    m = red[0];
    __syncthreads();
    float sum = 0.f;
#pragma unroll
    for (int i = 0; i < 4; i++) {
        v[i].x = __expf(v[i].x - m);
        v[i].y = __expf(v[i].y - m);
        v[i].z = __expf(v[i].z - m);
        v[i].w = __expf(v[i].w - m);
        sum += v[i].x + v[i].y + v[i].z + v[i].w;
    }
    red[t] = sum;
    __syncthreads();
    for (int s = 128; s > 0; s >>= 1) {
        if (t < s) red[t] += red[t + s];
        __syncthreads();
    }
    float inv = 1.f / red[0];
#pragma unroll
    for (int i = 0; i < 4; i++) {
        v[i].x *= inv; v[i].y *= inv; v[i].z *= inv; v[i].w *= inv;
        p4[t + i * 256] = v[i];
    }
}

// ---------------- CAM softmax ----------------
__global__ void cam_softmax_kernel(float* __restrict__ data) {
    float4* p4 = (float4*)(data + (size_t)blockIdx.x * IC);
    int t = threadIdx.x;
    float4 v = p4[t];
    __shared__ float red[128];
    float m = fmaxf(fmaxf(v.x, v.y), fmaxf(v.z, v.w));
    red[t] = m;
    __syncthreads();
    for (int s = 64; s > 0; s >>= 1) {
        if (t < s) red[t] = fmaxf(red[t], red[t + s]);
        __syncthreads();
    }
    float m1 = red[0];
    __syncthreads();
    float mn = fminf(fminf(v.x, v.y), fminf(v.z, v.w));
    red[t] = mn;
    __syncthreads();
    for (int s = 64; s > 0; s >>= 1) {
        if (t < s) red[t] = fminf(red[t], red[t + s]);
        __syncthreads();
    }
    float m2 = m1 - red[0];
    __syncthreads();
    float4 e;
    e.x = __expf(m1 - v.x - m2);
    e.y = __expf(m1 - v.y - m2);
    e.z = __expf(m1 - v.z - m2);
    e.w = __expf(m1 - v.w - m2);
    red[t] = e.x + e.y + e.z + e.w;
    __syncthreads();
    for (int s = 64; s > 0; s >>= 1) {
        if (t < s) red[t] += red[t + s];
        __syncthreads();
    }
    float inv = 1.f / red[0];
    e.x *= inv; e.y *= inv; e.z *= inv; e.w *= inv;
    p4[t] = e;
}

// ---------------- elementwise add ----------------
__global__ void add_kernel(const float* __restrict__ a, const float* __restrict__ b,
                           float* __restrict__ c, int n) {
    int i = blockIdx.x * 256 + threadIdx.x;
    if (i < n) c[i] = a[i] + b[i];
}

// ---------------- bilinear 2x upsample ----------------
__global__ void up2x_kernel(const float* __restrict__ src, float* __restrict__ dst) {
    int idx = blockIdx.x * 256 + threadIdx.x;
    const int total = BB * NCLS * OHW;
    if (idx >= total) return;
    int ox = idx & 127;
    int r = idx >> 7;
    int oy = r & 127;
    r >>= 7;
    float sy = oy * 0.5f - 0.25f;
    float sx = ox * 0.5f - 0.25f;
    float fy = floorf(sy), fx = floorf(sx);
    float wy = sy - fy, wx = sx - fx;
    int y0 = (int)fy, x0 = (int)fx;
    int y0c = max(y0, 0), y1c = min(y0 + 1, 63);
    int x0c = max(x0, 0), x1c = min(x0 + 1, 63);
    const float* s = src + (size_t)r * HW;
    float v00 = s[y0c*64+x0c], v01 = s[y0c*64+x1c];
    float v10 = s[y1c*64+x0c], v11 = s[y1c*64+x1c];
    dst[idx] = (1.f-wy)*((1.f-wx)*v00 + wx*v01) + wy*((1.f-wx)*v10 + wx*v11);
}

// ---------------- orchestration ----------------
extern "C" void kernel_launch(void* const* d_in, const int* in_sizes, int n_in,
                              void* d_out, int out_size) {
    (void)in_sizes; (void)n_in; (void)out_size;
    const float* x    = (const float*)d_in[0];
    const float* wp1  = (const float*)d_in[1];
    const float* sp1  = (const float*)d_in[2];
    const float* bp1  = (const float*)d_in[3];
    const float* wc1  = (const float*)d_in[4];
    const float* sc1  = (const float*)d_in[5];
    const float* bc1  = (const float*)d_in[6];
    const float* pwb  = (const float*)d_in[7];
    const float* pbb  = (const float*)d_in[8];
    const float* pwc  = (const float*)d_in[9];
    const float* pbc  = (const float*)d_in[10];
    const float* pwd  = (const float*)d_in[11];
    const float* pbd  = (const float*)d_in[12];
    const float* alpha = (const float*)d_in[13];
    const float* beta  = (const float*)d_in[14];
    const float* wp2  = (const float*)d_in[15];
    const float* sp2  = (const float*)d_in[16];
    const float* bp2  = (const float*)d_in[17];
    const float* wc2  = (const float*)d_in[18];
    const float* sc2  = (const float*)d_in[19];
    const float* bc2  = (const float*)d_in[20];
    const float* wlog = (const float*)d_in[21];
    const float* blog = (const float*)d_in[22];
    const float* wp3  = (const float*)d_in[23];
    const float* bp3  = (const float*)d_in[24];
    const float* wc3  = (const float*)d_in[25];
    const float* bc3  = (const float*)d_in[26];
    float* out = (float*)d_out;

    float *wt1p, *wt2p, *featp0, *featc0, *fb, *fc, *fd, *attn;
    float *pam, *featp, *camatt, *cam, *featc, *fusion, *pout, *cout_, *fout;
    uint32_t *wbc1, *wbc2;
    cudaGetSymbolAddress((void**)&wt1p, g_wt1p);
    cudaGetSymbolAddress((void**)&wbc1, g_wbc1);
    cudaGetSymbolAddress((void**)&wt2p, g_wt2p);
    cudaGetSymbolAddress((void**)&wbc2, g_wbc2);
    cudaGetSymbolAddress((void**)&featp0, g_featp0);
    cudaGetSymbolAddress((void**)&featc0, g_featc0);
    cudaGetSymbolAddress((void**)&fb, g_fb);
    cudaGetSymbolAddress((void**)&fc, g_fc);
    cudaGetSymbolAddress((void**)&fd, g_fd);
    cudaGetSymbolAddress((void**)&attn, g_attn);
    cudaGetSymbolAddress((void**)&pam, g_pam);
    cudaGetSymbolAddress((void**)&featp, g_featp);
    cudaGetSymbolAddress((void**)&camatt, g_camatt);
    cudaGetSymbolAddress((void**)&cam, g_cam);
    cudaGetSymbolAddress((void**)&featc, g_featc);
    cudaGetSymbolAddress((void**)&fusion, g_fusion);
    cudaGetSymbolAddress((void**)&pout, g_pout);
    cudaGetSymbolAddress((void**)&cout_, g_cout);
    cudaGetSymbolAddress((void**)&fout, g_fout);

    // launches ordered so that the dominant kernel (bf16 split conv c1) is launch #4 (ncu capture slot)
    wtrans_kernel<<<4096, 256>>>(wp1, wt1p, CIN, IC);                       // #1
    wsplitbf_kernel<<<8192, 256>>>(wc1, wbc1, CIN, IC);                     // #2
    conv3x3_tf32_kernel<<<dim3(128, 4), 256>>>(x, wt1p, featp0, sp1, bp1, CIN, 1);   // #3
    conv3x3_bf16s_kernel<<<dim3(128, 4), 256>>>(x, wbc1, featc0, sc1, bc1, CIN, 1);  // #4 <- ncu
    wtrans_kernel<<<2048, 256>>>(wp2, wt2p, IC, IC);                        // #5
    wsplitbf_kernel<<<2048, 256>>>(wc2, wbc2, IC, IC);                      // #6

    // PAM projections (1x1 convs)
    gemm_nn_kernel<<<dim3(32, 1, 4), 256>>>(pwb, 0, featp0, (long)IC * HW,
                                            fb, (long)C8 * HW, pbb, 0, 0, C8, HW, IC);
    gemm_nn_kernel<<<dim3(32, 1, 4), 256>>>(pwc, 0, featp0, (long)IC * HW,
                                            fc, (long)C8 * HW, pbc, 0, 0, C8, HW, IC);
    gemm_nn_kernel<<<dim3(32, 4, 4), 256>>>(pwd, 0, featp0, (long)IC * HW,
                                            fd, (long)IC * HW, pbd, 0, 0, IC, HW, IC);

    // attention logits + softmax
    pam_logits_kernel<<<dim3(64, 64, 4), 256>>>(fb, fc, attn);
    softmax4096_kernel<<<BB * HW, 256>>>(attn);

    // PAM apply: pam = alpha * (fd @ attn^T) + featp0
    gemm_nt_kernel<<<dim3(32, 4, 4), 256>>>(fd, (long)IC * HW, attn, (long)HW * HW,
                                            pam, (long)IC * HW, 0, alpha, featp0,
                                            IC, HW, HW);

    // conv p2 (plain tf32)
    conv3x3_tf32_kernel<<<dim3(128, 4), 256>>>(pam, wt2p, featp, sp2, bp2, IC, 1);

    // CAM: gram (fp32 SIMT), softmax, apply (fp32 SIMT)
    gemm_nt_kernel<<<dim3(4, 4, 4), 256>>>(featc0, (long)IC * HW, featc0, (long)IC * HW,
                                           camatt, (long)IC * IC, 0, 0, 0,
                                           IC, IC, HW);
    cam_softmax_kernel<<<BB * IC, 128>>>(camatt);
    gemm_nn_kernel<<<dim3(32, 4, 4), 256>>>(camatt, (long)IC * IC, featc0, (long)IC * HW,
                                            cam, (long)IC * HW, 0, beta, featc0,
                                            IC, HW, IC);

    // conv c2 (bf16 triple-split, fp32-grade)
    conv3x3_bf16s_kernel<<<dim3(128, 4), 256>>>(cam, wbc2, featc, sc2, bc2, IC, 1);

    // fusion + output heads
    add_kernel<<<(BB * IC * HW) / 256, 256>>>(featp, featc, fusion, BB * IC * HW);
    gemm_nn_kernel<<<dim3(32, 1, 4), 256>>>(wp3, 0, featp, (long)IC * HW,
                                            pout, (long)NCLS * HW, bp3, 0, 0, NCLS, HW, IC);
    gemm_nn_kernel<<<dim3(32, 1, 4), 256>>>(wc3, 0, featc, (long)IC * HW,
                                            cout_, (long)NCLS * HW, bc3, 0, 0, NCLS, HW, IC);
    gemm_nn_kernel<<<dim3(32, 1, 4), 256>>>(wlog, 0, fusion, (long)IC * HW,
                                            fout, (long)NCLS * HW, blog, 0, 0, NCLS, HW, IC);

    // upsample 2x into output
    const int outElems = BB * NCLS * OHW;
    up2x_kernel<<<(outElems + 255) / 256, 256>>>(pout, out);
    up2x_kernel<<<(outElems + 255) / 256, 256>>>(cout_, out + outElems);
    up2x_kernel<<<(outElems + 255) / 256, 256>>>(fout, out + 2 * (size_t)outElems);
}

// round 6
// speedup vs baseline: 2.2587x; 1.5361x over previous
#include <cuda_runtime.h>
#include <cuda_bf16.h>
#include <math.h>
#include <stdint.h>

// ---------------- problem constants ----------------
#define BB 4
#define CIN 2048
#define IC 512
#define C8 64
#define NCLS 81
#define HH 64
#define WW 64
#define HW 4096
#define OHW (128*128)
#define K2C1 (3*CIN/2)   // 3072 pair-rows per tap (c1)
#define K2C2 (3*IC/2)    // 768  pair-rows per tap (c2)

// ---------------- scratch (__device__ globals, no runtime alloc) ----------------
__device__ __align__(16) uint32_t g_wt1p[9*CIN*IC];      // tf32 bits, [k][Cout]
__device__ __align__(16) uint32_t g_wbc1[9*K2C1*IC];     // bf16-pair split weights c1
__device__ __align__(16) uint32_t g_wt2p[9*IC*IC];
__device__ __align__(16) uint32_t g_wbc2[9*K2C2*IC];
__device__ __align__(16) uint32_t g_xtf[BB*CIN*HW];      // tf32-packed x (p-branch)
__device__ __align__(16) uint32_t g_xsp[(size_t)BB*K2C1*HW]; // bf16-split-packed x (c-branch)
__device__ __align__(16) uint32_t g_pamtf[BB*IC*HW];     // tf32-packed pam
__device__ __align__(16) uint32_t g_camsp[(size_t)BB*K2C2*HW]; // bf16-split-packed cam
__device__ float g_featp0[BB*IC*HW];
__device__ float g_featc0[BB*IC*HW];
__device__ float g_fb[BB*C8*HW];
__device__ float g_fc[BB*C8*HW];
__device__ float g_fd[BB*IC*HW];
__device__ float g_attn[(size_t)BB*HW*HW];
__device__ float g_pam[BB*IC*HW];
__device__ float g_featp[BB*IC*HW];
__device__ float g_camatt[BB*IC*IC];
__device__ float g_cam[BB*IC*HW];
__device__ float g_featc[BB*IC*HW];
__device__ float g_fusion[BB*IC*HW];
__device__ float g_pout[BB*NCLS*HW];
__device__ float g_cout[BB*NCLS*HW];
__device__ float g_fout[BB*NCLS*HW];

// ---------------- helpers ----------------
__device__ __forceinline__ uint32_t f2tf32(float f) {
    uint32_t r;
    asm("cvt.rna.tf32.f32 %0, %1;" : "=r"(r) : "f"(f));
    return r;
}
__device__ __forceinline__ void mma_tf32(float* c, const uint32_t* a, const uint32_t* b) {
    asm volatile(
        "mma.sync.aligned.m16n8k8.row.col.f32.tf32.tf32.f32 "
        "{%0,%1,%2,%3}, {%4,%5,%6,%7}, {%8,%9}, {%0,%1,%2,%3};"
        : "+f"(c[0]), "+f"(c[1]), "+f"(c[2]), "+f"(c[3])
        : "r"(a[0]), "r"(a[1]), "r"(a[2]), "r"(a[3]), "r"(b[0]), "r"(b[1]));
}
__device__ __forceinline__ void mma_bf16(float* c, const uint32_t* a, const uint32_t* b) {
    asm volatile(
        "mma.sync.aligned.m16n8k16.row.col.f32.bf16.bf16.f32 "
        "{%0,%1,%2,%3}, {%4,%5,%6,%7}, {%8,%9}, {%0,%1,%2,%3};"
        : "+f"(c[0]), "+f"(c[1]), "+f"(c[2]), "+f"(c[3])
        : "r"(a[0]), "r"(a[1]), "r"(a[2]), "r"(a[3]), "r"(b[0]), "r"(b[1]));
}
__device__ __forceinline__ unsigned short bf16bits(float v) {
    __nv_bfloat16 b = __float2bfloat16_rn(v);
    return *reinterpret_cast<unsigned short*>(&b);
}
__device__ __forceinline__ float bf16hi(float v) {
    return __bfloat162float(__float2bfloat16_rn(v));
}
__device__ __forceinline__ void cp4(uint32_t dst, const void* src, uint32_t sz) {
    asm volatile("cp.async.ca.shared.global [%0], [%1], 4, %2;" :: "r"(dst), "l"(src), "r"(sz));
}
__device__ __forceinline__ void cp16(uint32_t dst, const void* src) {
    asm volatile("cp.async.cg.shared.global [%0], [%1], 16;" :: "r"(dst), "l"(src));
}
#define CP_COMMIT() asm volatile("cp.async.commit_group;")
#define CP_WAIT2()  asm volatile("cp.async.wait_group 2;")

// ---------------- weight transpose to tf32 bits: wt[(tap*Cin+ci)*Cout+co] ----------------
__global__ void wtrans_kernel(const float* __restrict__ w, uint32_t* __restrict__ wt,
                              int Cin, int Cout) {
    size_t total = (size_t)Cout * Cin * 9;
    for (size_t i = (size_t)blockIdx.x * blockDim.x + threadIdx.x; i < total;
         i += (size_t)gridDim.x * blockDim.x) {
        int co = (int)(i % Cout);
        size_t r = i / Cout;
        int ci = (int)(r % Cin);
        int tap = (int)(r / Cin);
        wt[i] = f2tf32(w[((size_t)co * Cin + ci) * 9 + tap]);
    }
}

// ---------------- bf16 triple-split packed weight prep (slots: hi, lo, hi) ----------------
__global__ void wsplitbf_kernel(const float* __restrict__ w, uint32_t* __restrict__ wp,
                                int Cin, int Cout) {
    int K2Ct = 3 * Cin / 2;
    size_t total = (size_t)9 * K2Ct * Cout;
    for (size_t i = (size_t)blockIdx.x * blockDim.x + threadIdx.x; i < total;
         i += (size_t)gridDim.x * blockDim.x) {
        int co = (int)(i % Cout);
        size_t r = i / Cout;
        int k2 = (int)(r % K2Ct);
        int tap = (int)(r / K2Ct);
        unsigned short h[2];
#pragma unroll
        for (int j = 0; j < 2; j++) {
            int s = 2 * k2 + j;
            int ci = s / 3, part = s - 3 * ci;
            float v = w[((size_t)co * Cin + ci) * 9 + tap];
            if (part == 1) v = v - bf16hi(v);
            h[j] = bf16bits(v);
        }
        wp[i] = (uint32_t)h[0] | ((uint32_t)h[1] << 16);
    }
}

// ---------------- activation prepack: f32 -> tf32 bits (1:1 layout) ----------------
__global__ void packtf_kernel(const float* __restrict__ in, uint32_t* __restrict__ out,
                              size_t n) {
    for (size_t i = (size_t)blockIdx.x * blockDim.x + threadIdx.x; i < n;
         i += (size_t)gridDim.x * blockDim.x)
        out[i] = f2tf32(in[i]);
}

// ---------------- activation prepack: f32 [B][C][HW] -> split pairs [B][3C/2][HW] ----------------
// activation slot phases per channel: 0=hi, 1=hi, 2=lo
__global__ void packsp_kernel(const float* __restrict__ in, uint32_t* __restrict__ out,
                              int Cin) {
    int K2Ct = 3 * Cin / 2;
    size_t per_b = (size_t)K2Ct * HW;
    size_t total = (size_t)BB * per_b;
    for (size_t i = (size_t)blockIdx.x * blockDim.x + threadIdx.x; i < total;
         i += (size_t)gridDim.x * blockDim.x) {
        int b = (int)(i / per_b);
        size_t r = i - (size_t)b * per_b;
        int k2 = (int)(r / HW);
        int pos = (int)(r - (size_t)k2 * HW);
        const float* xb = in + (size_t)b * Cin * HW;
        unsigned short h[2];
#pragma unroll
        for (int j = 0; j < 2; j++) {
            int s = 2 * k2 + j;
            int ci = s / 3, ph = s - 3 * ci;
            float v = xb[(size_t)ci * HW + pos];
            if (ph == 2) v = v - bf16hi(v);
            h[j] = bf16bits(v);
        }
        out[i] = (uint32_t)h[0] | ((uint32_t)h[1] << 16);
    }
}

// ---------------- conv3x3 tf32, cp.async 4-stage pipeline (p-branch) ----------------
// dynamic smem: 4 stages x (A 16x136 + B 16x136) u32 = 69632 B
#define TF_STG (2*16*136)
__global__ __launch_bounds__(256, 2)
void conv_tf32ca_kernel(const uint32_t* __restrict__ xtf, const uint32_t* __restrict__ wt,
                        float* __restrict__ out,
                        const float* __restrict__ s, const float* __restrict__ bias,
                        int Cin, int relu) {
    const int Cout = gridDim.y * 128;
    extern __shared__ uint32_t dyn[];
    int sb = blockIdx.x;
    int b = sb >> 5;
    int y0 = (sb & 31) * 2;
    int co0 = blockIdx.y * 128;
    int t = threadIdx.x;
    int lane = t & 31, wid = t >> 5;
    int wm = (wid & 3) * 32, wn = (wid >> 2) * 64;
    int lg = lane >> 2, lq = lane & 3;
    const uint32_t* xb = xtf + (size_t)b * Cin * HW;
    const int iters = 9 * Cin / 16;
    uint32_t smb = (uint32_t)__cvta_generic_to_shared(dyn);

    auto issue = [&](int kt) {
        if (kt < iters) {
            int st = kt & 3;
            uint32_t sA = smb + st * TF_STG * 4;
            uint32_t sB = sA + 16 * 136 * 4;
            int gk = kt * 16;
            int tap = gk / Cin;
            int ci0 = gk - tap * Cin;
            int dy = tap / 3 - 1, dx = tap % 3 - 1;
#pragma unroll
            for (int i = 0; i < 2; i++) {
                int f = t + i * 256;
                int row = f >> 5, c4 = (f & 31) * 4;
                cp16(sA + (uint32_t)(row * 136 + c4) * 4,
                     wt + (size_t)(gk + row) * Cout + co0 + c4);
            }
#pragma unroll
            for (int i = 0; i < 8; i++) {
                int f = t + i * 256;
                int row = f >> 7, n = f & 127;
                int iy = y0 + (n >> 6) + dy, ix = (n & 63) + dx;
                bool inb = ((unsigned)iy < 64u) && ((unsigned)ix < 64u);
                const uint32_t* src = inb ? (xb + (size_t)(ci0 + row) * HW + iy * WW + ix) : xb;
                cp4(sB + (uint32_t)(row * 136 + n) * 4, src, inb ? 4u : 0u);
            }
        }
        CP_COMMIT();
    };

    issue(0); issue(1); issue(2);

    float acc[2][8][4];
#pragma unroll
    for (int i = 0; i < 2; i++)
#pragma unroll
        for (int j = 0; j < 8; j++)
#pragma unroll
            for (int q = 0; q < 4; q++) acc[i][j][q] = 0.f;

    for (int kt = 0; kt < iters; kt++) {
        CP_WAIT2();
        __syncthreads();
        int st = kt & 3;
        const uint32_t* sA = dyn + st * TF_STG;
        const uint32_t* sB = sA + 16 * 136;
#pragma unroll
        for (int k0 = 0; k0 < 16; k0 += 8) {
            uint32_t af[2][4], bf[8][2];
#pragma unroll
            for (int mt = 0; mt < 2; mt++) {
                int m = wm + mt * 16;
                af[mt][0] = sA[(k0 + lq) * 136 + m + lg];
                af[mt][1] = sA[(k0 + lq) * 136 + m + 8 + lg];
                af[mt][2] = sA[(k0 + 4 + lq) * 136 + m + lg];
                af[mt][3] = sA[(k0 + 4 + lq) * 136 + m + 8 + lg];
            }
#pragma unroll
            for (int nt = 0; nt < 8; nt++) {
                int n = wn + nt * 8;
                bf[nt][0] = sB[(k0 + lq) * 136 + n + lg];
                bf[nt][1] = sB[(k0 + 4 + lq) * 136 + n + lg];
            }
#pragma unroll
            for (int mt = 0; mt < 2; mt++)
#pragma unroll
                for (int nt = 0; nt < 8; nt++)
                    mma_tf32(acc[mt][nt], af[mt], bf[nt]);
        }
        issue(kt + 3);
    }

#pragma unroll
    for (int mt = 0; mt < 2; mt++) {
        int r0 = co0 + wm + mt * 16 + lg;
        float s0 = s ? s[r0] : 1.f, s1 = s ? s[r0 + 8] : 1.f;
        float b0 = bias ? bias[r0] : 0.f, b1 = bias ? bias[r0 + 8] : 0.f;
#pragma unroll
        for (int nt = 0; nt < 8; nt++) {
            int col = wn + nt * 8 + lq * 2;
            int yy = y0 + (col >> 6), xx = col & 63;
            float v0 = acc[mt][nt][0] * s0 + b0, v1 = acc[mt][nt][1] * s0 + b0;
            float v2 = acc[mt][nt][2] * s1 + b1, v3 = acc[mt][nt][3] * s1 + b1;
            if (relu) { v0 = fmaxf(v0, 0.f); v1 = fmaxf(v1, 0.f);
                        v2 = fmaxf(v2, 0.f); v3 = fmaxf(v3, 0.f); }
            size_t o0 = (((size_t)b * Cout + r0) * HH + yy) * WW + xx;
            size_t o1 = (((size_t)b * Cout + r0 + 8) * HH + yy) * WW + xx;
            *(float2*)(out + o0) = make_float2(v0, v1);
            *(float2*)(out + o1) = make_float2(v2, v3);
        }
    }
}

// ---------------- conv3x3 bf16 triple-split, cp.async 4-stage (c-branch, fp32-grade) ----------------
// static smem: 4 stages x (A 8x136 + B 8x136) u32 = 34816 B
#define BF_STG (2*8*136)
__global__ __launch_bounds__(256, 2)
void conv_bf16ca_kernel(const uint32_t* __restrict__ xsp, const uint32_t* __restrict__ wp,
                        float* __restrict__ out,
                        const float* __restrict__ s, const float* __restrict__ bias,
                        int Cin, int relu) {
    const int Cout = gridDim.y * 128;
    const int K2Ct = 3 * Cin / 2;          // pair rows per tap
    __shared__ uint32_t smem[4 * BF_STG];
    int sb = blockIdx.x;
    int b = sb >> 5;
    int y0 = (sb & 31) * 2;
    int co0 = blockIdx.y * 128;
    int t = threadIdx.x;
    int lane = t & 31, wid = t >> 5;
    int wm = (wid & 3) * 32, wn = (wid >> 2) * 64;
    int lg = lane >> 2, lq = lane & 3;
    const uint32_t* xb = xsp + (size_t)b * K2Ct * HW;
    const int iters = 9 * K2Ct / 8;
    uint32_t smb = (uint32_t)__cvta_generic_to_shared(smem);

    auto issue = [&](int kt) {
        if (kt < iters) {
            int st = kt & 3;
            uint32_t sA = smb + st * BF_STG * 4;
            uint32_t sB = sA + 8 * 136 * 4;
            int g0 = kt * 8;                 // global pair row base
            int tap = g0 / K2Ct;
            int k20 = g0 - tap * K2Ct;
            int dy = tap / 3 - 1, dx = tap % 3 - 1;
            {
                int row = t >> 5, c4 = (t & 31) * 4;
                cp16(sA + (uint32_t)(row * 136 + c4) * 4,
                     wp + (size_t)(g0 + row) * Cout + co0 + c4);
            }
#pragma unroll
            for (int i = 0; i < 4; i++) {
                int f = t + i * 256;
                int row = f >> 7, n = f & 127;
                int iy = y0 + (n >> 6) + dy, ix = (n & 63) + dx;
                bool inb = ((unsigned)iy < 64u) && ((unsigned)ix < 64u);
                const uint32_t* src = inb ? (xb + (size_t)(k20 + row) * HW + iy * WW + ix) : xb;
                cp4(sB + (uint32_t)(row * 136 + n) * 4, src, inb ? 4u : 0u);
            }
        }
        CP_COMMIT();
    };

    issue(0); issue(1); issue(2);

    float acc[2][8][4];
#pragma unroll
    for (int i = 0; i < 2; i++)
#pragma unroll
        for (int j = 0; j < 8; j++)
#pragma unroll
            for (int q = 0; q < 4; q++) acc[i][j][q] = 0.f;

    for (int kt = 0; kt < iters; kt++) {
        CP_WAIT2();
        __syncthreads();
        int st = kt & 3;
        const uint32_t* sA = smem + st * BF_STG;
        const uint32_t* sB = sA + 8 * 136;
        {
            uint32_t af[2][4], bf[8][2];
#pragma unroll
            for (int mt = 0; mt < 2; mt++) {
                int m = wm + mt * 16;
                af[mt][0] = sA[lq * 136 + m + lg];
                af[mt][1] = sA[lq * 136 + m + 8 + lg];
                af[mt][2] = sA[(lq + 4) * 136 + m + lg];
                af[mt][3] = sA[(lq + 4) * 136 + m + 8 + lg];
            }
#pragma unroll
            for (int nt = 0; nt < 8; nt++) {
                int n = wn + nt * 8;
                bf[nt][0] = sB[lq * 136 + n + lg];
                bf[nt][1] = sB[(lq + 4) * 136 + n + lg];
            }
#pragma unroll
            for (int mt = 0; mt < 2; mt++)
#pragma unroll
                for (int nt = 0; nt < 8; nt++)
                    mma_bf16(acc[mt][nt], af[mt], bf[nt]);
        }
        issue(kt + 3);
    }

#pragma unroll
    for (int mt = 0; mt < 2; mt++) {
        int r0 = co0 + wm + mt * 16 + lg;
        float s0 = s ? s[r0] : 1.f, s1 = s ? s[r0 + 8] : 1.f;
        float b0 = bias ? bias[r0] : 0.f, b1 = bias ? bias[r0 + 8] : 0.f;
#pragma unroll
        for (int nt = 0; nt < 8; nt++) {
            int col = wn + nt * 8 + lq * 2;
            int yy = y0 + (col >> 6), xx = col & 63;
            float v0 = acc[mt][nt][0] * s0 + b0, v1 = acc[mt][nt][1] * s0 + b0;
            float v2 = acc[mt][nt][2] * s1 + b1, v3 = acc[mt][nt][3] * s1 + b1;
            if (relu) { v0 = fmaxf(v0, 0.f); v1 = fmaxf(v1, 0.f);
                        v2 = fmaxf(v2, 0.f); v3 = fmaxf(v3, 0.f); }
            size_t o0 = (((size_t)b * Cout + r0) * HH + yy) * WW + xx;
            size_t o1 = (((size_t)b * Cout + r0 + 8) * HH + yy) * WW + xx;
            *(float2*)(out + o0) = make_float2(v0, v1);
            *(float2*)(out + o1) = make_float2(v2, v3);
        }
    }
}

// ---------------- generic 128x128 GEMM NN (fp32 SIMT) ----------------
__global__ void gemm_nn_kernel(const float* __restrict__ A, long aBS,
                               const float* __restrict__ Bm, long bBS,
                               float* __restrict__ C, long cBS,
                               const float* __restrict__ bias,
                               const float* __restrict__ scalePtr,
                               const float* __restrict__ Res,
                               int M, int N, int K) {
    int z = blockIdx.z;
    const float* Ab = A + (size_t)z * aBS;
    const float* Bb = Bm + (size_t)z * bBS;
    float* Cb = C + (size_t)z * cBS;
    const float* Rb = Res ? Res + (size_t)z * cBS : (const float*)0;
    int n0 = blockIdx.x * 128, m0 = blockIdx.y * 128;
    int t = threadIdx.x, tx = t & 15, ty = t >> 4;
    __shared__ float aS[8][128];
    __shared__ float bS[8][128];
    float acc[8][8];
#pragma unroll
    for (int i = 0; i < 8; i++)
#pragma unroll
        for (int j = 0; j < 8; j++) acc[i][j] = 0.f;

    int mload = t >> 1;
    int kq = (t & 1) * 4;

    for (int ck = 0; ck < K; ck += 8) {
        float4 av = make_float4(0.f, 0.f, 0.f, 0.f);
        if (m0 + mload < M)
            av = *(const float4*)(Ab + (size_t)(m0 + mload) * K + ck + kq);
        aS[kq+0][mload]=av.x; aS[kq+1][mload]=av.y; aS[kq+2][mload]=av.z; aS[kq+3][mload]=av.w;
#pragma unroll
        for (int i = 0; i < 4; ++i) {
            int idx = t + i * 256;
            int k = idx >> 7, n = idx & 127;
            bS[k][n] = Bb[(size_t)(ck + k) * N + n0 + n];
        }
        __syncthreads();
#pragma unroll
        for (int kk = 0; kk < 8; ++kk) {
            float a[8], bv[8];
#pragma unroll
            for (int i = 0; i < 8; i++) a[i] = aS[kk][ty*8+i];
#pragma unroll
            for (int j = 0; j < 8; j++) bv[j] = bS[kk][tx*8+j];
#pragma unroll
            for (int i = 0; i < 8; i++)
#pragma unroll
                for (int j = 0; j < 8; j++) acc[i][j] = fmaf(a[i], bv[j], acc[i][j]);
        }
        __syncthreads();
    }

    float scale = scalePtr ? scalePtr[0] : 1.f;
#pragma unroll
    for (int i = 0; i < 8; i++) {
        int m = m0 + ty * 8 + i;
        if (m < M) {
            float bi = bias ? bias[m] : 0.f;
#pragma unroll
            for (int j = 0; j < 8; j++) {
                int n = n0 + tx * 8 + j;
                size_t off = (size_t)m * N + n;
                float v = acc[i][j];
                if (Rb) v = scale * v + Rb[off];
                else v += bi;
                Cb[off] = v;
            }
        }
    }
}

// ---------------- generic 128x128 GEMM NT (fp32 SIMT) ----------------
__global__ void gemm_nt_kernel(const float* __restrict__ A, long aBS,
                               const float* __restrict__ Bm, long bBS,
                               float* __restrict__ C, long cBS,
                               const float* __restrict__ bias,
                               const float* __restrict__ scalePtr,
                               const float* __restrict__ Res,
                               int M, int N, int K) {
    int z = blockIdx.z;
    const float* Ab = A + (size_t)z * aBS;
    const float* Bb = Bm + (size_t)z * bBS;
    float* Cb = C + (size_t)z * cBS;
    const float* Rb = Res ? Res + (size_t)z * cBS : (const float*)0;
    int n0 = blockIdx.x * 128, m0 = blockIdx.y * 128;
    int t = threadIdx.x, tx = t & 15, ty = t >> 4;
    __shared__ float aS[8][128];
    __shared__ float bS[8][128];
    float acc[8][8];
#pragma unroll
    for (int i = 0; i < 8; i++)
#pragma unroll
        for (int j = 0; j < 8; j++) acc[i][j] = 0.f;

    int rload = t >> 1;
    int kq = (t & 1) * 4;

    for (int ck = 0; ck < K; ck += 8) {
        float4 av = make_float4(0.f, 0.f, 0.f, 0.f);
        if (m0 + rload < M)
            av = *(const float4*)(Ab + (size_t)(m0 + rload) * K + ck + kq);
        aS[kq+0][rload]=av.x; aS[kq+1][rload]=av.y; aS[kq+2][rload]=av.z; aS[kq+3][rload]=av.w;
        float4 bv4 = *(const float4*)(Bb + (size_t)(n0 + rload) * K + ck + kq);
        bS[kq+0][rload]=bv4.x; bS[kq+1][rload]=bv4.y; bS[kq+2][rload]=bv4.z; bS[kq+3][rload]=bv4.w;
        __syncthreads();
#pragma unroll
        for (int kk = 0; kk < 8; ++kk) {
            float a[8], bv[8];
#pragma unroll
            for (int i = 0; i < 8; i++) a[i] = aS[kk][ty*8+i];
#pragma unroll
            for (int j = 0; j < 8; j++) bv[j] = bS[kk][tx*8+j];
#pragma unroll
            for (int i = 0; i < 8; i++)
#pragma unroll
                for (int j = 0; j < 8; j++) acc[i][j] = fmaf(a[i], bv[j], acc[i][j]);
        }
        __syncthreads();
    }

    float scale = scalePtr ? scalePtr[0] : 1.f;
#pragma unroll
    for (int i = 0; i < 8; i++) {
        int m = m0 + ty * 8 + i;
        if (m < M) {
            float bi = bias ? bias[m] : 0.f;
#pragma unroll
            for (int j = 0; j < 8; j++) {
                int n = n0 + tx * 8 + j;
                size_t off = (size_t)m * N + n;
                float v = acc[i][j];
                if (Rb) v = scale * v + Rb[off];
                else v += bi;
                Cb[off] = v;
            }
        }
    }
}

// ---------------- PAM attention logits ----------------
__global__ void pam_logits_kernel(const float* __restrict__ fb, const float* __restrict__ fc,
                                  float* __restrict__ attn) {
    int b = blockIdx.z;
    int n0 = blockIdx.x * 64, m0 = blockIdx.y * 64;
    __shared__ float aS[64][65];
    __shared__ float bS[64][65];
    int t = threadIdx.x;
#pragma unroll
    for (int i = 0; i < 16; i++) {
        int idx = t + i * 256;
        int c = idx >> 6, n = idx & 63;
        aS[c][n] = fb[((size_t)b * 64 + c) * HW + n0 + n];
        bS[c][n] = fc[((size_t)b * 64 + c) * HW + m0 + n];
    }
    __syncthreads();
    int tx = t & 15, ty = t >> 4;
    float acc[4][4];
#pragma unroll
    for (int i = 0; i < 4; i++)
#pragma unroll
        for (int j = 0; j < 4; j++) acc[i][j] = 0.f;
#pragma unroll 8
    for (int c = 0; c < 64; c++) {
        float a[4], bv[4];
#pragma unroll
        for (int i = 0; i < 4; i++) a[i] = aS[c][ty*4+i];
#pragma unroll
        for (int j = 0; j < 4; j++) bv[j] = bS[c][tx*4+j];
#pragma unroll
        for (int i = 0; i < 4; i++)
#pragma unroll
            for (int j = 0; j < 4; j++) acc[i][j] = fmaf(a[i], bv[j], acc[i][j]);
    }
    float* dst = attn + (size_t)b * HW * HW;
#pragma unroll
    for (int i = 0; i < 4; i++)
#pragma unroll
        for (int j = 0; j < 4; j++)
            dst[(size_t)(n0 + ty*4+i) * HW + m0 + tx*4+j] = acc[i][j];
}

// ---------------- row softmax, cols = 4096 ----------------
__global__ void softmax4096_kernel(float* __restrict__ data) {
    size_t row = blockIdx.x;
    float4* p4 = (float4*)(data + row * (size_t)HW);
    int t = threadIdx.x;
    float4 v[4];
    float m = -1e30f;
#pragma unroll
    for (int i = 0; i < 4; i++) {
        v[i] = p4[t + i * 256];
        m = fmaxf(m, fmaxf(fmaxf(v[i].x, v[i].y), fmaxf(v[i].z, v[i].w)));
    }
    __shared__ float red[256];
    red[t] = m;
    __syncthreads();
    for (int s = 128; s > 0; s >>= 1) {
        if (t < s) red[t] = fmaxf(red[t], red[t + s]);
        __syncthreads();
    }
    m = red[0];
    __syncthreads();
    float sum = 0.f;
#pragma unroll
    for (int i = 0; i < 4; i++) {
        v[i].x = __expf(v[i].x - m);
        v[i].y = __expf(v[i].y - m);
        v[i].z = __expf(v[i].z - m);
        v[i].w = __expf(v[i].w - m);
        sum += v[i].x + v[i].y + v[i].z + v[i].w;
    }
    red[t] = sum;
    __syncthreads();
    for (int s = 128; s > 0; s >>= 1) {
        if (t < s) red[t] += red[t + s];
        __syncthreads();
    }
    float inv = 1.f / red[0];
#pragma unroll
    for (int i = 0; i < 4; i++) {
        v[i].x *= inv; v[i].y *= inv; v[i].z *= inv; v[i].w *= inv;
        p4[t + i * 256] = v[i];
    }
}

// ---------------- CAM softmax ----------------
__global__ void cam_softmax_kernel(float* __restrict__ data) {
    float4* p4 = (float4*)(data + (size_t)blockIdx.x * IC);
    int t = threadIdx.x;
    float4 v = p4[t];
    __shared__ float red[128];
    float m = fmaxf(fmaxf(v.x, v.y), fmaxf(v.z, v.w));
    red[t] = m;
    __syncthreads();
    for (int s = 64; s > 0; s >>= 1) {
        if (t < s) red[t] = fmaxf(red[t], red[t + s]);
        __syncthreads();
    }
    float m1 = red[0];
    __syncthreads();
    float mn = fminf(fminf(v.x, v.y), fminf(v.z, v.w));
    red[t] = mn;
    __syncthreads();
    for (int s = 64; s > 0; s >>= 1) {
        if (t < s) red[t] = fminf(red[t], red[t + s]);
        __syncthreads();
    }
    float m2 = m1 - red[0];
    __syncthreads();
    float4 e;
    e.x = __expf(m1 - v.x - m2);
    e.y = __expf(m1 - v.y - m2);
    e.z = __expf(m1 - v.z - m2);
    e.w = __expf(m1 - v.w - m2);
    red[t] = e.x + e.y + e.z + e.w;
    __syncthreads();
    for (int s = 64; s > 0; s >>= 1) {
        if (t < s) red[t] += red[t + s];
        __syncthreads();
    }
    float inv = 1.f / red[0];
    e.x *= inv; e.y *= inv; e.z *= inv; e.w *= inv;
    p4[t] = e;
}

// ---------------- elementwise add ----------------
__global__ void add_kernel(const float* __restrict__ a, const float* __restrict__ b,
                           float* __restrict__ c, int n) {
    int i = blockIdx.x * 256 + threadIdx.x;
    if (i < n) c[i] = a[i] + b[i];
}

// ---------------- bilinear 2x upsample ----------------
__global__ void up2x_kernel(const float* __restrict__ src, float* __restrict__ dst) {
    int idx = blockIdx.x * 256 + threadIdx.x;
    const int total = BB * NCLS * OHW;
    if (idx >= total) return;
    int ox = idx & 127;
    int r = idx >> 7;
    int oy = r & 127;
    r >>= 7;
    float sy = oy * 0.5f - 0.25f;
    float sx = ox * 0.5f - 0.25f;
    float fy = floorf(sy), fx = floorf(sx);
    float wy = sy - fy, wx = sx - fx;
    int y0 = (int)fy, x0 = (int)fx;
    int y0c = max(y0, 0), y1c = min(y0 + 1, 63);
    int x0c = max(x0, 0), x1c = min(x0 + 1, 63);
    const float* s = src + (size_t)r * HW;
    float v00 = s[y0c*64+x0c], v01 = s[y0c*64+x1c];
    float v10 = s[y1c*64+x0c], v11 = s[y1c*64+x1c];
    dst[idx] = (1.f-wy)*((1.f-wx)*v00 + wx*v01) + wy*((1.f-wx)*v10 + wx*v11);
}

// ---------------- orchestration ----------------
extern "C" void kernel_launch(void* const* d_in, const int* in_sizes, int n_in,
                              void* d_out, int out_size) {
    (void)in_sizes; (void)n_in; (void)out_size;
    const float* x    = (const float*)d_in[0];
    const float* wp1  = (const float*)d_in[1];
    const float* sp1  = (const float*)d_in[2];
    const float* bp1  = (const float*)d_in[3];
    const float* wc1  = (const float*)d_in[4];
    const float* sc1  = (const float*)d_in[5];
    const float* bc1  = (const float*)d_in[6];
    const float* pwb  = (const float*)d_in[7];
    const float* pbb  = (const float*)d_in[8];
    const float* pwc  = (const float*)d_in[9];
    const float* pbc  = (const float*)d_in[10];
    const float* pwd  = (const float*)d_in[11];
    const float* pbd  = (const float*)d_in[12];
    const float* alpha = (const float*)d_in[13];
    const float* beta  = (const float*)d_in[14];
    const float* wp2  = (const float*)d_in[15];
    const float* sp2  = (const float*)d_in[16];
    const float* bp2  = (const float*)d_in[17];
    const float* wc2  = (const float*)d_in[18];
    const float* sc2  = (const float*)d_in[19];
    const float* bc2  = (const float*)d_in[20];
    const float* wlog = (const float*)d_in[21];
    const float* blog = (const float*)d_in[22];
    const float* wp3  = (const float*)d_in[23];
    const float* bp3  = (const float*)d_in[24];
    const float* wc3  = (const float*)d_in[25];
    const float* bc3  = (const float*)d_in[26];
    float* out = (float*)d_out;

    uint32_t *wt1p, *wbc1, *wt2p, *wbc2, *xtf, *xsp, *pamtf, *camsp;
    float *featp0, *featc0, *fb, *fc, *fd, *attn;
    float *pam, *featp, *camatt, *cam, *featc, *fusion, *pout, *cout_, *fout;
    cudaGetSymbolAddress((void**)&wt1p, g_wt1p);
    cudaGetSymbolAddress((void**)&wbc1, g_wbc1);
    cudaGetSymbolAddress((void**)&wt2p, g_wt2p);
    cudaGetSymbolAddress((void**)&wbc2, g_wbc2);
    cudaGetSymbolAddress((void**)&xtf, g_xtf);
    cudaGetSymbolAddress((void**)&xsp, g_xsp);
    cudaGetSymbolAddress((void**)&pamtf, g_pamtf);
    cudaGetSymbolAddress((void**)&camsp, g_camsp);
    cudaGetSymbolAddress((void**)&featp0, g_featp0);
    cudaGetSymbolAddress((void**)&featc0, g_featc0);
    cudaGetSymbolAddress((void**)&fb, g_fb);
    cudaGetSymbolAddress((void**)&fc, g_fc);
    cudaGetSymbolAddress((void**)&fd, g_fd);
    cudaGetSymbolAddress((void**)&attn, g_attn);
    cudaGetSymbolAddress((void**)&pam, g_pam);
    cudaGetSymbolAddress((void**)&featp, g_featp);
    cudaGetSymbolAddress((void**)&camatt, g_camatt);
    cudaGetSymbolAddress((void**)&cam, g_cam);
    cudaGetSymbolAddress((void**)&featc, g_featc);
    cudaGetSymbolAddress((void**)&fusion, g_fusion);
    cudaGetSymbolAddress((void**)&pout, g_pout);
    cudaGetSymbolAddress((void**)&cout_, g_cout);
    cudaGetSymbolAddress((void**)&fout, g_fout);

    cudaFuncSetAttribute(conv_tf32ca_kernel,
                         cudaFuncAttributeMaxDynamicSharedMemorySize, TF_STG * 4 * 4);

    // weight + activation prepacks; conv_bf16 c1 placed 6th for ncu capture
    wtrans_kernel<<<4096, 256>>>(wp1, wt1p, CIN, IC);                         // 1
    wsplitbf_kernel<<<8192, 256>>>(wc1, wbc1, CIN, IC);                       // 2
    packtf_kernel<<<16384, 256>>>(x, xtf, (size_t)BB * CIN * HW);             // 3
    packsp_kernel<<<16384, 256>>>(x, xsp, CIN);                               // 4
    conv_tf32ca_kernel<<<dim3(128, 4), 256, TF_STG * 4 * 4>>>(xtf, wt1p, featp0, sp1, bp1, CIN, 1); // 5
    conv_bf16ca_kernel<<<dim3(128, 4), 256>>>(xsp, wbc1, featc0, sc1, bc1, CIN, 1);                 // 6
    wtrans_kernel<<<2048, 256>>>(wp2, wt2p, IC, IC);
    wsplitbf_kernel<<<2048, 256>>>(wc2, wbc2, IC, IC);

    // PAM projections (1x1 convs)
    gemm_nn_kernel<<<dim3(32, 1, 4), 256>>>(pwb, 0, featp0, (long)IC * HW,
                                            fb, (long)C8 * HW, pbb, 0, 0, C8, HW, IC);
    gemm_nn_kernel<<<dim3(32, 1, 4), 256>>>(pwc, 0, featp0, (long)IC * HW,
                                            fc, (long)C8 * HW, pbc, 0, 0, C8, HW, IC);
    gemm_nn_kernel<<<dim3(32, 4, 4), 256>>>(pwd, 0, featp0, (long)IC * HW,
                                            fd, (long)IC * HW, pbd, 0, 0, IC, HW, IC);

    // attention logits + softmax
    pam_logits_kernel<<<dim3(64, 64, 4), 256>>>(fb, fc, attn);
    softmax4096_kernel<<<BB * HW, 256>>>(attn);

    // PAM apply: pam = alpha * (fd @ attn^T) + featp0
    gemm_nt_kernel<<<dim3(32, 4, 4), 256>>>(fd, (long)IC * HW, attn, (long)HW * HW,
                                            pam, (long)IC * HW, 0, alpha, featp0,
                                            IC, HW, HW);

    // conv p2 (tf32, cp.async) after prepack
    packtf_kernel<<<8192, 256>>>(pam, pamtf, (size_t)BB * IC * HW);
    conv_tf32ca_kernel<<<dim3(128, 4), 256, TF_STG * 4 * 4>>>(pamtf, wt2p, featp, sp2, bp2, IC, 1);

    // CAM: gram (fp32 SIMT), softmax, apply (fp32 SIMT)
    gemm_nt_kernel<<<dim3(4, 4, 4), 256>>>(featc0, (long)IC * HW, featc0, (long)IC * HW,
                                           camatt, (long)IC * IC, 0, 0, 0,
                                           IC, IC, HW);
    cam_softmax_kernel<<<BB * IC, 128>>>(camatt);
    gemm_nn_kernel<<<dim3(32, 4, 4), 256>>>(camatt, (long)IC * IC, featc0, (long)IC * HW,
                                            cam, (long)IC * HW, 0, beta, featc0,
                                            IC, HW, IC);

    // conv c2 (bf16 split, cp.async) after prepack
    packsp_kernel<<<8192, 256>>>(cam, camsp, IC);
    conv_bf16ca_kernel<<<dim3(128, 4), 256>>>(camsp, wbc2, featc, sc2, bc2, IC, 1);

    // fusion + output heads
    add_kernel<<<(BB * IC * HW) / 256, 256>>>(featp, featc, fusion, BB * IC * HW);
    gemm_nn_kernel<<<dim3(32, 1, 4), 256>>>(wp3, 0, featp, (long)IC * HW,
                                            pout, (long)NCLS * HW, bp3, 0, 0, NCLS, HW, IC);
    gemm_nn_kernel<<<dim3(32, 1, 4), 256>>>(wc3, 0, featc, (long)IC * HW,
                                            cout_, (long)NCLS * HW, bc3, 0, 0, NCLS, HW, IC);
    gemm_nn_kernel<<<dim3(32, 1, 4), 256>>>(wlog, 0, fusion, (long)IC * HW,
                                            fout, (long)NCLS * HW, blog, 0, 0, NCLS, HW, IC);

    // upsample 2x into output
    const int outElems = BB * NCLS * OHW;
    up2x_kernel<<<(outElems + 255) / 256, 256>>>(pout, out);
    up2x_kernel<<<(outElems + 255) / 256, 256>>>(cout_, out + outElems);
    up2x_kernel<<<(outElems + 255) / 256, 256>>>(fout, out + 2 * (size_t)outElems);
}

// round 7
// speedup vs baseline: 2.3390x; 1.0356x over previous
#include <cuda_runtime.h>
#include <cuda_bf16.h>
#include <math.h>
#include <stdint.h>

// ---------------- problem constants ----------------
#define BB 4
#define CIN 2048
#define IC 512
#define C8 64
#define NCLS 81
#define HH 64
#define WW 64
#define HW 4096
#define OHW (128*128)
#define K2C1 (3*CIN/2)   // 3072 pair-rows per tap (c1)
#define K2C2 (3*IC/2)    // 768  pair-rows per tap (c2)
#define K2HW (3*HW/2)    // 6144 pair-words per 4096-length row

// ---------------- scratch (__device__ globals, no runtime alloc) ----------------
__device__ __align__(16) uint32_t g_wt1p[9*CIN*IC];
__device__ __align__(16) uint32_t g_wbc1[9*K2C1*IC];
__device__ __align__(16) uint32_t g_wt2p[9*IC*IC];
__device__ __align__(16) uint32_t g_wbc2[9*K2C2*IC];
__device__ __align__(16) uint32_t g_xtf[BB*CIN*HW];
__device__ __align__(16) uint32_t g_xsp[(size_t)BB*K2C1*HW];
__device__ __align__(16) uint32_t g_pamtf[BB*IC*HW];
__device__ __align__(16) uint32_t g_camsp[(size_t)BB*K2C2*HW];
__device__ __align__(16) uint32_t g_fbsp[BB*(3*C8/2)*HW];
__device__ __align__(16) uint32_t g_fcsp[BB*(3*C8/2)*HW];
__device__ __align__(16) uint32_t g_fdsp[(size_t)BB*IC*K2HW];
__device__ __align__(16) uint32_t g_attnsp[(size_t)BB*HW*K2HW];
__device__ float g_featp0[BB*IC*HW];
__device__ float g_featc0[BB*IC*HW];
__device__ float g_fb[BB*C8*HW];
__device__ float g_fc[BB*C8*HW];
__device__ float g_fd[BB*IC*HW];
__device__ float g_attn[(size_t)BB*HW*HW];
__device__ float g_pam[BB*IC*HW];
__device__ float g_featp[BB*IC*HW];
__device__ float g_camatt[BB*IC*IC];
__device__ float g_cam[BB*IC*HW];
__device__ float g_featc[BB*IC*HW];
__device__ float g_fusion[BB*IC*HW];
__device__ float g_pout[BB*NCLS*HW];
__device__ float g_cout[BB*NCLS*HW];
__device__ float g_fout[BB*NCLS*HW];

// ---------------- helpers ----------------
__device__ __forceinline__ uint32_t f2tf32(float f) {
    uint32_t r;
    asm("cvt.rna.tf32.f32 %0, %1;" : "=r"(r) : "f"(f));
    return r;
}
__device__ __forceinline__ void mma_tf32(float* c, const uint32_t* a, const uint32_t* b) {
    asm volatile(
        "mma.sync.aligned.m16n8k8.row.col.f32.tf32.tf32.f32 "
        "{%0,%1,%2,%3}, {%4,%5,%6,%7}, {%8,%9}, {%0,%1,%2,%3};"
        : "+f"(c[0]), "+f"(c[1]), "+f"(c[2]), "+f"(c[3])
        : "r"(a[0]), "r"(a[1]), "r"(a[2]), "r"(a[3]), "r"(b[0]), "r"(b[1]));
}
__device__ __forceinline__ void mma_bf16(float* c, const uint32_t* a, const uint32_t* b) {
    asm volatile(
        "mma.sync.aligned.m16n8k16.row.col.f32.bf16.bf16.f32 "
        "{%0,%1,%2,%3}, {%4,%5,%6,%7}, {%8,%9}, {%0,%1,%2,%3};"
        : "+f"(c[0]), "+f"(c[1]), "+f"(c[2]), "+f"(c[3])
        : "r"(a[0]), "r"(a[1]), "r"(a[2]), "r"(a[3]), "r"(b[0]), "r"(b[1]));
}
__device__ __forceinline__ unsigned short bf16bits(float v) {
    __nv_bfloat16 b = __float2bfloat16_rn(v);
    return *reinterpret_cast<unsigned short*>(&b);
}
__device__ __forceinline__ float bf16hi(float v) {
    return __bfloat162float(__float2bfloat16_rn(v));
}
__device__ __forceinline__ void cp4(uint32_t dst, const void* src, uint32_t sz) {
    asm volatile("cp.async.ca.shared.global [%0], [%1], 4, %2;" :: "r"(dst), "l"(src), "r"(sz));
}
__device__ __forceinline__ void cp4u(uint32_t dst, const void* src) {
    asm volatile("cp.async.ca.shared.global [%0], [%1], 4;" :: "r"(dst), "l"(src));
}
__device__ __forceinline__ void cp16(uint32_t dst, const void* src) {
    asm volatile("cp.async.cg.shared.global [%0], [%1], 16;" :: "r"(dst), "l"(src));
}
#define CP_COMMIT() asm volatile("cp.async.commit_group;")
#define CP_WAIT2()  asm volatile("cp.async.wait_group 2;")

// ---------------- weight transpose to tf32 bits ----------------
__global__ void wtrans_kernel(const float* __restrict__ w, uint32_t* __restrict__ wt,
                              int Cin, int Cout) {
    size_t total = (size_t)Cout * Cin * 9;
    for (size_t i = (size_t)blockIdx.x * blockDim.x + threadIdx.x; i < total;
         i += (size_t)gridDim.x * blockDim.x) {
        int co = (int)(i % Cout);
        size_t r = i / Cout;
        int ci = (int)(r % Cin);
        int tap = (int)(r / Cin);
        wt[i] = f2tf32(w[((size_t)co * Cin + ci) * 9 + tap]);
    }
}

// ---------------- bf16 triple-split packed weight prep (slots: hi, lo, hi) ----------------
__global__ void wsplitbf_kernel(const float* __restrict__ w, uint32_t* __restrict__ wp,
                                int Cin, int Cout) {
    int K2Ct = 3 * Cin / 2;
    size_t total = (size_t)9 * K2Ct * Cout;
    for (size_t i = (size_t)blockIdx.x * blockDim.x + threadIdx.x; i < total;
         i += (size_t)gridDim.x * blockDim.x) {
        int co = (int)(i % Cout);
        size_t r = i / Cout;
        int k2 = (int)(r % K2Ct);
        int tap = (int)(r / K2Ct);
        unsigned short h[2];
#pragma unroll
        for (int j = 0; j < 2; j++) {
            int s = 2 * k2 + j;
            int ci = s / 3, part = s - 3 * ci;
            float v = w[((size_t)co * Cin + ci) * 9 + tap];
            if (part == 1) v = v - bf16hi(v);
            h[j] = bf16bits(v);
        }
        wp[i] = (uint32_t)h[0] | ((uint32_t)h[1] << 16);
    }
}

// ---------------- activation prepack: f32 -> tf32 bits ----------------
__global__ void packtf_kernel(const float* __restrict__ in, uint32_t* __restrict__ out,
                              size_t n) {
    for (size_t i = (size_t)blockIdx.x * blockDim.x + threadIdx.x; i < n;
         i += (size_t)gridDim.x * blockDim.x)
        out[i] = f2tf32(in[i]);
}

// ---------------- channel-split pack: [B][C][HW] -> [B][3C/2][HW] bf16 pairs ----------------
// phlo selects which phase slot holds the low part (A-side: 1, B-side: 2).
__global__ void packsp_kernel(const float* __restrict__ in, uint32_t* __restrict__ out,
                              int Cin, int phlo) {
    int K2Ct = 3 * Cin / 2;
    size_t per_b = (size_t)K2Ct * HW;
    size_t total = (size_t)BB * per_b;
    for (size_t i = (size_t)blockIdx.x * blockDim.x + threadIdx.x; i < total;
         i += (size_t)gridDim.x * blockDim.x) {
        int b = (int)(i / per_b);
        size_t r = i - (size_t)b * per_b;
        int k2 = (int)(r / HW);
        int pos = (int)(r - (size_t)k2 * HW);
        const float* xb = in + (size_t)b * Cin * HW;
        unsigned short h[2];
#pragma unroll
        for (int j = 0; j < 2; j++) {
            int s = 2 * k2 + j;
            int ci = s / 3, ph = s - 3 * ci;
            float v = xb[(size_t)ci * HW + pos];
            if (ph == phlo) v = v - bf16hi(v);
            h[j] = bf16bits(v);
        }
        out[i] = (uint32_t)h[0] | ((uint32_t)h[1] << 16);
    }
}

// ---------------- row-split pack: [R][Kd] -> [R][3Kd/2] bf16 pairs along the row ----------------
__global__ void packrs_kernel(const float* __restrict__ in, uint32_t* __restrict__ out,
                              size_t rows, int Kd, int phlo) {
    int K2o = 3 * Kd / 2;
    size_t total = rows * (size_t)K2o;
    for (size_t i = (size_t)blockIdx.x * blockDim.x + threadIdx.x; i < total;
         i += (size_t)gridDim.x * blockDim.x) {
        size_t r = i / (size_t)K2o;
        int k2 = (int)(i - r * (size_t)K2o);
        const float* row = in + r * (size_t)Kd;
        unsigned short h[2];
#pragma unroll
        for (int j = 0; j < 2; j++) {
            int s = 2 * k2 + j;
            int k = s / 3, ph = s - 3 * k;
            float v = row[k];
            if (ph == phlo) v = v - bf16hi(v);
            h[j] = bf16bits(v);
        }
        out[i] = (uint32_t)h[0] | ((uint32_t)h[1] << 16);
    }
}

// ---------------- conv3x3 tf32, cp.async 4-stage pipeline (p-branch) ----------------
#define TF_STG (2*16*136)
__global__ __launch_bounds__(256, 2)
void conv_tf32ca_kernel(const uint32_t* __restrict__ xtf, const uint32_t* __restrict__ wt,
                        float* __restrict__ out,
                        const float* __restrict__ s, const float* __restrict__ bias,
                        int Cin, int relu) {
    const int Cout = gridDim.y * 128;
    extern __shared__ uint32_t dyn[];
    int sb = blockIdx.x;
    int b = sb >> 5;
    int y0 = (sb & 31) * 2;
    int co0 = blockIdx.y * 128;
    int t = threadIdx.x;
    int lane = t & 31, wid = t >> 5;
    int wm = (wid & 3) * 32, wn = (wid >> 2) * 64;
    int lg = lane >> 2, lq = lane & 3;
    const uint32_t* xb = xtf + (size_t)b * Cin * HW;
    const int iters = 9 * Cin / 16;
    uint32_t smb = (uint32_t)__cvta_generic_to_shared(dyn);

    auto issue = [&](int kt) {
        if (kt < iters) {
            int st = kt & 3;
            uint32_t sA = smb + st * TF_STG * 4;
            uint32_t sB = sA + 16 * 136 * 4;
            int gk = kt * 16;
            int tap = gk / Cin;
            int ci0 = gk - tap * Cin;
            int dy = tap / 3 - 1, dx = tap % 3 - 1;
#pragma unroll
            for (int i = 0; i < 2; i++) {
                int f = t + i * 256;
                int row = f >> 5, c4 = (f & 31) * 4;
                cp16(sA + (uint32_t)(row * 136 + c4) * 4,
                     wt + (size_t)(gk + row) * Cout + co0 + c4);
            }
#pragma unroll
            for (int i = 0; i < 8; i++) {
                int f = t + i * 256;
                int row = f >> 7, n = f & 127;
                int iy = y0 + (n >> 6) + dy, ix = (n & 63) + dx;
                bool inb = ((unsigned)iy < 64u) && ((unsigned)ix < 64u);
                const uint32_t* src = inb ? (xb + (size_t)(ci0 + row) * HW + iy * WW + ix) : xb;
                cp4(sB + (uint32_t)(row * 136 + n) * 4, src, inb ? 4u : 0u);
            }
        }
        CP_COMMIT();
    };

    issue(0); issue(1); issue(2);

    float acc[2][8][4];
#pragma unroll
    for (int i = 0; i < 2; i++)
#pragma unroll
        for (int j = 0; j < 8; j++)
#pragma unroll
            for (int q = 0; q < 4; q++) acc[i][j][q] = 0.f;

    for (int kt = 0; kt < iters; kt++) {
        CP_WAIT2();
        __syncthreads();
        int st = kt & 3;
        const uint32_t* sA = dyn + st * TF_STG;
        const uint32_t* sB = sA + 16 * 136;
#pragma unroll
        for (int k0 = 0; k0 < 16; k0 += 8) {
            uint32_t af[2][4], bf[8][2];
#pragma unroll
            for (int mt = 0; mt < 2; mt++) {
                int m = wm + mt * 16;
                af[mt][0] = sA[(k0 + lq) * 136 + m + lg];
                af[mt][1] = sA[(k0 + lq) * 136 + m + 8 + lg];
                af[mt][2] = sA[(k0 + 4 + lq) * 136 + m + lg];
                af[mt][3] = sA[(k0 + 4 + lq) * 136 + m + 8 + lg];
            }
#pragma unroll
            for (int nt = 0; nt < 8; nt++) {
                int n = wn + nt * 8;
                bf[nt][0] = sB[(k0 + lq) * 136 + n + lg];
                bf[nt][1] = sB[(k0 + 4 + lq) * 136 + n + lg];
            }
#pragma unroll
            for (int mt = 0; mt < 2; mt++)
#pragma unroll
                for (int nt = 0; nt < 8; nt++)
                    mma_tf32(acc[mt][nt], af[mt], bf[nt]);
        }
        issue(kt + 3);
    }

#pragma unroll
    for (int mt = 0; mt < 2; mt++) {
        int r0 = co0 + wm + mt * 16 + lg;
        float s0 = s ? s[r0] : 1.f, s1 = s ? s[r0 + 8] : 1.f;
        float b0 = bias ? bias[r0] : 0.f, b1 = bias ? bias[r0 + 8] : 0.f;
#pragma unroll
        for (int nt = 0; nt < 8; nt++) {
            int col = wn + nt * 8 + lq * 2;
            int yy = y0 + (col >> 6), xx = col & 63;
            float v0 = acc[mt][nt][0] * s0 + b0, v1 = acc[mt][nt][1] * s0 + b0;
            float v2 = acc[mt][nt][2] * s1 + b1, v3 = acc[mt][nt][3] * s1 + b1;
            if (relu) { v0 = fmaxf(v0, 0.f); v1 = fmaxf(v1, 0.f);
                        v2 = fmaxf(v2, 0.f); v3 = fmaxf(v3, 0.f); }
            size_t o0 = (((size_t)b * Cout + r0) * HH + yy) * WW + xx;
            size_t o1 = (((size_t)b * Cout + r0 + 8) * HH + yy) * WW + xx;
            *(float2*)(out + o0) = make_float2(v0, v1);
            *(float2*)(out + o1) = make_float2(v2, v3);
        }
    }
}

// ---------------- conv3x3 bf16 triple-split, cp.async 4-stage (c-branch) ----------------
#define BF_STG (2*8*136)
__global__ __launch_bounds__(256, 2)
void conv_bf16ca_kernel(const uint32_t* __restrict__ xsp, const uint32_t* __restrict__ wp,
                        float* __restrict__ out,
                        const float* __restrict__ s, const float* __restrict__ bias,
                        int Cin, int relu) {
    const int Cout = gridDim.y * 128;
    const int K2Ct = 3 * Cin / 2;
    __shared__ uint32_t smem[4 * BF_STG];
    int sb = blockIdx.x;
    int b = sb >> 5;
    int y0 = (sb & 31) * 2;
    int co0 = blockIdx.y * 128;
    int t = threadIdx.x;
    int lane = t & 31, wid = t >> 5;
    int wm = (wid & 3) * 32, wn = (wid >> 2) * 64;
    int lg = lane >> 2, lq = lane & 3;
    const uint32_t* xb = xsp + (size_t)b * K2Ct * HW;
    const int iters = 9 * K2Ct / 8;
    uint32_t smb = (uint32_t)__cvta_generic_to_shared(smem);

    auto issue = [&](int kt) {
        if (kt < iters) {
            int st = kt & 3;
            uint32_t sA = smb + st * BF_STG * 4;
            uint32_t sB = sA + 8 * 136 * 4;
            int g0 = kt * 8;
            int tap = g0 / K2Ct;
            int k20 = g0 - tap * K2Ct;
            int dy = tap / 3 - 1, dx = tap % 3 - 1;
            {
                int row = t >> 5, c4 = (t & 31) * 4;
                cp16(sA + (uint32_t)(row * 136 + c4) * 4,
                     wp + (size_t)(g0 + row) * Cout + co0 + c4);
            }
#pragma unroll
            for (int i = 0; i < 4; i++) {
                int f = t + i * 256;
                int row = f >> 7, n = f & 127;
                int iy = y0 + (n >> 6) + dy, ix = (n & 63) + dx;
                bool inb = ((unsigned)iy < 64u) && ((unsigned)ix < 64u);
                const uint32_t* src = inb ? (xb + (size_t)(k20 + row) * HW + iy * WW + ix) : xb;
                cp4(sB + (uint32_t)(row * 136 + n) * 4, src, inb ? 4u : 0u);
            }
        }
        CP_COMMIT();
    };

    issue(0); issue(1); issue(2);

    float acc[2][8][4];
#pragma unroll
    for (int i = 0; i < 2; i++)
#pragma unroll
        for (int j = 0; j < 8; j++)
#pragma unroll
            for (int q = 0; q < 4; q++) acc[i][j][q] = 0.f;

    for (int kt = 0; kt < iters; kt++) {
        CP_WAIT2();
        __syncthreads();
        int st = kt & 3;
        const uint32_t* sA = smem + st * BF_STG;
        const uint32_t* sB = sA + 8 * 136;
        {
            uint32_t af[2][4], bf[8][2];
#pragma unroll
            for (int mt = 0; mt < 2; mt++) {
                int m = wm + mt * 16;
                af[mt][0] = sA[lq * 136 + m + lg];
                af[mt][1] = sA[lq * 136 + m + 8 + lg];
                af[mt][2] = sA[(lq + 4) * 136 + m + lg];
                af[mt][3] = sA[(lq + 4) * 136 + m + 8 + lg];
            }
#pragma unroll
            for (int nt = 0; nt < 8; nt++) {
                int n = wn + nt * 8;
                bf[nt][0] = sB[lq * 136 + n + lg];
                bf[nt][1] = sB[(lq + 4) * 136 + n + lg];
            }
#pragma unroll
            for (int mt = 0; mt < 2; mt++)
#pragma unroll
                for (int nt = 0; nt < 8; nt++)
                    mma_bf16(acc[mt][nt], af[mt], bf[nt]);
        }
        issue(kt + 3);
    }

#pragma unroll
    for (int mt = 0; mt < 2; mt++) {
        int r0 = co0 + wm + mt * 16 + lg;
        float s0 = s ? s[r0] : 1.f, s1 = s ? s[r0 + 8] : 1.f;
        float b0 = bias ? bias[r0] : 0.f, b1 = bias ? bias[r0 + 8] : 0.f;
#pragma unroll
        for (int nt = 0; nt < 8; nt++) {
            int col = wn + nt * 8 + lq * 2;
            int yy = y0 + (col >> 6), xx = col & 63;
            float v0 = acc[mt][nt][0] * s0 + b0, v1 = acc[mt][nt][1] * s0 + b0;
            float v2 = acc[mt][nt][2] * s1 + b1, v3 = acc[mt][nt][3] * s1 + b1;
            if (relu) { v0 = fmaxf(v0, 0.f); v1 = fmaxf(v1, 0.f);
                        v2 = fmaxf(v2, 0.f); v3 = fmaxf(v3, 0.f); }
            size_t o0 = (((size_t)b * Cout + r0) * HH + yy) * WW + xx;
            size_t o1 = (((size_t)b * Cout + r0 + 8) * HH + yy) * WW + xx;
            *(float2*)(out + o0) = make_float2(v0, v1);
            *(float2*)(out + o1) = make_float2(v2, v3);
        }
    }
}

// ---------------- bf16 triple-split GEMM, cp.async 4-stage ----------------
// AT: A is [M][K2] row-major (trans-load) else [K2][ldA] k-major. Same for BT.
// C[m][n] = sum over pairs; epilogue: scale*acc + Res (if Res) else plain.
#define GS_STG (2*8*136)
template<int AT, int BT>
__global__ __launch_bounds__(256, 2)
void gemm_bf16s_kernel(const uint32_t* __restrict__ A, long aBS, int lda,
                       const uint32_t* __restrict__ B, long bBS, int ldb,
                       float* __restrict__ C, long cBS, int ldc,
                       const float* __restrict__ scalePtr,
                       const float* __restrict__ Res,
                       int K2) {
    __shared__ uint32_t smem[4 * GS_STG];
    int z = blockIdx.z;
    const uint32_t* Ab = A + (size_t)z * aBS;
    const uint32_t* Bb = B + (size_t)z * bBS;
    float* Cb = C + (size_t)z * cBS;
    const float* Rb = Res ? Res + (size_t)z * cBS : (const float*)0;
    int n0 = blockIdx.x * 128, m0 = blockIdx.y * 128;
    int t = threadIdx.x;
    int lane = t & 31, wid = t >> 5;
    int wm = (wid & 3) * 32, wn = (wid >> 2) * 64;
    int lg = lane >> 2, lq = lane & 3;
    const int iters = K2 / 8;
    uint32_t smb = (uint32_t)__cvta_generic_to_shared(smem);

    auto issue = [&](int kt) {
        if (kt < iters) {
            int st = kt & 3;
            uint32_t sA = smb + st * GS_STG * 4;
            uint32_t sB = sA + 8 * 136 * 4;
            int g0 = kt * 8;
            if (AT) {
#pragma unroll
                for (int i = 0; i < 4; i++) {
                    int f = t + i * 256;
                    int k2 = f & 7, m = f >> 3;
                    cp4u(sA + (uint32_t)(k2 * 136 + m) * 4,
                         Ab + (size_t)(m0 + m) * lda + g0 + k2);
                }
            } else {
                int k2 = t >> 5, c4 = (t & 31) * 4;
                cp16(sA + (uint32_t)(k2 * 136 + c4) * 4,
                     Ab + (size_t)(g0 + k2) * lda + m0 + c4);
            }
            if (BT) {
#pragma unroll
                for (int i = 0; i < 4; i++) {
                    int f = t + i * 256;
                    int k2 = f & 7, n = f >> 3;
                    cp4u(sB + (uint32_t)(k2 * 136 + n) * 4,
                         Bb + (size_t)(n0 + n) * ldb + g0 + k2);
                }
            } else {
                int k2 = t >> 5, c4 = (t & 31) * 4;
                cp16(sB + (uint32_t)(k2 * 136 + c4) * 4,
                     Bb + (size_t)(g0 + k2) * ldb + n0 + c4);
            }
        }
        CP_COMMIT();
    };

    issue(0); issue(1); issue(2);

    float acc[2][8][4];
#pragma unroll
    for (int i = 0; i < 2; i++)
#pragma unroll
        for (int j = 0; j < 8; j++)
#pragma unroll
            for (int q = 0; q < 4; q++) acc[i][j][q] = 0.f;

    for (int kt = 0; kt < iters; kt++) {
        CP_WAIT2();
        __syncthreads();
        int st = kt & 3;
        const uint32_t* sA = smem + st * GS_STG;
        const uint32_t* sB = sA + 8 * 136;
        {
            uint32_t af[2][4], bf[8][2];
#pragma unroll
            for (int mt = 0; mt < 2; mt++) {
                int m = wm + mt * 16;
                af[mt][0] = sA[lq * 136 + m + lg];
                af[mt][1] = sA[lq * 136 + m + 8 + lg];
                af[mt][2] = sA[(lq + 4) * 136 + m + lg];
                af[mt][3] = sA[(lq + 4) * 136 + m + 8 + lg];
            }
#pragma unroll
            for (int nt = 0; nt < 8; nt++) {
                int n = wn + nt * 8;
                bf[nt][0] = sB[lq * 136 + n + lg];
                bf[nt][1] = sB[(lq + 4) * 136 + n + lg];
            }
#pragma unroll
            for (int mt = 0; mt < 2; mt++)
#pragma unroll
                for (int nt = 0; nt < 8; nt++)
                    mma_bf16(acc[mt][nt], af[mt], bf[nt]);
        }
        issue(kt + 3);
    }

    float scale = scalePtr ? scalePtr[0] : 1.f;
#pragma unroll
    for (int mt = 0; mt < 2; mt++) {
        int r0 = m0 + wm + mt * 16 + lg;
#pragma unroll
        for (int nt = 0; nt < 8; nt++) {
            int col = n0 + wn + nt * 8 + lq * 2;
            size_t o0 = (size_t)r0 * ldc + col;
            size_t o1 = (size_t)(r0 + 8) * ldc + col;
            float v0 = acc[mt][nt][0], v1 = acc[mt][nt][1];
            float v2 = acc[mt][nt][2], v3 = acc[mt][nt][3];
            if (Rb) {
                v0 = scale * v0 + Rb[o0]; v1 = scale * v1 + Rb[o0 + 1];
                v2 = scale * v2 + Rb[o1]; v3 = scale * v3 + Rb[o1 + 1];
            }
            *(float2*)(Cb + o0) = make_float2(v0, v1);
            *(float2*)(Cb + o1) = make_float2(v2, v3);
        }
    }
}

// ---------------- generic 128x128 GEMM NN (fp32 SIMT) ----------------
__global__ void gemm_nn_kernel(const float* __restrict__ A, long aBS,
                               const float* __restrict__ Bm, long bBS,
                               float* __restrict__ C, long cBS,
                               const float* __restrict__ bias,
                               const float* __restrict__ scalePtr,
                               const float* __restrict__ Res,
                               int M, int N, int K) {
    int z = blockIdx.z;
    const float* Ab = A + (size_t)z * aBS;
    const float* Bb = Bm + (size_t)z * bBS;
    float* Cb = C + (size_t)z * cBS;
    const float* Rb = Res ? Res + (size_t)z * cBS : (const float*)0;
    int n0 = blockIdx.x * 128, m0 = blockIdx.y * 128;
    int t = threadIdx.x, tx = t & 15, ty = t >> 4;
    __shared__ float aS[8][128];
    __shared__ float bS[8][128];
    float acc[8][8];
#pragma unroll
    for (int i = 0; i < 8; i++)
#pragma unroll
        for (int j = 0; j < 8; j++) acc[i][j] = 0.f;

    int mload = t >> 1;
    int kq = (t & 1) * 4;

    for (int ck = 0; ck < K; ck += 8) {
        float4 av = make_float4(0.f, 0.f, 0.f, 0.f);
        if (m0 + mload < M)
            av = *(const float4*)(Ab + (size_t)(m0 + mload) * K + ck + kq);
        aS[kq+0][mload]=av.x; aS[kq+1][mload]=av.y; aS[kq+2][mload]=av.z; aS[kq+3][mload]=av.w;
#pragma unroll
        for (int i = 0; i < 4; ++i) {
            int idx = t + i * 256;
            int k = idx >> 7, n = idx & 127;
            bS[k][n] = Bb[(size_t)(ck + k) * N + n0 + n];
        }
        __syncthreads();
#pragma unroll
        for (int kk = 0; kk < 8; ++kk) {
            float a[8], bv[8];
#pragma unroll
            for (int i = 0; i < 8; i++) a[i] = aS[kk][ty*8+i];
#pragma unroll
            for (int j = 0; j < 8; j++) bv[j] = bS[kk][tx*8+j];
#pragma unroll
            for (int i = 0; i < 8; i++)
#pragma unroll
                for (int j = 0; j < 8; j++) acc[i][j] = fmaf(a[i], bv[j], acc[i][j]);
        }
        __syncthreads();
    }

    float scale = scalePtr ? scalePtr[0] : 1.f;
#pragma unroll
    for (int i = 0; i < 8; i++) {
        int m = m0 + ty * 8 + i;
        if (m < M) {
            float bi = bias ? bias[m] : 0.f;
#pragma unroll
            for (int j = 0; j < 8; j++) {
                int n = n0 + tx * 8 + j;
                size_t off = (size_t)m * N + n;
                float v = acc[i][j];
                if (Rb) v = scale * v + Rb[off];
                else v += bi;
                Cb[off] = v;
            }
        }
    }
}

// ---------------- generic 128x128 GEMM NT (fp32 SIMT) ----------------
__global__ void gemm_nt_kernel(const float* __restrict__ A, long aBS,
                               const float* __restrict__ Bm, long bBS,
                               float* __restrict__ C, long cBS,
                               const float* __restrict__ bias,
                               const float* __restrict__ scalePtr,
                               const float* __restrict__ Res,
                               int M, int N, int K) {
    int z = blockIdx.z;
    const float* Ab = A + (size_t)z * aBS;
    const float* Bb = Bm + (size_t)z * bBS;
    float* Cb = C + (size_t)z * cBS;
    const float* Rb = Res ? Res + (size_t)z * cBS : (const float*)0;
    int n0 = blockIdx.x * 128, m0 = blockIdx.y * 128;
    int t = threadIdx.x, tx = t & 15, ty = t >> 4;
    __shared__ float aS[8][128];
    __shared__ float bS[8][128];
    float acc[8][8];
#pragma unroll
    for (int i = 0; i < 8; i++)
#pragma unroll
        for (int j = 0; j < 8; j++) acc[i][j] = 0.f;

    int rload = t >> 1;
    int kq = (t & 1) * 4;

    for (int ck = 0; ck < K; ck += 8) {
        float4 av = make_float4(0.f, 0.f, 0.f, 0.f);
        if (m0 + rload < M)
            av = *(const float4*)(Ab + (size_t)(m0 + rload) * K + ck + kq);
        aS[kq+0][rload]=av.x; aS[kq+1][rload]=av.y; aS[kq+2][rload]=av.z; aS[kq+3][rload]=av.w;
        float4 bv4 = *(const float4*)(Bb + (size_t)(n0 + rload) * K + ck + kq);
        bS[kq+0][rload]=bv4.x; bS[kq+1][rload]=bv4.y; bS[kq+2][rload]=bv4.z; bS[kq+3][rload]=bv4.w;
        __syncthreads();
#pragma unroll
        for (int kk = 0; kk < 8; ++kk) {
            float a[8], bv[8];
#pragma unroll
            for (int i = 0; i < 8; i++) a[i] = aS[kk][ty*8+i];
#pragma unroll
            for (int j = 0; j < 8; j++) bv[j] = bS[kk][tx*8+j];
#pragma unroll
            for (int i = 0; i < 8; i++)
#pragma unroll
                for (int j = 0; j < 8; j++) acc[i][j] = fmaf(a[i], bv[j], acc[i][j]);
        }
        __syncthreads();
    }

    float scale = scalePtr ? scalePtr[0] : 1.f;
#pragma unroll
    for (int i = 0; i < 8; i++) {
        int m = m0 + ty * 8 + i;
        if (m < M) {
            float bi = bias ? bias[m] : 0.f;
#pragma unroll
            for (int j = 0; j < 8; j++) {
                int n = n0 + tx * 8 + j;
                size_t off = (size_t)m * N + n;
                float v = acc[i][j];
                if (Rb) v = scale * v + Rb[off];
                else v += bi;
                Cb[off] = v;
            }
        }
    }
}

// ---------------- row softmax, cols = 4096 ----------------
__global__ void softmax4096_kernel(float* __restrict__ data) {
    size_t row = blockIdx.x;
    float4* p4 = (float4*)(data + row * (size_t)HW);
    int t = threadIdx.x;
    float4 v[4];
    float m = -1e30f;
#pragma unroll
    for (int i = 0; i < 4; i++) {
        v[i] = p4[t + i * 256];
        m = fmaxf(m, fmaxf(fmaxf(v[i].x, v[i].y), fmaxf(v[i].z, v[i].w)));
    }
    __shared__ float red[256];
    red[t] = m;
    __syncthreads();
    for (int s = 128; s > 0; s >>= 1) {
        if (t < s) red[t] = fmaxf(red[t], red[t + s]);
        __syncthreads();
    }
    m = red[0];
    __syncthreads();
    float sum = 0.f;
#pragma unroll
    for (int i = 0; i < 4; i++) {
        v[i].x = __expf(v[i].x - m);
        v[i].y = __expf(v[i].y - m);
        v[i].z = __expf(v[i].z - m);
        v[i].w = __expf(v[i].w - m);
        sum += v[i].x + v[i].y + v[i].z + v[i].w;
    }
    red[t] = sum;
    __syncthreads();
    for (int s = 128; s > 0; s >>= 1) {
        if (t < s) red[t] += red[t + s];
        __syncthreads();
    }
    float inv = 1.f / red[0];
#pragma unroll
    for (int i = 0; i < 4; i++) {
        v[i].x *= inv; v[i].y *= inv; v[i].z *= inv; v[i].w *= inv;
        p4[t + i * 256] = v[i];
    }
}

// ---------------- CAM softmax ----------------
__global__ void cam_softmax_kernel(float* __restrict__ data) {
    float4* p4 = (float4*)(data + (size_t)blockIdx.x * IC);
    int t = threadIdx.x;
    float4 v = p4[t];
    __shared__ float red[128];
    float m = fmaxf(fmaxf(v.x, v.y), fmaxf(v.z, v.w));
    red[t] = m;
    __syncthreads();
    for (int s = 64; s > 0; s >>= 1) {
        if (t < s) red[t] = fmaxf(red[t], red[t + s]);
        __syncthreads();
    }
    float m1 = red[0];
    __syncthreads();
    float mn = fminf(fminf(v.x, v.y), fminf(v.z, v.w));
    red[t] = mn;
    __syncthreads();
    for (int s = 64; s > 0; s >>= 1) {
        if (t < s) red[t] = fminf(red[t], red[t + s]);
        __syncthreads();
    }
    float m2 = m1 - red[0];
    __syncthreads();
    float4 e;
    e.x = __expf(m1 - v.x - m2);
    e.y = __expf(m1 - v.y - m2);
    e.z = __expf(m1 - v.z - m2);
    e.w = __expf(m1 - v.w - m2);
    red[t] = e.x + e.y + e.z + e.w;
    __syncthreads();
    for (int s = 64; s > 0; s >>= 1) {
        if (t < s) red[t] += red[t + s];
        __syncthreads();
    }
    float inv = 1.f / red[0];
    e.x *= inv; e.y *= inv; e.z *= inv; e.w *= inv;
    p4[t] = e;
}

// ---------------- elementwise add ----------------
__global__ void add_kernel(const float* __restrict__ a, const float* __restrict__ b,
                           float* __restrict__ c, int n) {
    int i = blockIdx.x * 256 + threadIdx.x;
    if (i < n) c[i] = a[i] + b[i];
}

// ---------------- bilinear 2x upsample ----------------
__global__ void up2x_kernel(const float* __restrict__ src, float* __restrict__ dst) {
    int idx = blockIdx.x * 256 + threadIdx.x;
    const int total = BB * NCLS * OHW;
    if (idx >= total) return;
    int ox = idx & 127;
    int r = idx >> 7;
    int oy = r & 127;
    r >>= 7;
    float sy = oy * 0.5f - 0.25f;
    float sx = ox * 0.5f - 0.25f;
    float fy = floorf(sy), fx = floorf(sx);
    float wy = sy - fy, wx = sx - fx;
    int y0 = (int)fy, x0 = (int)fx;
    int y0c = max(y0, 0), y1c = min(y0 + 1, 63);
    int x0c = max(x0, 0), x1c = min(x0 + 1, 63);
    const float* s = src + (size_t)r * HW;
    float v00 = s[y0c*64+x0c], v01 = s[y0c*64+x1c];
    float v10 = s[y1c*64+x0c], v11 = s[y1c*64+x1c];
    dst[idx] = (1.f-wy)*((1.f-wx)*v00 + wx*v01) + wy*((1.f-wx)*v10 + wx*v11);
}

// ---------------- orchestration ----------------
extern "C" void kernel_launch(void* const* d_in, const int* in_sizes, int n_in,
                              void* d_out, int out_size) {
    (void)in_sizes; (void)n_in; (void)out_size;
    const float* x    = (const float*)d_in[0];
    const float* wp1  = (const float*)d_in[1];
    const float* sp1  = (const float*)d_in[2];
    const float* bp1  = (const float*)d_in[3];
    const float* wc1  = (const float*)d_in[4];
    const float* sc1  = (const float*)d_in[5];
    const float* bc1  = (const float*)d_in[6];
    const float* pwb  = (const float*)d_in[7];
    const float* pbb  = (const float*)d_in[8];
    const float* pwc  = (const float*)d_in[9];
    const float* pbc  = (const float*)d_in[10];
    const float* pwd  = (const float*)d_in[11];
    const float* pbd  = (const float*)d_in[12];
    const float* alpha = (const float*)d_in[13];
    const float* beta  = (const float*)d_in[14];
    const float* wp2  = (const float*)d_in[15];
    const float* sp2  = (const float*)d_in[16];
    const float* bp2  = (const float*)d_in[17];
    const float* wc2  = (const float*)d_in[18];
    const float* sc2  = (const float*)d_in[19];
    const float* bc2  = (const float*)d_in[20];
    const float* wlog = (const float*)d_in[21];
    const float* blog = (const float*)d_in[22];
    const float* wp3  = (const float*)d_in[23];
    const float* bp3  = (const float*)d_in[24];
    const float* wc3  = (const float*)d_in[25];
    const float* bc3  = (const float*)d_in[26];
    float* out = (float*)d_out;

    uint32_t *wt1p, *wbc1, *wt2p, *wbc2, *xtf, *xsp, *pamtf, *camsp;
    uint32_t *fbsp, *fcsp, *fdsp, *attnsp;
    float *featp0, *featc0, *fb, *fc, *fd, *attn;
    float *pam, *featp, *camatt, *cam, *featc, *fusion, *pout, *cout_, *fout;
    cudaGetSymbolAddress((void**)&wt1p, g_wt1p);
    cudaGetSymbolAddress((void**)&wbc1, g_wbc1);
    cudaGetSymbolAddress((void**)&wt2p, g_wt2p);
    cudaGetSymbolAddress((void**)&wbc2, g_wbc2);
    cudaGetSymbolAddress((void**)&xtf, g_xtf);
    cudaGetSymbolAddress((void**)&xsp, g_xsp);
    cudaGetSymbolAddress((void**)&pamtf, g_pamtf);
    cudaGetSymbolAddress((void**)&camsp, g_camsp);
    cudaGetSymbolAddress((void**)&fbsp, g_fbsp);
    cudaGetSymbolAddress((void**)&fcsp, g_fcsp);
    cudaGetSymbolAddress((void**)&fdsp, g_fdsp);
    cudaGetSymbolAddress((void**)&attnsp, g_attnsp);
    cudaGetSymbolAddress((void**)&featp0, g_featp0);
    cudaGetSymbolAddress((void**)&featc0, g_featc0);
    cudaGetSymbolAddress((void**)&fb, g_fb);
    cudaGetSymbolAddress((void**)&fc, g_fc);
    cudaGetSymbolAddress((void**)&fd, g_fd);
    cudaGetSymbolAddress((void**)&attn, g_attn);
    cudaGetSymbolAddress((void**)&pam, g_pam);
    cudaGetSymbolAddress((void**)&featp, g_featp);
    cudaGetSymbolAddress((void**)&camatt, g_camatt);
    cudaGetSymbolAddress((void**)&cam, g_cam);
    cudaGetSymbolAddress((void**)&featc, g_featc);
    cudaGetSymbolAddress((void**)&fusion, g_fusion);
    cudaGetSymbolAddress((void**)&pout, g_pout);
    cudaGetSymbolAddress((void**)&cout_, g_cout);
    cudaGetSymbolAddress((void**)&fout, g_fout);

    cudaFuncSetAttribute(conv_tf32ca_kernel,
                         cudaFuncAttributeMaxDynamicSharedMemorySize, TF_STG * 4 * 4);

    // weight + activation prepacks
    wtrans_kernel<<<4096, 256>>>(wp1, wt1p, CIN, IC);
    wsplitbf_kernel<<<8192, 256>>>(wc1, wbc1, CIN, IC);
    packtf_kernel<<<16384, 256>>>(x, xtf, (size_t)BB * CIN * HW);
    packsp_kernel<<<16384, 256>>>(x, xsp, CIN, 2);
    conv_tf32ca_kernel<<<dim3(128, 4), 256, TF_STG * 4 * 4>>>(xtf, wt1p, featp0, sp1, bp1, CIN, 1);
    conv_bf16ca_kernel<<<dim3(128, 4), 256>>>(xsp, wbc1, featc0, sc1, bc1, CIN, 1);
    wtrans_kernel<<<2048, 256>>>(wp2, wt2p, IC, IC);
    wsplitbf_kernel<<<2048, 256>>>(wc2, wbc2, IC, IC);

    // PAM projections (1x1 convs, fp32 SIMT)
    gemm_nn_kernel<<<dim3(32, 1, 4), 256>>>(pwb, 0, featp0, (long)IC * HW,
                                            fb, (long)C8 * HW, pbb, 0, 0, C8, HW, IC);
    gemm_nn_kernel<<<dim3(32, 1, 4), 256>>>(pwc, 0, featp0, (long)IC * HW,
                                            fc, (long)C8 * HW, pbc, 0, 0, C8, HW, IC);
    gemm_nn_kernel<<<dim3(32, 4, 4), 256>>>(pwd, 0, featp0, (long)IC * HW,
                                            fd, (long)IC * HW, pbd, 0, 0, IC, HW, IC);

    // PAM logits on tensor cores (bf16-split3, fp32-grade): attn[n][m] = fb^T fc
    packsp_kernel<<<2048, 256>>>(fb, fbsp, C8, 1);   // A-side phases (hi, lo, hi)
    packsp_kernel<<<2048, 256>>>(fc, fcsp, C8, 2);   // B-side phases (hi, hi, lo)
    gemm_bf16s_kernel<0, 0><<<dim3(32, 32, 4), 256>>>(
        fbsp, (long)(3 * C8 / 2) * HW, HW,
        fcsp, (long)(3 * C8 / 2) * HW, HW,
        attn, (long)HW * HW, HW, 0, 0, 3 * C8 / 2);
    softmax4096_kernel<<<BB * HW, 256>>>(attn);

    // PAM apply on tensor cores: pam = alpha * (fd @ attn^T) + featp0
    packrs_kernel<<<8192, 256>>>(fd, fdsp, (size_t)BB * IC, HW, 1);
    packrs_kernel<<<32768, 256>>>(attn, attnsp, (size_t)BB * HW, HW, 2);
    gemm_bf16s_kernel<1, 1><<<dim3(32, 4, 4), 256>>>(
        fdsp, (long)IC * K2HW, K2HW,
        attnsp, (long)HW * K2HW, K2HW,
        pam, (long)IC * HW, HW, alpha, featp0, K2HW);

    // conv p2 (tf32, cp.async) after prepack
    packtf_kernel<<<8192, 256>>>(pam, pamtf, (size_t)BB * IC * HW);
    conv_tf32ca_kernel<<<dim3(128, 4), 256, TF_STG * 4 * 4>>>(pamtf, wt2p, featp, sp2, bp2, IC, 1);

    // CAM: gram (fp32 SIMT), softmax, apply (fp32 SIMT)
    gemm_nt_kernel<<<dim3(4, 4, 4), 256>>>(featc0, (long)IC * HW, featc0, (long)IC * HW,
                                           camatt, (long)IC * IC, 0, 0, 0,
                                           IC, IC, HW);
    cam_softmax_kernel<<<BB * IC, 128>>>(camatt);
    gemm_nn_kernel<<<dim3(32, 4, 4), 256>>>(camatt, (long)IC * IC, featc0, (long)IC * HW,
                                            cam, (long)IC * HW, 0, beta, featc0,
                                            IC, HW, IC);

    // conv c2 (bf16 split, cp.async) after prepack
    packsp_kernel<<<8192, 256>>>(cam, camsp, IC, 2);
    conv_bf16ca_kernel<<<dim3(128, 4), 256>>>(camsp, wbc2, featc, sc2, bc2, IC, 1);

    // fusion + output heads
    add_kernel<<<(BB * IC * HW) / 256, 256>>>(featp, featc, fusion, BB * IC * HW);
    gemm_nn_kernel<<<dim3(32, 1, 4), 256>>>(wp3, 0, featp, (long)IC * HW,
                                            pout, (long)NCLS * HW, bp3, 0, 0, NCLS, HW, IC);
    gemm_nn_kernel<<<dim3(32, 1, 4), 256>>>(wc3, 0, featc, (long)IC * HW,
                                            cout_, (long)NCLS * HW, bc3, 0, 0, NCLS, HW, IC);
    gemm_nn_kernel<<<dim3(32, 1, 4), 256>>>(wlog, 0, fusion, (long)IC * HW,
                                            fout, (long)NCLS * HW, blog, 0, 0, NCLS, HW, IC);

    // upsample 2x into output
    const int outElems = BB * NCLS * OHW;
    up2x_kernel<<<(outElems + 255) / 256, 256>>>(pout, out);
    up2x_kernel<<<(outElems + 255) / 256, 256>>>(cout_, out + outElems);
    up2x_kernel<<<(outElems + 255) / 256, 256>>>(fout, out + 2 * (size_t)outElems);
}

// round 8
// speedup vs baseline: 2.4626x; 1.0529x over previous
#include <cuda_runtime.h>
#include <cuda_bf16.h>
#include <math.h>
#include <stdint.h>

// ---------------- problem constants ----------------
#define BB 4
#define CIN 2048
#define IC 512
#define C8 64
#define NCLS 81
#define HH 64
#define WW 64
#define HW 4096
#define OHW (128*128)
#define K2C1 (3*CIN/2)
#define K2C2 (3*IC/2)
#define K2HW (3*HW/2)    // 6144

// ---------------- scratch ----------------
__device__ __align__(16) uint32_t g_wt1p[9*CIN*IC];
__device__ __align__(16) uint32_t g_wbc1[9*K2C1*IC];
__device__ __align__(16) uint32_t g_wt2p[9*IC*IC];
__device__ __align__(16) uint32_t g_wbc2[9*K2C2*IC];
__device__ __align__(16) uint32_t g_xtf[BB*CIN*HW];
__device__ __align__(16) uint32_t g_xsp[(size_t)BB*K2C1*HW];
__device__ __align__(16) uint32_t g_pamtf[BB*IC*HW];
__device__ __align__(16) uint32_t g_camsp[(size_t)BB*K2C2*HW];
__device__ __align__(16) uint32_t g_fbsp[BB*(3*C8/2)*HW];
__device__ __align__(16) uint32_t g_fcsp[BB*(3*C8/2)*HW];
__device__ __align__(16) uint32_t g_fdsp[(size_t)BB*IC*K2HW];
__device__ __align__(16) uint32_t g_attnsp[(size_t)BB*HW*K2HW];
__device__ __align__(16) uint32_t g_fp0cs[(size_t)BB*K2C2*HW];
__device__ __align__(16) uint32_t g_fc0cs[(size_t)BB*K2C2*HW];
__device__ __align__(16) uint32_t g_fc0rsA[(size_t)BB*IC*K2HW];
__device__ __align__(16) uint32_t g_fc0rsB[(size_t)BB*IC*K2HW];
__device__ __align__(16) uint32_t g_wdrs[IC*(3*IC/2)];
__device__ __align__(16) uint32_t g_catsp[BB*IC*(3*IC/2)];
__device__ float g_featp0[BB*IC*HW];
__device__ float g_featc0[BB*IC*HW];
__device__ float g_fb[BB*C8*HW];
__device__ float g_fc[BB*C8*HW];
__device__ float g_fd[BB*IC*HW];
__device__ float g_attn[(size_t)BB*HW*HW];
__device__ float g_pam[BB*IC*HW];
__device__ float g_featp[BB*IC*HW];
__device__ float g_camatt[BB*IC*IC];
__device__ float g_cam[BB*IC*HW];
__device__ float g_featc[BB*IC*HW];
__device__ float g_fusion[BB*IC*HW];
__device__ float g_pout[BB*NCLS*HW];
__device__ float g_cout[BB*NCLS*HW];
__device__ float g_fout[BB*NCLS*HW];

// ---------------- helpers ----------------
__device__ __forceinline__ uint32_t f2tf32(float f) {
    uint32_t r;
    asm("cvt.rna.tf32.f32 %0, %1;" : "=r"(r) : "f"(f));
    return r;
}
__device__ __forceinline__ void mma_tf32(float* c, const uint32_t* a, const uint32_t* b) {
    asm volatile(
        "mma.sync.aligned.m16n8k8.row.col.f32.tf32.tf32.f32 "
        "{%0,%1,%2,%3}, {%4,%5,%6,%7}, {%8,%9}, {%0,%1,%2,%3};"
        : "+f"(c[0]), "+f"(c[1]), "+f"(c[2]), "+f"(c[3])
        : "r"(a[0]), "r"(a[1]), "r"(a[2]), "r"(a[3]), "r"(b[0]), "r"(b[1]));
}
__device__ __forceinline__ void mma_bf16(float* c, const uint32_t* a, const uint32_t* b) {
    asm volatile(
        "mma.sync.aligned.m16n8k16.row.col.f32.bf16.bf16.f32 "
        "{%0,%1,%2,%3}, {%4,%5,%6,%7}, {%8,%9}, {%0,%1,%2,%3};"
        : "+f"(c[0]), "+f"(c[1]), "+f"(c[2]), "+f"(c[3])
        : "r"(a[0]), "r"(a[1]), "r"(a[2]), "r"(a[3]), "r"(b[0]), "r"(b[1]));
}
__device__ __forceinline__ uint32_t bf16bits(float v) {
    __nv_bfloat16 b = __float2bfloat16_rn(v);
    return (uint32_t)*reinterpret_cast<unsigned short*>(&b);
}
__device__ __forceinline__ float bf16hi(float v) {
    return __bfloat162float(__float2bfloat16_rn(v));
}
// split pair (v0, v1) -> 3 u32 with A phases (hi,lo,hi) or B phases (hi,hi,lo)
__device__ __forceinline__ void split3(float v0, float v1, int phlo,
                                       uint32_t& u0, uint32_t& u1, uint32_t& u2) {
    uint32_t h0 = bf16bits(v0), h1 = bf16bits(v1);
    uint32_t l0 = bf16bits(v0 - bf16hi(v0)), l1 = bf16bits(v1 - bf16hi(v1));
    if (phlo == 1) { u0 = h0 | (l0 << 16); u1 = h0 | (h1 << 16); u2 = l1 | (h1 << 16); }
    else           { u0 = h0 | (h0 << 16); u1 = l0 | (h1 << 16); u2 = h1 | (l1 << 16); }
}
__device__ __forceinline__ void cp4(uint32_t dst, const void* src, uint32_t sz) {
    asm volatile("cp.async.ca.shared.global [%0], [%1], 4, %2;" :: "r"(dst), "l"(src), "r"(sz));
}
__device__ __forceinline__ void cp4u(uint32_t dst, const void* src) {
    asm volatile("cp.async.ca.shared.global [%0], [%1], 4;" :: "r"(dst), "l"(src));
}
__device__ __forceinline__ void cp16(uint32_t dst, const void* src) {
    asm volatile("cp.async.cg.shared.global [%0], [%1], 16;" :: "r"(dst), "l"(src));
}
#define CP_COMMIT() asm volatile("cp.async.commit_group;")
#define CP_WAIT2()  asm volatile("cp.async.wait_group 2;")

// ---------------- weight transpose to tf32 bits ----------------
__global__ void wtrans_kernel(const float* __restrict__ w, uint32_t* __restrict__ wt,
                              int Cin, int Cout) {
    size_t total = (size_t)Cout * Cin * 9;
    for (size_t i = (size_t)blockIdx.x * blockDim.x + threadIdx.x; i < total;
         i += (size_t)gridDim.x * blockDim.x) {
        int co = (int)(i % Cout);
        size_t r = i / Cout;
        int ci = (int)(r % Cin);
        int tap = (int)(r / Cin);
        wt[i] = f2tf32(w[((size_t)co * Cin + ci) * 9 + tap]);
    }
}

// ---------------- bf16 split weight prep for convs (slots: hi, lo, hi) ----------------
__global__ void wsplitbf_kernel(const float* __restrict__ w, uint32_t* __restrict__ wp,
                                int Cin, int Cout) {
    int K2Ct = 3 * Cin / 2;
    size_t total = (size_t)9 * K2Ct * Cout;
    for (size_t i = (size_t)blockIdx.x * blockDim.x + threadIdx.x; i < total;
         i += (size_t)gridDim.x * blockDim.x) {
        int co = (int)(i % Cout);
        size_t r = i / Cout;
        int k2 = (int)(r % K2Ct);
        int tap = (int)(r / K2Ct);
        uint32_t h[2];
#pragma unroll
        for (int j = 0; j < 2; j++) {
            int s = 2 * k2 + j;
            int ci = s / 3, part = s - 3 * ci;
            float v = w[((size_t)co * Cin + ci) * 9 + tap];
            if (part == 1) v = v - bf16hi(v);
            h[j] = bf16bits(v);
        }
        wp[i] = h[0] | (h[1] << 16);
    }
}

// ---------------- f32 -> tf32 bits ----------------
__global__ void packtf_kernel(const float* __restrict__ in, uint32_t* __restrict__ out,
                              size_t n) {
    for (size_t i = (size_t)blockIdx.x * blockDim.x + threadIdx.x; i < n;
         i += (size_t)gridDim.x * blockDim.x)
        out[i] = f2tf32(in[i]);
}

// ---------------- div-free channel-split pack: [B][C][HW] -> [B][3C/2][HW] ----------------
// One index handles channels (2q, 2q+1) at one pos -> 3 output rows. cshift: C/2 = 1<<cshift.
__global__ void packsp3_kernel(const float* __restrict__ in, uint32_t* __restrict__ out,
                               int cshift, size_t total, int phlo) {
    for (size_t i = (size_t)blockIdx.x * blockDim.x + threadIdx.x; i < total;
         i += (size_t)gridDim.x * blockDim.x) {
        size_t b = i >> (cshift + 12);
        int q = (int)((i >> 12) & ((1u << cshift) - 1));
        int pos = (int)(i & 4095);
        const float* xb = in + (b << (cshift + 13));            // b * C * HW
        float v0 = xb[((size_t)q << 13) + pos];
        float v1 = xb[((size_t)q << 13) + 4096 + pos];
        uint32_t u0, u1, u2;
        split3(v0, v1, phlo, u0, u1, u2);
        uint32_t* ob = out + b * ((size_t)3 << (cshift + 12));  // b * (3C/2) * HW
        size_t rb = ((size_t)(3 * q)) << 12;
        ob[rb + pos] = u0;
        ob[rb + 4096 + pos] = u1;
        ob[rb + 8192 + pos] = u2;
    }
}

// ---------------- div-free row-split pack: [rows][Kd] -> [rows][3Kd/2] ----------------
// kshift: Kd/2 = 1<<kshift. One index = one pair (2 input f32 -> 3 output u32).
__global__ void packrs3_kernel(const float* __restrict__ in, uint32_t* __restrict__ out,
                               size_t total, int kshift, int phlo) {
    for (size_t i = (size_t)blockIdx.x * blockDim.x + threadIdx.x; i < total;
         i += (size_t)gridDim.x * blockDim.x) {
        size_t r = i >> kshift;
        int g = (int)(i & ((1u << kshift) - 1));
        const float* row = in + (r << (kshift + 1));
        float2 v = *(const float2*)(row + 2 * g);
        uint32_t u0, u1, u2;
        split3(v.x, v.y, phlo, u0, u1, u2);
        uint32_t* o = out + r * ((size_t)3 << kshift) + 3 * (size_t)g;
        o[0] = u0; o[1] = u1; o[2] = u2;
    }
}

// ---------------- fused PAM softmax + row-split pack (phlo=2) ----------------
// One block per attn row (4096 logits): softmax then emit 6144 split u32 directly.
__global__ void softmax_pack_kernel(const float* __restrict__ logits,
                                    uint32_t* __restrict__ outsp) {
    size_t row = blockIdx.x;
    const float4* p4 = (const float4*)(logits + row * (size_t)HW);
    int t = threadIdx.x;
    __shared__ float red[256];
    __shared__ float srow[4096];
    float4 v[4];
    float m = -1e30f;
#pragma unroll
    for (int i = 0; i < 4; i++) {
        v[i] = p4[t + i * 256];
        m = fmaxf(m, fmaxf(fmaxf(v[i].x, v[i].y), fmaxf(v[i].z, v[i].w)));
    }
    red[t] = m;
    __syncthreads();
    for (int s = 128; s > 0; s >>= 1) {
        if (t < s) red[t] = fmaxf(red[t], red[t + s]);
        __syncthreads();
    }
    m = red[0];
    __syncthreads();
    float sum = 0.f;
#pragma unroll
    for (int i = 0; i < 4; i++) {
        float4 e;
        e.x = __expf(v[i].x - m); e.y = __expf(v[i].y - m);
        e.z = __expf(v[i].z - m); e.w = __expf(v[i].w - m);
        sum += e.x + e.y + e.z + e.w;
        *(float4*)&srow[(t + i * 256) * 4] = e;
    }
    red[t] = sum;
    __syncthreads();
    for (int s = 128; s > 0; s >>= 1) {
        if (t < s) red[t] += red[t + s];
        __syncthreads();
    }
    float inv = 1.f / red[0];
    uint32_t* orow = outsp + row * (size_t)K2HW;
#pragma unroll
    for (int j = 0; j < 8; j++) {
        float v0 = srow[16 * t + 2 * j * 1 + 0];
        (void)v0;
        float a0 = srow[16 * t + 2 * j] * inv;
        float a1 = srow[16 * t + 2 * j + 1] * inv;
        uint32_t u0, u1, u2;
        split3(a0, a1, 2, u0, u1, u2);
        int ob = 24 * t + 3 * j;
        orow[ob] = u0; orow[ob + 1] = u1; orow[ob + 2] = u2;
    }
}

// ---------------- fused CAM softmax + row-split pack (phlo=1, A-side) ----------------
// row length 512 f32 -> 768 u32; softmax(rowmax - x).
__global__ void cam_softmax_pack_kernel(const float* __restrict__ logits,
                                        uint32_t* __restrict__ outsp) {
    const float4* p4 = (const float4*)(logits + (size_t)blockIdx.x * IC);
    int t = threadIdx.x;  // 128
    float4 v = p4[t];
    __shared__ float red[128];
    float m = fmaxf(fmaxf(v.x, v.y), fmaxf(v.z, v.w));
    red[t] = m;
    __syncthreads();
    for (int s = 64; s > 0; s >>= 1) {
        if (t < s) red[t] = fmaxf(red[t], red[t + s]);
        __syncthreads();
    }
    float m1 = red[0];
    __syncthreads();
    float mn = fminf(fminf(v.x, v.y), fminf(v.z, v.w));
    red[t] = mn;
    __syncthreads();
    for (int s = 64; s > 0; s >>= 1) {
        if (t < s) red[t] = fminf(red[t], red[t + s]);
        __syncthreads();
    }
    float m2 = m1 - red[0];
    __syncthreads();
    float4 e;
    e.x = __expf(m1 - v.x - m2);
    e.y = __expf(m1 - v.y - m2);
    e.z = __expf(m1 - v.z - m2);
    e.w = __expf(m1 - v.w - m2);
    red[t] = e.x + e.y + e.z + e.w;
    __syncthreads();
    for (int s = 64; s > 0; s >>= 1) {
        if (t < s) red[t] += red[t + s];
        __syncthreads();
    }
    float inv = 1.f / red[0];
    uint32_t* orow = outsp + (size_t)blockIdx.x * (3 * IC / 2);
    uint32_t u0, u1, u2;
    split3(e.x * inv, e.y * inv, 1, u0, u1, u2);
    orow[6 * t] = u0; orow[6 * t + 1] = u1; orow[6 * t + 2] = u2;
    split3(e.z * inv, e.w * inv, 1, u0, u1, u2);
    orow[6 * t + 3] = u0; orow[6 * t + 4] = u1; orow[6 * t + 5] = u2;
}

// ---------------- conv3x3 tf32, cp.async 4-stage (p-branch) ----------------
#define TF_STG (2*16*136)
__global__ __launch_bounds__(256, 2)
void conv_tf32ca_kernel(const uint32_t* __restrict__ xtf, const uint32_t* __restrict__ wt,
                        float* __restrict__ out,
                        const float* __restrict__ s, const float* __restrict__ bias,
                        int Cin, int relu) {
    const int Cout = gridDim.y * 128;
    extern __shared__ uint32_t dyn[];
    int sb = blockIdx.x;
    int b = sb >> 5;
    int y0 = (sb & 31) * 2;
    int co0 = blockIdx.y * 128;
    int t = threadIdx.x;
    int lane = t & 31, wid = t >> 5;
    int wm = (wid & 3) * 32, wn = (wid >> 2) * 64;
    int lg = lane >> 2, lq = lane & 3;
    const uint32_t* xb = xtf + (size_t)b * Cin * HW;
    const int iters = 9 * Cin / 16;
    uint32_t smb = (uint32_t)__cvta_generic_to_shared(dyn);

    auto issue = [&](int kt) {
        if (kt < iters) {
            int st = kt & 3;
            uint32_t sA = smb + st * TF_STG * 4;
            uint32_t sB = sA + 16 * 136 * 4;
            int gk = kt * 16;
            int tap = gk / Cin;
            int ci0 = gk - tap * Cin;
            int dy = tap / 3 - 1, dx = tap % 3 - 1;
#pragma unroll
            for (int i = 0; i < 2; i++) {
                int f = t + i * 256;
                int row = f >> 5, c4 = (f & 31) * 4;
                cp16(sA + (uint32_t)(row * 136 + c4) * 4,
                     wt + (size_t)(gk + row) * Cout + co0 + c4);
            }
#pragma unroll
            for (int i = 0; i < 8; i++) {
                int f = t + i * 256;
                int row = f >> 7, n = f & 127;
                int iy = y0 + (n >> 6) + dy, ix = (n & 63) + dx;
                bool inb = ((unsigned)iy < 64u) && ((unsigned)ix < 64u);
                const uint32_t* src = inb ? (xb + (size_t)(ci0 + row) * HW + iy * WW + ix) : xb;
                cp4(sB + (uint32_t)(row * 136 + n) * 4, src, inb ? 4u : 0u);
            }
        }
        CP_COMMIT();
    };

    issue(0); issue(1); issue(2);

    float acc[2][8][4];
#pragma unroll
    for (int i = 0; i < 2; i++)
#pragma unroll
        for (int j = 0; j < 8; j++)
#pragma unroll
            for (int q = 0; q < 4; q++) acc[i][j][q] = 0.f;

    for (int kt = 0; kt < iters; kt++) {
        CP_WAIT2();
        __syncthreads();
        int st = kt & 3;
        const uint32_t* sA = dyn + st * TF_STG;
        const uint32_t* sB = sA + 16 * 136;
#pragma unroll
        for (int k0 = 0; k0 < 16; k0 += 8) {
            uint32_t af[2][4], bf[8][2];
#pragma unroll
            for (int mt = 0; mt < 2; mt++) {
                int m = wm + mt * 16;
                af[mt][0] = sA[(k0 + lq) * 136 + m + lg];
                af[mt][1] = sA[(k0 + lq) * 136 + m + 8 + lg];
                af[mt][2] = sA[(k0 + 4 + lq) * 136 + m + lg];
                af[mt][3] = sA[(k0 + 4 + lq) * 136 + m + 8 + lg];
            }
#pragma unroll
            for (int nt = 0; nt < 8; nt++) {
                int n = wn + nt * 8;
                bf[nt][0] = sB[(k0 + lq) * 136 + n + lg];
                bf[nt][1] = sB[(k0 + 4 + lq) * 136 + n + lg];
            }
#pragma unroll
            for (int mt = 0; mt < 2; mt++)
#pragma unroll
                for (int nt = 0; nt < 8; nt++)
                    mma_tf32(acc[mt][nt], af[mt], bf[nt]);
        }
        issue(kt + 3);
    }

#pragma unroll
    for (int mt = 0; mt < 2; mt++) {
        int r0 = co0 + wm + mt * 16 + lg;
        float s0 = s ? s[r0] : 1.f, s1 = s ? s[r0 + 8] : 1.f;
        float b0 = bias ? bias[r0] : 0.f, b1 = bias ? bias[r0 + 8] : 0.f;
#pragma unroll
        for (int nt = 0; nt < 8; nt++) {
            int col = wn + nt * 8 + lq * 2;
            int yy = y0 + (col >> 6), xx = col & 63;
            float v0 = acc[mt][nt][0] * s0 + b0, v1 = acc[mt][nt][1] * s0 + b0;
            float v2 = acc[mt][nt][2] * s1 + b1, v3 = acc[mt][nt][3] * s1 + b1;
            if (relu) { v0 = fmaxf(v0, 0.f); v1 = fmaxf(v1, 0.f);
                        v2 = fmaxf(v2, 0.f); v3 = fmaxf(v3, 0.f); }
            size_t o0 = (((size_t)b * Cout + r0) * HH + yy) * WW + xx;
            size_t o1 = (((size_t)b * Cout + r0 + 8) * HH + yy) * WW + xx;
            *(float2*)(out + o0) = make_float2(v0, v1);
            *(float2*)(out + o1) = make_float2(v2, v3);
        }
    }
}

// ---------------- conv3x3 bf16 triple-split, cp.async 4-stage (c-branch) ----------------
#define BF_STG (2*8*136)
__global__ __launch_bounds__(256, 2)
void conv_bf16ca_kernel(const uint32_t* __restrict__ xsp, const uint32_t* __restrict__ wp,
                        float* __restrict__ out,
                        const float* __restrict__ s, const float* __restrict__ bias,
                        int Cin, int relu) {
    const int Cout = gridDim.y * 128;
    const int K2Ct = 3 * Cin / 2;
    __shared__ uint32_t smem[4 * BF_STG];
    int sb = blockIdx.x;
    int b = sb >> 5;
    int y0 = (sb & 31) * 2;
    int co0 = blockIdx.y * 128;
    int t = threadIdx.x;
    int lane = t & 31, wid = t >> 5;
    int wm = (wid & 3) * 32, wn = (wid >> 2) * 64;
    int lg = lane >> 2, lq = lane & 3;
    const uint32_t* xb = xsp + (size_t)b * K2Ct * HW;
    const int iters = 9 * K2Ct / 8;
    uint32_t smb = (uint32_t)__cvta_generic_to_shared(smem);

    auto issue = [&](int kt) {
        if (kt < iters) {
            int st = kt & 3;
            uint32_t sA = smb + st * BF_STG * 4;
            uint32_t sB = sA + 8 * 136 * 4;
            int g0 = kt * 8;
            int tap = g0 / K2Ct;
            int k20 = g0 - tap * K2Ct;
            int dy = tap / 3 - 1, dx = tap % 3 - 1;
            {
                int row = t >> 5, c4 = (t & 31) * 4;
                cp16(sA + (uint32_t)(row * 136 + c4) * 4,
                     wp + (size_t)(g0 + row) * Cout + co0 + c4);
            }
#pragma unroll
            for (int i = 0; i < 4; i++) {
                int f = t + i * 256;
                int row = f >> 7, n = f & 127;
                int iy = y0 + (n >> 6) + dy, ix = (n & 63) + dx;
                bool inb = ((unsigned)iy < 64u) && ((unsigned)ix < 64u);
                const uint32_t* src = inb ? (xb + (size_t)(k20 + row) * HW + iy * WW + ix) : xb;
                cp4(sB + (uint32_t)(row * 136 + n) * 4, src, inb ? 4u : 0u);
            }
        }
        CP_COMMIT();
    };

    issue(0); issue(1); issue(2);

    float acc[2][8][4];
#pragma unroll
    for (int i = 0; i < 2; i++)
#pragma unroll
        for (int j = 0; j < 8; j++)
#pragma unroll
            for (int q = 0; q < 4; q++) acc[i][j][q] = 0.f;

    for (int kt = 0; kt < iters; kt++) {
        CP_WAIT2();
        __syncthreads();
        int st = kt & 3;
        const uint32_t* sA = smem + st * BF_STG;
        const uint32_t* sB = sA + 8 * 136;
        {
            uint32_t af[2][4], bf[8][2];
#pragma unroll
            for (int mt = 0; mt < 2; mt++) {
                int m = wm + mt * 16;
                af[mt][0] = sA[lq * 136 + m + lg];
                af[mt][1] = sA[lq * 136 + m + 8 + lg];
                af[mt][2] = sA[(lq + 4) * 136 + m + lg];
                af[mt][3] = sA[(lq + 4) * 136 + m + 8 + lg];
            }
#pragma unroll
            for (int nt = 0; nt < 8; nt++) {
                int n = wn + nt * 8;
                bf[nt][0] = sB[lq * 136 + n + lg];
                bf[nt][1] = sB[(lq + 4) * 136 + n + lg];
            }
#pragma unroll
            for (int mt = 0; mt < 2; mt++)
#pragma unroll
                for (int nt = 0; nt < 8; nt++)
                    mma_bf16(acc[mt][nt], af[mt], bf[nt]);
        }
        issue(kt + 3);
    }

#pragma unroll
    for (int mt = 0; mt < 2; mt++) {
        int r0 = co0 + wm + mt * 16 + lg;
        float s0 = s ? s[r0] : 1.f, s1 = s ? s[r0 + 8] : 1.f;
        float b0 = bias ? bias[r0] : 0.f, b1 = bias ? bias[r0 + 8] : 0.f;
#pragma unroll
        for (int nt = 0; nt < 8; nt++) {
            int col = wn + nt * 8 + lq * 2;
            int yy = y0 + (col >> 6), xx = col & 63;
            float v0 = acc[mt][nt][0] * s0 + b0, v1 = acc[mt][nt][1] * s0 + b0;
            float v2 = acc[mt][nt][2] * s1 + b1, v3 = acc[mt][nt][3] * s1 + b1;
            if (relu) { v0 = fmaxf(v0, 0.f); v1 = fmaxf(v1, 0.f);
                        v2 = fmaxf(v2, 0.f); v3 = fmaxf(v3, 0.f); }
            size_t o0 = (((size_t)b * Cout + r0) * HH + yy) * WW + xx;
            size_t o1 = (((size_t)b * Cout + r0 + 8) * HH + yy) * WW + xx;
            *(float2*)(out + o0) = make_float2(v0, v1);
            *(float2*)(out + o1) = make_float2(v2, v3);
        }
    }
}

// ---------------- bf16 triple-split GEMM, cp.async 4-stage ----------------
// AT=1: A is [M][K2] row-major; AT=0: [K2][lda]. Same for B.
// Epilogue: scale*acc + Res if Res; else acc + bias[m] if bias; else acc.
#define GS_STG (2*8*136)
template<int AT, int BT>
__global__ __launch_bounds__(256, 2)
void gemm_bf16s_kernel(const uint32_t* __restrict__ A, long aBS, int lda,
                       const uint32_t* __restrict__ B, long bBS, int ldb,
                       float* __restrict__ C, long cBS, int ldc,
                       const float* __restrict__ scalePtr,
                       const float* __restrict__ bias,
                       const float* __restrict__ Res,
                       int K2) {
    __shared__ uint32_t smem[4 * GS_STG];
    int z = blockIdx.z;
    const uint32_t* Ab = A + (size_t)z * aBS;
    const uint32_t* Bb = B + (size_t)z * bBS;
    float* Cb = C + (size_t)z * cBS;
    const float* Rb = Res ? Res + (size_t)z * cBS : (const float*)0;
    int n0 = blockIdx.x * 128, m0 = blockIdx.y * 128;
    int t = threadIdx.x;
    int lane = t & 31, wid = t >> 5;
    int wm = (wid & 3) * 32, wn = (wid >> 2) * 64;
    int lg = lane >> 2, lq = lane & 3;
    const int iters = K2 / 8;
    uint32_t smb = (uint32_t)__cvta_generic_to_shared(smem);

    auto issue = [&](int kt) {
        if (kt < iters) {
            int st = kt & 3;
            uint32_t sA = smb + st * GS_STG * 4;
            uint32_t sB = sA + 8 * 136 * 4;
            int g0 = kt * 8;
            if (AT) {
#pragma unroll
                for (int i = 0; i < 4; i++) {
                    int f = t + i * 256;
                    int k2 = f & 7, m = f >> 3;
                    cp4u(sA + (uint32_t)(k2 * 136 + m) * 4,
                         Ab + (size_t)(m0 + m) * lda + g0 + k2);
                }
            } else {
                int k2 = t >> 5, c4 = (t & 31) * 4;
                cp16(sA + (uint32_t)(k2 * 136 + c4) * 4,
                     Ab + (size_t)(g0 + k2) * lda + m0 + c4);
            }
            if (BT) {
#pragma unroll
                for (int i = 0; i < 4; i++) {
                    int f = t + i * 256;
                    int k2 = f & 7, n = f >> 3;
                    cp4u(sB + (uint32_t)(k2 * 136 + n) * 4,
                         Bb + (size_t)(n0 + n) * ldb + g0 + k2);
                }
            } else {
                int k2 = t >> 5, c4 = (t & 31) * 4;
                cp16(sB + (uint32_t)(k2 * 136 + c4) * 4,
                     Bb + (size_t)(g0 + k2) * ldb + n0 + c4);
            }
        }
        CP_COMMIT();
    };

    issue(0); issue(1); issue(2);

    float acc[2][8][4];
#pragma unroll
    for (int i = 0; i < 2; i++)
#pragma unroll
        for (int j = 0; j < 8; j++)
#pragma unroll
            for (int q = 0; q < 4; q++) acc[i][j][q] = 0.f;

    for (int kt = 0; kt < iters; kt++) {
        CP_WAIT2();
        __syncthreads();
        int st = kt & 3;
        const uint32_t* sA = smem + st * GS_STG;
        const uint32_t* sB = sA + 8 * 136;
        {
            uint32_t af[2][4], bf[8][2];
#pragma unroll
            for (int mt = 0; mt < 2; mt++) {
                int m = wm + mt * 16;
                af[mt][0] = sA[lq * 136 + m + lg];
                af[mt][1] = sA[lq * 136 + m + 8 + lg];
                af[mt][2] = sA[(lq + 4) * 136 + m + lg];
                af[mt][3] = sA[(lq + 4) * 136 + m + 8 + lg];
            }
#pragma unroll
            for (int nt = 0; nt < 8; nt++) {
                int n = wn + nt * 8;
                bf[nt][0] = sB[lq * 136 + n + lg];
                bf[nt][1] = sB[(lq + 4) * 136 + n + lg];
            }
#pragma unroll
            for (int mt = 0; mt < 2; mt++)
#pragma unroll
                for (int nt = 0; nt < 8; nt++)
                    mma_bf16(acc[mt][nt], af[mt], bf[nt]);
        }
        issue(kt + 3);
    }

    float scale = scalePtr ? scalePtr[0] : 1.f;
#pragma unroll
    for (int mt = 0; mt < 2; mt++) {
        int r0 = m0 + wm + mt * 16 + lg;
        float bi0 = bias ? bias[r0] : 0.f;
        float bi1 = bias ? bias[r0 + 8] : 0.f;
#pragma unroll
        for (int nt = 0; nt < 8; nt++) {
            int col = n0 + wn + nt * 8 + lq * 2;
            size_t o0 = (size_t)r0 * ldc + col;
            size_t o1 = (size_t)(r0 + 8) * ldc + col;
            float v0 = acc[mt][nt][0], v1 = acc[mt][nt][1];
            float v2 = acc[mt][nt][2], v3 = acc[mt][nt][3];
            if (Rb) {
                v0 = scale * v0 + Rb[o0]; v1 = scale * v1 + Rb[o0 + 1];
                v2 = scale * v2 + Rb[o1]; v3 = scale * v3 + Rb[o1 + 1];
            } else {
                v0 += bi0; v1 += bi0; v2 += bi1; v3 += bi1;
            }
            *(float2*)(Cb + o0) = make_float2(v0, v1);
            *(float2*)(Cb + o1) = make_float2(v2, v3);
        }
    }
}

// ---------------- generic 128x128 GEMM NN (fp32 SIMT, small M cases) ----------------
__global__ void gemm_nn_kernel(const float* __restrict__ A, long aBS,
                               const float* __restrict__ Bm, long bBS,
                               float* __restrict__ C, long cBS,
                               const float* __restrict__ bias,
                               const float* __restrict__ scalePtr,
                               const float* __restrict__ Res,
                               int M, int N, int K) {
    int z = blockIdx.z;
    const float* Ab = A + (size_t)z * aBS;
    const float* Bb = Bm + (size_t)z * bBS;
    float* Cb = C + (size_t)z * cBS;
    const float* Rb = Res ? Res + (size_t)z * cBS : (const float*)0;
    int n0 = blockIdx.x * 128, m0 = blockIdx.y * 128;
    int t = threadIdx.x, tx = t & 15, ty = t >> 4;
    __shared__ float aS[8][128];
    __shared__ float bS[8][128];
    float acc[8][8];
#pragma unroll
    for (int i = 0; i < 8; i++)
#pragma unroll
        for (int j = 0; j < 8; j++) acc[i][j] = 0.f;

    int mload = t >> 1;
    int kq = (t & 1) * 4;

    for (int ck = 0; ck < K; ck += 8) {
        float4 av = make_float4(0.f, 0.f, 0.f, 0.f);
        if (m0 + mload < M)
            av = *(const float4*)(Ab + (size_t)(m0 + mload) * K + ck + kq);
        aS[kq+0][mload]=av.x; aS[kq+1][mload]=av.y; aS[kq+2][mload]=av.z; aS[kq+3][mload]=av.w;
#pragma unroll
        for (int i = 0; i < 4; ++i) {
            int idx = t + i * 256;
            int k = idx >> 7, n = idx & 127;
            bS[k][n] = Bb[(size_t)(ck + k) * N + n0 + n];
        }
        __syncthreads();
#pragma unroll
        for (int kk = 0; kk < 8; ++kk) {
            float a[8], bv[8];
#pragma unroll
            for (int i = 0; i < 8; i++) a[i] = aS[kk][ty*8+i];
#pragma unroll
            for (int j = 0; j < 8; j++) bv[j] = bS[kk][tx*8+j];
#pragma unroll
            for (int i = 0; i < 8; i++)
#pragma unroll
                for (int j = 0; j < 8; j++) acc[i][j] = fmaf(a[i], bv[j], acc[i][j]);
        }
        __syncthreads();
    }

    float scale = scalePtr ? scalePtr[0] : 1.f;
#pragma unroll
    for (int i = 0; i < 8; i++) {
        int m = m0 + ty * 8 + i;
        if (m < M) {
            float bi = bias ? bias[m] : 0.f;
#pragma unroll
            for (int j = 0; j < 8; j++) {
                int n = n0 + tx * 8 + j;
                size_t off = (size_t)m * N + n;
                float v = acc[i][j];
                if (Rb) v = scale * v + Rb[off];
                else v += bi;
                Cb[off] = v;
            }
        }
    }
}

// ---------------- elementwise add ----------------
__global__ void add_kernel(const float* __restrict__ a, const float* __restrict__ b,
                           float* __restrict__ c, int n) {
    int i = blockIdx.x * 256 + threadIdx.x;
    if (i < n) c[i] = a[i] + b[i];
}

// ---------------- bilinear 2x upsample ----------------
__global__ void up2x_kernel(const float* __restrict__ src, float* __restrict__ dst) {
    int idx = blockIdx.x * 256 + threadIdx.x;
    const int total = BB * NCLS * OHW;
    if (idx >= total) return;
    int ox = idx & 127;
    int r = idx >> 7;
    int oy = r & 127;
    r >>= 7;
    float sy = oy * 0.5f - 0.25f;
    float sx = ox * 0.5f - 0.25f;
    float fy = floorf(sy), fx = floorf(sx);
    float wy = sy - fy, wx = sx - fx;
    int y0 = (int)fy, x0 = (int)fx;
    int y0c = max(y0, 0), y1c = min(y0 + 1, 63);
    int x0c = max(x0, 0), x1c = min(x0 + 1, 63);
    const float* s = src + (size_t)r * HW;
    float v00 = s[y0c*64+x0c], v01 = s[y0c*64+x1c];
    float v10 = s[y1c*64+x0c], v11 = s[y1c*64+x1c];
    dst[idx] = (1.f-wy)*((1.f-wx)*v00 + wx*v01) + wy*((1.f-wx)*v10 + wx*v11);
}

// ---------------- orchestration ----------------
extern "C" void kernel_launch(void* const* d_in, const int* in_sizes, int n_in,
                              void* d_out, int out_size) {
    (void)in_sizes; (void)n_in; (void)out_size;
    const float* x    = (const float*)d_in[0];
    const float* wp1  = (const float*)d_in[1];
    const float* sp1  = (const float*)d_in[2];
    const float* bp1  = (const float*)d_in[3];
    const float* wc1  = (const float*)d_in[4];
    const float* sc1  = (const float*)d_in[5];
    const float* bc1  = (const float*)d_in[6];
    const float* pwb  = (const float*)d_in[7];
    const float* pbb  = (const float*)d_in[8];
    const float* pwc  = (const float*)d_in[9];
    const float* pbc  = (const float*)d_in[10];
    const float* pwd  = (const float*)d_in[11];
    const float* pbd  = (const float*)d_in[12];
    const float* alpha = (const float*)d_in[13];
    const float* beta  = (const float*)d_in[14];
    const float* wp2  = (const float*)d_in[15];
    const float* sp2  = (const float*)d_in[16];
    const float* bp2  = (const float*)d_in[17];
    const float* wc2  = (const float*)d_in[18];
    const float* sc2  = (const float*)d_in[19];
    const float* bc2  = (const float*)d_in[20];
    const float* wlog = (const float*)d_in[21];
    const float* blog = (const float*)d_in[22];
    const float* wp3  = (const float*)d_in[23];
    const float* bp3  = (const float*)d_in[24];
    const float* wc3  = (const float*)d_in[25];
    const float* bc3  = (const float*)d_in[26];
    float* out = (float*)d_out;

    uint32_t *wt1p, *wbc1, *wt2p, *wbc2, *xtf, *xsp, *pamtf, *camsp;
    uint32_t *fbsp, *fcsp, *fdsp, *attnsp, *fp0cs, *fc0cs, *fc0rsA, *fc0rsB, *wdrs, *catsp;
    float *featp0, *featc0, *fb, *fc, *fd, *attn;
    float *pam, *featp, *camatt, *cam, *featc, *fusion, *pout, *cout_, *fout;
    cudaGetSymbolAddress((void**)&wt1p, g_wt1p);
    cudaGetSymbolAddress((void**)&wbc1, g_wbc1);
    cudaGetSymbolAddress((void**)&wt2p, g_wt2p);
    cudaGetSymbolAddress((void**)&wbc2, g_wbc2);
    cudaGetSymbolAddress((void**)&xtf, g_xtf);
    cudaGetSymbolAddress((void**)&xsp, g_xsp);
    cudaGetSymbolAddress((void**)&pamtf, g_pamtf);
    cudaGetSymbolAddress((void**)&camsp, g_camsp);
    cudaGetSymbolAddress((void**)&fbsp, g_fbsp);
    cudaGetSymbolAddress((void**)&fcsp, g_fcsp);
    cudaGetSymbolAddress((void**)&fdsp, g_fdsp);
    cudaGetSymbolAddress((void**)&attnsp, g_attnsp);
    cudaGetSymbolAddress((void**)&fp0cs, g_fp0cs);
    cudaGetSymbolAddress((void**)&fc0cs, g_fc0cs);
    cudaGetSymbolAddress((void**)&fc0rsA, g_fc0rsA);
    cudaGetSymbolAddress((void**)&fc0rsB, g_fc0rsB);
    cudaGetSymbolAddress((void**)&wdrs, g_wdrs);
    cudaGetSymbolAddress((void**)&catsp, g_catsp);
    cudaGetSymbolAddress((void**)&featp0, g_featp0);
    cudaGetSymbolAddress((void**)&featc0, g_featc0);
    cudaGetSymbolAddress((void**)&fb, g_fb);
    cudaGetSymbolAddress((void**)&fc, g_fc);
    cudaGetSymbolAddress((void**)&fd, g_fd);
    cudaGetSymbolAddress((void**)&attn, g_attn);
    cudaGetSymbolAddress((void**)&pam, g_pam);
    cudaGetSymbolAddress((void**)&featp, g_featp);
    cudaGetSymbolAddress((void**)&camatt, g_camatt);
    cudaGetSymbolAddress((void**)&cam, g_cam);
    cudaGetSymbolAddress((void**)&featc, g_featc);
    cudaGetSymbolAddress((void**)&fusion, g_fusion);
    cudaGetSymbolAddress((void**)&pout, g_pout);
    cudaGetSymbolAddress((void**)&cout_, g_cout);
    cudaGetSymbolAddress((void**)&fout, g_fout);

    cudaFuncSetAttribute(conv_tf32ca_kernel,
                         cudaFuncAttributeMaxDynamicSharedMemorySize, TF_STG * 4 * 4);

    // c1 first so conv_bf16ca lands in the ncu capture slot (#4)
    wsplitbf_kernel<<<8192, 256>>>(wc1, wbc1, CIN, IC);                              // 1
    packsp3_kernel<<<16384, 256>>>(x, xsp, 10, (size_t)BB << 22, 2);                 // 2 (C=2048)
    wtrans_kernel<<<4096, 256>>>(wp1, wt1p, CIN, IC);                                // 3
    conv_bf16ca_kernel<<<dim3(128, 4), 256>>>(xsp, wbc1, featc0, sc1, bc1, CIN, 1);  // 4 <- ncu
    packtf_kernel<<<16384, 256>>>(x, xtf, (size_t)BB * CIN * HW);                    // 5
    conv_tf32ca_kernel<<<dim3(128, 4), 256, TF_STG * 4 * 4>>>(xtf, wt1p, featp0, sp1, bp1, CIN, 1);
    wtrans_kernel<<<2048, 256>>>(wp2, wt2p, IC, IC);
    wsplitbf_kernel<<<2048, 256>>>(wc2, wbc2, IC, IC);

    // PAM projections: fb/fc SIMT (M=64), fd via bf16-split tensor GEMM
    gemm_nn_kernel<<<dim3(32, 1, 4), 256>>>(pwb, 0, featp0, (long)IC * HW,
                                            fb, (long)C8 * HW, pbb, 0, 0, C8, HW, IC);
    gemm_nn_kernel<<<dim3(32, 1, 4), 256>>>(pwc, 0, featp0, (long)IC * HW,
                                            fc, (long)C8 * HW, pbc, 0, 0, C8, HW, IC);
    packsp3_kernel<<<8192, 256>>>(featp0, fp0cs, 8, (size_t)BB << 20, 2);            // C=512
    packrs3_kernel<<<512, 256>>>(pwd, wdrs, (size_t)IC << 8, 8, 1);                  // rows=512, Kd=512
    gemm_bf16s_kernel<1, 0><<<dim3(32, 4, 4), 256>>>(
        wdrs, 0, 3 * IC / 2,
        fp0cs, (long)K2C2 * HW, HW,
        fd, (long)IC * HW, HW, 0, pbd, 0, 3 * IC / 2);

    // PAM logits (bf16-split3) + fused softmax+pack
    packsp3_kernel<<<1024, 256>>>(fb, fbsp, 5, (size_t)BB << 17, 1);                 // C=64
    packsp3_kernel<<<1024, 256>>>(fc, fcsp, 5, (size_t)BB << 17, 2);
    gemm_bf16s_kernel<0, 0><<<dim3(32, 32, 4), 256>>>(
        fbsp, (long)(3 * C8 / 2) * HW, HW,
        fcsp, (long)(3 * C8 / 2) * HW, HW,
        attn, (long)HW * HW, HW, 0, 0, 0, 3 * C8 / 2);
    softmax_pack_kernel<<<BB * HW, 256>>>(attn, attnsp);

    // PAM apply: pam = alpha * (fd @ attn^T) + featp0
    packrs3_kernel<<<8192, 256>>>(fd, fdsp, (size_t)(BB * IC) << 11, 11, 1);
    gemm_bf16s_kernel<1, 1><<<dim3(32, 4, 4), 256>>>(
        fdsp, (long)IC * K2HW, K2HW,
        attnsp, (long)HW * K2HW, K2HW,
        pam, (long)IC * HW, HW, alpha, 0, featp0, K2HW);

    // conv p2
    packtf_kernel<<<8192, 256>>>(pam, pamtf, (size_t)BB * IC * HW);
    conv_tf32ca_kernel<<<dim3(128, 4), 256, TF_STG * 4 * 4>>>(pamtf, wt2p, featp, sp2, bp2, IC, 1);

    // CAM: gram (bf16-split3, fp32-grade) + fused softmax+pack + apply (bf16-split3)
    packrs3_kernel<<<8192, 256>>>(featc0, fc0rsA, (size_t)(BB * IC) << 11, 11, 1);
    packrs3_kernel<<<8192, 256>>>(featc0, fc0rsB, (size_t)(BB * IC) << 11, 11, 2);
    gemm_bf16s_kernel<1, 1><<<dim3(4, 4, 4), 256>>>(
        fc0rsA, (long)IC * K2HW, K2HW,
        fc0rsB, (long)IC * K2HW, K2HW,
        camatt, (long)IC * IC, IC, 0, 0, 0, K2HW);
    cam_softmax_pack_kernel<<<BB * IC, 128>>>(camatt, catsp);
    packsp3_kernel<<<8192, 256>>>(featc0, fc0cs, 8, (size_t)BB << 20, 2);
    gemm_bf16s_kernel<1, 0><<<dim3(32, 4, 4), 256>>>(
        catsp, (long)IC * (3 * IC / 2), 3 * IC / 2,
        fc0cs, (long)K2C2 * HW, HW,
        cam, (long)IC * HW, HW, beta, 0, featc0, 3 * IC / 2);

    // conv c2
    packsp3_kernel<<<8192, 256>>>(cam, camsp, 8, (size_t)BB << 20, 2);
    conv_bf16ca_kernel<<<dim3(128, 4), 256>>>(camsp, wbc2, featc, sc2, bc2, IC, 1);

    // fusion + output heads (SIMT, M=81)
    add_kernel<<<(BB * IC * HW) / 256, 256>>>(featp, featc, fusion, BB * IC * HW);
    gemm_nn_kernel<<<dim3(32, 1, 4), 256>>>(wp3, 0, featp, (long)IC * HW,
                                            pout, (long)NCLS * HW, bp3, 0, 0, NCLS, HW, IC);
    gemm_nn_kernel<<<dim3(32, 1, 4), 256>>>(wc3, 0, featc, (long)IC * HW,
                                            cout_, (long)NCLS * HW, bc3, 0, 0, NCLS, HW, IC);
    gemm_nn_kernel<<<dim3(32, 1, 4), 256>>>(wlog, 0, fusion, (long)IC * HW,
                                            fout, (long)NCLS * HW, blog, 0, 0, NCLS, HW, IC);

    // upsample 2x into output
    const int outElems = BB * NCLS * OHW;
    up2x_kernel<<<(outElems + 255) / 256, 256>>>(pout, out);
    up2x_kernel<<<(outElems + 255) / 256, 256>>>(cout_, out + outElems);
    up2x_kernel<<<(outElems + 255) / 256, 256>>>(fout, out + 2 * (size_t)outElems);
}